// round 7
// baseline (speedup 1.0000x reference)
#include <cuda_runtime.h>
#include <cuda_fp16.h>
#include <cstdint>
#include <float.h>

#define NTOK 32768
#define DIMD 256
#define KVOC 8192
#define NTIL   64           // n-tiles of 128 codewords
#define MGRP   8            // m-tiles per CTA (persistent-B)
#define TAU  0.08f

// ---- device scratch ----
__device__ __half g_Ah[(size_t)NTOK * DIMD];   // 16 MB fp16 tokens
__device__ __half g_Bh[(size_t)KVOC * DIMD];   // 4 MB fp16 vocab
__device__ float  g_vnorm[KVOC];               // 0.5*||v||^2 fp32
__device__ float  g_s1[(size_t)NTIL * NTOK];
__device__ float  g_s2[(size_t)NTIL * NTOK];
__device__ int    g_i1[(size_t)NTIL * NTOK];
__device__ unsigned long long g_key[NTOK];
__device__ int    g_wl[NTOK];
__device__ int    g_wlcount;

// ---- smem layout: A stages (2x16KB) | B chunks (4x16KB) | vn | red ----
#define SA_OFF(st) ((st) * 16384)
#define SB_OFF(c)  (32768 + (c) * 16384)
#define SO_VN  98304
#define SO_R1  98816
#define SO_R2  100864
#define SO_RI  102912
#define SM_TOTAL 104960

// ============================ asm helpers ============================
__device__ __forceinline__ uint32_t smem_u32(const void* p) {
    uint32_t a;
    asm("{ .reg .u64 t; cvta.to.shared.u64 t, %1; cvt.u32.u64 %0, t; }"
        : "=r"(a) : "l"(p));
    return a;
}
__device__ __forceinline__ void cpasync16(uint32_t s, const void* g) {
    asm volatile("cp.async.cg.shared.global [%0], [%1], 16;" :: "r"(s), "l"(g));
}
#define CP_COMMIT() asm volatile("cp.async.commit_group;" ::: "memory")
#define CP_WAIT(N)  asm volatile("cp.async.wait_group " #N ";" ::: "memory")

__device__ __forceinline__ void ldsm4(uint32_t& r0, uint32_t& r1, uint32_t& r2,
                                      uint32_t& r3, uint32_t addr) {
    asm volatile("ldmatrix.sync.aligned.m8n8.x4.shared.b16 {%0,%1,%2,%3}, [%4];"
                 : "=r"(r0), "=r"(r1), "=r"(r2), "=r"(r3) : "r"(addr));
}
__device__ __forceinline__ void mma16816(float* d, const uint32_t* a,
                                         uint32_t b0, uint32_t b1) {
    asm volatile(
        "mma.sync.aligned.m16n8k16.row.col.f32.f16.f16.f32 "
        "{%0,%1,%2,%3},{%4,%5,%6,%7},{%8,%9},{%0,%1,%2,%3};"
        : "+f"(d[0]), "+f"(d[1]), "+f"(d[2]), "+f"(d[3])
        : "r"(a[0]), "r"(a[1]), "r"(a[2]), "r"(a[3]), "r"(b0), "r"(b1));
}
__device__ __forceinline__ uint32_t swz(uint32_t off) {
    return off ^ ((off >> 3) & 0x70);
}
// monotone float -> uint mapping (order preserving incl. negatives)
__device__ __forceinline__ uint32_t f2ord(float s) {
    uint32_t fb = __float_as_uint(s);
    return (fb & 0x80000000u) ? ~fb : (fb | 0x80000000u);
}

// =================== fused convert kernel (seq + vocab) ===================
// blocks [0, 8192): seq -> fp16 ; blocks [8192, 9216): vocab -> fp16 + vnorm
__global__ void convert_kernel(const float* __restrict__ seq,
                               const float* __restrict__ vocab) {
    if (blockIdx.x == 0 && threadIdx.x == 0) g_wlcount = 0;
    if (blockIdx.x < 8192) {
        int idx = blockIdx.x * 256 + threadIdx.x;   // one float4 each
        int row = idx >> 6;
        int c4  = idx & 63;
        float4 x = ((const float4*)seq)[idx];
        __half2 a = __floats2half2_rn(x.x, x.y);
        __half2 b = __floats2half2_rn(x.z, x.w);
        uint2 u;
        u.x = *(uint32_t*)&a; u.y = *(uint32_t*)&b;
        *(uint2*)(g_Ah + (size_t)row * DIMD + c4 * 4) = u;
    } else {
        int row  = (blockIdx.x - 8192) * 8 + (threadIdx.x >> 5);
        int lane = threadIdx.x & 31;
        const float4* v = (const float4*)(vocab + (size_t)row * DIMD);
        float s = 0.f;
        #pragma unroll
        for (int c4 = lane; c4 < 64; c4 += 32) {
            float4 x = v[c4];
            s += x.x*x.x + x.y*x.y + x.z*x.z + x.w*x.w;
            __half2 a = __floats2half2_rn(x.x, x.y);
            __half2 b = __floats2half2_rn(x.z, x.w);
            uint2 u;
            u.x = *(uint32_t*)&a; u.y = *(uint32_t*)&b;
            *(uint2*)(g_Bh + (size_t)row * DIMD + c4 * 4) = u;
        }
        #pragma unroll
        for (int o = 16; o; o >>= 1) s += __shfl_xor_sync(0xffffffffu, s, o);
        if (lane == 0) g_vnorm[row] = 0.5f * s;
    }
}

// ================= persistent-B fp16 GEMM + fused top-2 =================
__global__ __launch_bounds__(256, 2)
void gemm_kernel() {
    extern __shared__ char smem[];
    uint32_t sbase = smem_u32(smem);
    float* s_vn = (float*)(smem + SO_VN);
    float* r1a  = (float*)(smem + SO_R1);
    float* r2a  = (float*)(smem + SO_R2);
    int*   ria  = (int*)  (smem + SO_RI);

    const int tid = threadIdx.x, lane = tid & 31, wid = tid >> 5;
    const int wm = wid & 1, wn = wid >> 1;          // 2 x 4 warp grid
    const int bn = blockIdx.x & (NTIL - 1);         // n-tile (fast-varying)
    const int mg = blockIdx.x >> 6;                 // m-group (8 m-tiles)
    const int n0 = bn * 128;
    const int mbase = mg * MGRP * 128;

    const char* Bb = (const char*)g_Bh + (size_t)n0 * 512;

    // ---- load full B n-tile (64KB = 4 chunk-swizzled sub-tiles), one group
    #pragma unroll
    for (int q = 0; q < 16; q++) {
        int c  = q >> 2;
        int p  = tid + 256 * (q & 3);
        int r  = p >> 3, jj = p & 7;
        cpasync16(sbase + SB_OFF(c) + swz(r * 128 + jj * 16),
                  Bb + (size_t)r * 512 + c * 128 + jj * 16);
    }
    CP_COMMIT();

    // A chunk j (j = mt*4 + c) -> stage (c & 1)
#define LOAD_A(J)                                                              \
    {                                                                          \
        int mt_ = (J) >> 2, c_ = (J) & 3;                                      \
        uint32_t st = sbase + SA_OFF(c_ & 1);                                  \
        const char* Asrc = (const char*)g_Ah                                   \
            + (size_t)(mbase + mt_ * 128) * 512 + c_ * 128;                    \
        _Pragma("unroll")                                                      \
        for (int q = 0; q < 4; q++) {                                          \
            int p = tid + 256 * q; int r = p >> 3, jj = p & 7;                 \
            cpasync16(st + swz(r * 128 + jj * 16),                             \
                      Asrc + (size_t)r * 512 + jj * 16);                       \
        }                                                                      \
        CP_COMMIT();                                                           \
    }

    LOAD_A(0)
    LOAD_A(1)
    if (tid < 128) s_vn[tid] = g_vnorm[n0 + tid];

#define COMPUTE_CHUNK(ST, CB)                                                  \
    {                                                                          \
        uint32_t Abase = sbase + SA_OFF(ST);                                   \
        uint32_t Bbase = sbase + SB_OFF(CB);                                   \
        _Pragma("unroll")                                                      \
        for (int ks = 0; ks < 4; ks++) {                                       \
            uint32_t af[4][4];                                                 \
            _Pragma("unroll")                                                  \
            for (int mt = 0; mt < 4; mt++) {                                   \
                int row = wm * 64 + mt * 16 + (lane & 15);                     \
                uint32_t ad = Abase + swz(row * 128 + ks * 32 + (lane >> 4) * 16); \
                ldsm4(af[mt][0], af[mt][1], af[mt][2], af[mt][3], ad);         \
            }                                                                  \
            uint32_t bf[2][4];                                                 \
            _Pragma("unroll")                                                  \
            for (int np = 0; np < 2; np++) {                                   \
                int row = wn * 32 + np * 16 + (lane & 15);                     \
                uint32_t bd = Bbase + swz(row * 128 + ks * 32 + (lane >> 4) * 16); \
                ldsm4(bf[np][0], bf[np][1], bf[np][2], bf[np][3], bd);         \
            }                                                                  \
            _Pragma("unroll")                                                  \
            for (int mt = 0; mt < 4; mt++) {                                   \
                _Pragma("unroll")                                              \
                for (int nt = 0; nt < 4; nt++) {                               \
                    int np = nt >> 1, sub = nt & 1;                            \
                    mma16816(acc[mt][nt], af[mt], bf[np][sub], bf[np][sub + 2]); \
                }                                                              \
            }                                                                  \
        }                                                                      \
    }

    float acc[4][4][4];

    for (int mt = 0; mt < MGRP; mt++) {
        #pragma unroll
        for (int i = 0; i < 4; i++)
            #pragma unroll
            for (int j = 0; j < 4; j++)
                #pragma unroll
                for (int c = 0; c < 4; c++) acc[i][j][c] = 0.f;

        #pragma unroll
        for (int c = 0; c < 4; c++) {
            if (mt == MGRP - 1 && c == 3) { CP_WAIT(0); } else { CP_WAIT(1); }
            __syncthreads();
            COMPUTE_CHUNK(c & 1, c)
            __syncthreads();
            int nj = mt * 4 + c + 2;
            if (nj < MGRP * 4) LOAD_A(nj)
        }

        // ---- fused top-2 epilogue for this m-tile ----
        const int m0 = mbase + mt * 128;
        float m1[8], m2[8]; int i1[8];             // slot = mtile*2 + rowgroup
        #pragma unroll
        for (int s = 0; s < 8; s++) { m1[s] = FLT_MAX; m2[s] = FLT_MAX; i1[s] = 0x7FFFFFFF; }

        #pragma unroll
        for (int nt = 0; nt < 4; nt++) {
            int nloc_base = wn * 32 + (nt >> 1) * 16 + (nt & 1) * 8 + (lane & 3) * 2;
            #pragma unroll
            for (int cc = 0; cc < 2; cc++) {
                int nloc = nloc_base + cc;
                float vn = s_vn[nloc];
                int n = n0 + nloc;
                #pragma unroll
                for (int mq = 0; mq < 4; mq++) {
                    #pragma unroll
                    for (int rg = 0; rg < 2; rg++) {
                        int s_ = mq * 2 + rg;
                        float sc = vn - acc[mq][nt][rg * 2 + cc];
                        if (sc < m1[s_]) { m2[s_] = m1[s_]; m1[s_] = sc; i1[s_] = n; }
                        else if (sc < m2[s_]) m2[s_] = sc;
                    }
                }
            }
        }
        #pragma unroll
        for (int s = 0; s < 8; s++) {
            #pragma unroll
            for (int off = 1; off <= 2; off <<= 1) {
                float om1 = __shfl_xor_sync(0xffffffffu, m1[s], off);
                float om2 = __shfl_xor_sync(0xffffffffu, m2[s], off);
                int   oi  = __shfl_xor_sync(0xffffffffu, i1[s], off);
                if (om1 < m1[s] || (om1 == m1[s] && oi < i1[s])) {
                    m2[s] = fminf(m1[s], om2); m1[s] = om1; i1[s] = oi;
                } else {
                    m2[s] = fminf(m2[s], om1);
                }
            }
        }
        if ((lane & 3) == 0) {
            #pragma unroll
            for (int mq = 0; mq < 4; mq++)
                #pragma unroll
                for (int rg = 0; rg < 2; rg++) {
                    int s_ = mq * 2 + rg;
                    int row = wm * 64 + mq * 16 + rg * 8 + (lane >> 2);
                    r1a[row * 4 + wn] = m1[s_];
                    r2a[row * 4 + wn] = m2[s_];
                    ria[row * 4 + wn] = i1[s_];
                }
        }
        __syncthreads();
        if (tid < 128) {
            float M1 = FLT_MAX, M2 = FLT_MAX; int I1 = 0x7FFFFFFF;
            #pragma unroll
            for (int w = 0; w < 4; w++) {
                float a1 = r1a[tid * 4 + w], a2 = r2a[tid * 4 + w];
                int   ai = ria[tid * 4 + w];
                if (a1 < M1 || (a1 == M1 && ai < I1)) {
                    M2 = fminf(M1, a2); M1 = a1; I1 = ai;
                } else {
                    M2 = fminf(M2, a1);
                }
            }
            int token = m0 + tid;
            g_s1[(size_t)bn * NTOK + token] = M1;
            g_s2[(size_t)bn * NTOK + token] = M2;
            g_i1[(size_t)bn * NTOK + token] = I1;
        }
    }
#undef COMPUTE_CHUNK
#undef LOAD_A
}

// ============================ reduce + flag ============================
__global__ void reduce_kernel() {
    int t = blockIdx.x * blockDim.x + threadIdx.x;
    float m1 = FLT_MAX, m2 = FLT_MAX; int i1 = 0x7FFFFFFF;
    #pragma unroll 4
    for (int nt = 0; nt < NTIL; nt++) {
        float s1 = g_s1[(size_t)nt * NTOK + t];
        float s2 = g_s2[(size_t)nt * NTOK + t];
        int   ii = g_i1[(size_t)nt * NTOK + t];
        if (s1 < m1 || (s1 == m1 && ii < i1)) {
            m2 = fminf(m1, s2); m1 = s1; i1 = ii;
        } else {
            m2 = fminf(m2, s1);
        }
    }
    if (m2 - m1 < TAU) {
        g_key[t] = 0xFFFFFFFFFFFFFFFFull;       // sentinel: exact pass decides
        int slot = atomicAdd(&g_wlcount, 1);
        g_wl[slot] = t;
    } else {
        g_key[t] = ((unsigned long long)f2ord(m1) << 32) | (uint32_t)i1;
    }
}

// ============== exact fp32 cleanup: (32-token group) x (1024-codeword slice) ==
#define CW   32          // tokens per work item
#define CSL  8           // vocab slices (KVOC/CSL = 1024 each)
#define CKC  32
__global__ __launch_bounds__(256, 2)
void cleanup_kernel(const float* __restrict__ seq, const float* __restrict__ vocab) {
    __shared__ float As[CKC][33];    // [k][m] (pad 33 -> conflict-free)
    __shared__ float Bs[CKC][132];   // [k][n]
    __shared__ int   tk[CW];

    const int nf = g_wlcount;
    if (nf == 0) return;
    const int ngrp   = (nf + CW - 1) / CW;
    const int nitems = ngrp * CSL;

    const int tid = threadIdx.x;
    const int tm  = tid >> 4;        // 0..15 -> token rows tm*2, tm*2+1
    const int tn  = tid & 15;        // 0..15 -> 8 codeword cols
    const int lk  = tid & 31;
    const int lm  = tid >> 5;        // 0..7

    for (int item = blockIdx.x; item < nitems; item += gridDim.x) {
        const int tg    = item / CSL;
        const int nbase = (item % CSL) * (KVOC / CSL);

        __syncthreads();   // protect tk across iterations
        if (tid < CW) {
            int w = tg * CW + tid;
            tk[tid] = g_wl[w < nf ? w : (nf - 1)];
        }
        __syncthreads();

        float minv[2]; int mini[2];
        minv[0] = minv[1] = FLT_MAX; mini[0] = mini[1] = 0;

        for (int n0 = nbase; n0 < nbase + KVOC / CSL; n0 += 128) {
            float acc[2][8];
            #pragma unroll
            for (int i = 0; i < 2; i++)
                #pragma unroll
                for (int j = 0; j < 8; j++) acc[i][j] = 0.f;

            for (int kc = 0; kc < DIMD; kc += CKC) {
                __syncthreads();
                #pragma unroll
                for (int m = lm; m < CW; m += 8)
                    As[lk][m] = seq[(size_t)tk[m] * DIMD + kc + lk];
                #pragma unroll
                for (int n = lm; n < 128; n += 8)
                    Bs[lk][n] = vocab[(size_t)(n0 + n) * DIMD + kc + lk];
                __syncthreads();

                #pragma unroll 8
                for (int k = 0; k < CKC; k++) {
                    float a0 = As[k][tm * 2];
                    float a1 = As[k][tm * 2 + 1];
                    float4 b0 = *(const float4*)&Bs[k][tn * 8];
                    float4 b1 = *(const float4*)&Bs[k][tn * 8 + 4];
                    float b[8] = {b0.x, b0.y, b0.z, b0.w, b1.x, b1.y, b1.z, b1.w};
                    #pragma unroll
                    for (int j = 0; j < 8; j++) {
                        acc[0][j] += a0 * b[j];
                        acc[1][j] += a1 * b[j];
                    }
                }
            }
            #pragma unroll
            for (int j = 0; j < 8; j++) {
                int n = n0 + tn * 8 + j;
                float vn = g_vnorm[n];
                #pragma unroll
                for (int i = 0; i < 2; i++) {
                    float sc = vn - acc[i][j];
                    if (sc < minv[i]) { minv[i] = sc; mini[i] = n; }
                }
            }
        }

        // reduce across the 16 tn-threads (16-lane groups)
        #pragma unroll
        for (int off = 8; off; off >>= 1) {
            #pragma unroll
            for (int i = 0; i < 2; i++) {
                float ov = __shfl_down_sync(0xffffffffu, minv[i], off, 16);
                int   oi = __shfl_down_sync(0xffffffffu, mini[i], off, 16);
                if (ov < minv[i] || (ov == minv[i] && oi < mini[i])) {
                    minv[i] = ov; mini[i] = oi;
                }
            }
        }
        if (tn == 0) {
            #pragma unroll
            for (int i = 0; i < 2; i++) {
                int row = tm * 2 + i;
                unsigned long long key =
                    ((unsigned long long)f2ord(minv[i]) << 32) | (uint32_t)mini[i];
                atomicMin(&g_key[tk[row]], key);
            }
        }
    }
}

// ============================ gather (reads packed key) ============================
__global__ void gather_kernel(const float* __restrict__ vocab,
                              float* __restrict__ out, int write_idx) {
    int token = blockIdx.x * 4 + (threadIdx.x >> 6);
    int l     = threadIdx.x & 63;
    int idx   = (int)(unsigned)(g_key[token] & 0xFFFFFFFFull);
    const float4* src = (const float4*)(vocab + (size_t)idx * DIMD);
    float4*       dst = (float4*)(out + (size_t)token * DIMD);
    dst[l] = src[l];
    if (write_idx && l == 0)
        out[(size_t)NTOK * DIMD + token] = (float)idx;
}

// ============================ launch ============================
extern "C" void kernel_launch(void* const* d_in, const int* in_sizes, int n_in,
                              void* d_out, int out_size) {
    const float* seq   = (const float*)d_in[0];
    const float* vocab = (const float*)d_in[1];
    float* out = (float*)d_out;
    int write_idx = (out_size >= NTOK * DIMD + NTOK) ? 1 : 0;

    cudaFuncSetAttribute(gemm_kernel,
                         cudaFuncAttributeMaxDynamicSharedMemorySize, SM_TOTAL);

    convert_kernel<<<8192 + 1024, 256>>>(seq, vocab);
    gemm_kernel<<<(NTOK / (MGRP * 128)) * NTIL, 256, SM_TOTAL>>>();
    reduce_kernel<<<NTOK / 128, 128>>>();
    cleanup_kernel<<<512, 256>>>(seq, vocab);
    gather_kernel<<<NTOK / 4, 256>>>(vocab, out, write_idx);
}

// round 8
// speedup vs baseline: 1.1115x; 1.1115x over previous
#include <cuda_runtime.h>
#include <cuda_fp16.h>
#include <cstdint>
#include <float.h>

#define NTOK 32768
#define DIMD 256
#define KVOC 8192
#define NTIL   64           // n-tiles of 128 codewords
#define MGRP   8            // m-tiles per CTA (persistent-B)
#define TAU  0.08f

// ---- device scratch ----
__device__ __half g_Ah[(size_t)NTOK * DIMD];   // 16 MB fp16 tokens
__device__ __half g_Bh[(size_t)KVOC * DIMD];   // 4 MB fp16 vocab
__device__ float  g_vnorm[KVOC];               // 0.5*||v||^2 fp32
__device__ float  g_s1[(size_t)NTIL * NTOK];
__device__ float  g_s2[(size_t)NTIL * NTOK];
__device__ int    g_i1[(size_t)NTIL * NTOK];
__device__ unsigned long long g_key[NTOK];
__device__ int    g_wl[NTOK];
__device__ int    g_wlcount;

// ---- smem layout: A stages (2x16KB) | B chunks (4x16KB) | vn | red ----
#define SA_OFF(st) ((st) * 16384)
#define SB_OFF(c)  (32768 + (c) * 16384)
#define SO_VN  98304
#define SO_R1  98816
#define SO_R2  100864
#define SO_RI  102912
#define SM_TOTAL 104960

// ============================ asm helpers ============================
__device__ __forceinline__ uint32_t smem_u32(const void* p) {
    uint32_t a;
    asm("{ .reg .u64 t; cvta.to.shared.u64 t, %1; cvt.u32.u64 %0, t; }"
        : "=r"(a) : "l"(p));
    return a;
}
__device__ __forceinline__ void cpasync16(uint32_t s, const void* g) {
    asm volatile("cp.async.cg.shared.global [%0], [%1], 16;" :: "r"(s), "l"(g));
}
#define CP_COMMIT() asm volatile("cp.async.commit_group;" ::: "memory")
#define CP_WAIT(N)  asm volatile("cp.async.wait_group " #N ";" ::: "memory")

__device__ __forceinline__ void ldsm4(uint32_t& r0, uint32_t& r1, uint32_t& r2,
                                      uint32_t& r3, uint32_t addr) {
    asm volatile("ldmatrix.sync.aligned.m8n8.x4.shared.b16 {%0,%1,%2,%3}, [%4];"
                 : "=r"(r0), "=r"(r1), "=r"(r2), "=r"(r3) : "r"(addr));
}
__device__ __forceinline__ void mma16816(float* d, const uint32_t* a,
                                         uint32_t b0, uint32_t b1) {
    asm volatile(
        "mma.sync.aligned.m16n8k16.row.col.f32.f16.f16.f32 "
        "{%0,%1,%2,%3},{%4,%5,%6,%7},{%8,%9},{%0,%1,%2,%3};"
        : "+f"(d[0]), "+f"(d[1]), "+f"(d[2]), "+f"(d[3])
        : "r"(a[0]), "r"(a[1]), "r"(a[2]), "r"(a[3]), "r"(b0), "r"(b1));
}
__device__ __forceinline__ uint32_t swz(uint32_t off) {
    return off ^ ((off >> 3) & 0x70);
}
// monotone float -> uint mapping (order preserving incl. negatives)
__device__ __forceinline__ uint32_t f2ord(float s) {
    uint32_t fb = __float_as_uint(s);
    return (fb & 0x80000000u) ? ~fb : (fb | 0x80000000u);
}

// =================== fused convert kernel (seq + vocab) ===================
__global__ void convert_kernel(const float* __restrict__ seq,
                               const float* __restrict__ vocab) {
    if (blockIdx.x == 0 && threadIdx.x == 0) g_wlcount = 0;
    if (blockIdx.x < 8192) {
        int idx = blockIdx.x * 256 + threadIdx.x;   // one float4 each
        int row = idx >> 6;
        int c4  = idx & 63;
        float4 x = ((const float4*)seq)[idx];
        __half2 a = __floats2half2_rn(x.x, x.y);
        __half2 b = __floats2half2_rn(x.z, x.w);
        uint2 u;
        u.x = *(uint32_t*)&a; u.y = *(uint32_t*)&b;
        *(uint2*)(g_Ah + (size_t)row * DIMD + c4 * 4) = u;
    } else {
        int row  = (blockIdx.x - 8192) * 8 + (threadIdx.x >> 5);
        int lane = threadIdx.x & 31;
        const float4* v = (const float4*)(vocab + (size_t)row * DIMD);
        float s = 0.f;
        #pragma unroll
        for (int c4 = lane; c4 < 64; c4 += 32) {
            float4 x = v[c4];
            s += x.x*x.x + x.y*x.y + x.z*x.z + x.w*x.w;
            __half2 a = __floats2half2_rn(x.x, x.y);
            __half2 b = __floats2half2_rn(x.z, x.w);
            uint2 u;
            u.x = *(uint32_t*)&a; u.y = *(uint32_t*)&b;
            *(uint2*)(g_Bh + (size_t)row * DIMD + c4 * 4) = u;
        }
        #pragma unroll
        for (int o = 16; o; o >>= 1) s += __shfl_xor_sync(0xffffffffu, s, o);
        if (lane == 0) g_vnorm[row] = 0.5f * s;
    }
}

// ================= persistent-B fp16 GEMM + fused top-2 =================
__global__ __launch_bounds__(256, 2)
void gemm_kernel() {
    extern __shared__ char smem[];
    uint32_t sbase = smem_u32(smem);
    float* s_vn = (float*)(smem + SO_VN);
    float* r1a  = (float*)(smem + SO_R1);
    float* r2a  = (float*)(smem + SO_R2);
    int*   ria  = (int*)  (smem + SO_RI);

    const int tid = threadIdx.x, lane = tid & 31, wid = tid >> 5;
    const int wm = wid & 1, wn = wid >> 1;          // 2 x 4 warp grid
    const int bn = blockIdx.x & (NTIL - 1);         // n-tile (fast-varying)
    const int mg = blockIdx.x >> 6;                 // m-group (8 m-tiles)
    const int n0 = bn * 128;
    const int mbase = mg * MGRP * 128;

    const char* Bb = (const char*)g_Bh + (size_t)n0 * 512;

    // ---- load full B n-tile (64KB = 4 chunk-swizzled sub-tiles), one group
    #pragma unroll
    for (int q = 0; q < 16; q++) {
        int c  = q >> 2;
        int p  = tid + 256 * (q & 3);
        int r  = p >> 3, jj = p & 7;
        cpasync16(sbase + SB_OFF(c) + swz(r * 128 + jj * 16),
                  Bb + (size_t)r * 512 + c * 128 + jj * 16);
    }
    CP_COMMIT();

    // A chunk j (j = mt*4 + c) -> stage (c & 1)
#define LOAD_A(J)                                                              \
    {                                                                          \
        int mt_ = (J) >> 2, c_ = (J) & 3;                                      \
        uint32_t st = sbase + SA_OFF(c_ & 1);                                  \
        const char* Asrc = (const char*)g_Ah                                   \
            + (size_t)(mbase + mt_ * 128) * 512 + c_ * 128;                    \
        _Pragma("unroll")                                                      \
        for (int q = 0; q < 4; q++) {                                          \
            int p = tid + 256 * q; int r = p >> 3, jj = p & 7;                 \
            cpasync16(st + swz(r * 128 + jj * 16),                             \
                      Asrc + (size_t)r * 512 + jj * 16);                       \
        }                                                                      \
        CP_COMMIT();                                                           \
    }

    LOAD_A(0)
    LOAD_A(1)
    if (tid < 128) s_vn[tid] = g_vnorm[n0 + tid];

#define COMPUTE_CHUNK(ST, CB)                                                  \
    {                                                                          \
        uint32_t Abase = sbase + SA_OFF(ST);                                   \
        uint32_t Bbase = sbase + SB_OFF(CB);                                   \
        _Pragma("unroll")                                                      \
        for (int ks = 0; ks < 4; ks++) {                                       \
            uint32_t af[4][4];                                                 \
            _Pragma("unroll")                                                  \
            for (int mt = 0; mt < 4; mt++) {                                   \
                int row = wm * 64 + mt * 16 + (lane & 15);                     \
                uint32_t ad = Abase + swz(row * 128 + ks * 32 + (lane >> 4) * 16); \
                ldsm4(af[mt][0], af[mt][1], af[mt][2], af[mt][3], ad);         \
            }                                                                  \
            uint32_t bf[2][4];                                                 \
            _Pragma("unroll")                                                  \
            for (int np = 0; np < 2; np++) {                                   \
                int row = wn * 32 + np * 16 + (lane & 15);                     \
                uint32_t bd = Bbase + swz(row * 128 + ks * 32 + (lane >> 4) * 16); \
                ldsm4(bf[np][0], bf[np][1], bf[np][2], bf[np][3], bd);         \
            }                                                                  \
            _Pragma("unroll")                                                  \
            for (int mt = 0; mt < 4; mt++) {                                   \
                _Pragma("unroll")                                              \
                for (int nt = 0; nt < 4; nt++) {                               \
                    int np = nt >> 1, sub = nt & 1;                            \
                    mma16816(acc[mt][nt], af[mt], bf[np][sub], bf[np][sub + 2]); \
                }                                                              \
            }                                                                  \
        }                                                                      \
    }

    float acc[4][4][4];

    for (int mt = 0; mt < MGRP; mt++) {
        #pragma unroll
        for (int i = 0; i < 4; i++)
            #pragma unroll
            for (int j = 0; j < 4; j++)
                #pragma unroll
                for (int c = 0; c < 4; c++) acc[i][j][c] = 0.f;

        #pragma unroll
        for (int c = 0; c < 4; c++) {
            if (mt == MGRP - 1 && c == 3) { CP_WAIT(0); } else { CP_WAIT(1); }
            __syncthreads();
            COMPUTE_CHUNK(c & 1, c)
            __syncthreads();
            int nj = mt * 4 + c + 2;
            if (nj < MGRP * 4) LOAD_A(nj)
        }

        // ---- fused top-2 epilogue for this m-tile ----
        const int m0 = mbase + mt * 128;
        float m1[8], m2[8]; int i1[8];             // slot = mtile*2 + rowgroup
        #pragma unroll
        for (int s = 0; s < 8; s++) { m1[s] = FLT_MAX; m2[s] = FLT_MAX; i1[s] = 0x7FFFFFFF; }

        #pragma unroll
        for (int nt = 0; nt < 4; nt++) {
            int nloc_base = wn * 32 + (nt >> 1) * 16 + (nt & 1) * 8 + (lane & 3) * 2;
            #pragma unroll
            for (int cc = 0; cc < 2; cc++) {
                int nloc = nloc_base + cc;
                float vn = s_vn[nloc];
                int n = n0 + nloc;
                #pragma unroll
                for (int mq = 0; mq < 4; mq++) {
                    #pragma unroll
                    for (int rg = 0; rg < 2; rg++) {
                        int s_ = mq * 2 + rg;
                        float sc = vn - acc[mq][nt][rg * 2 + cc];
                        if (sc < m1[s_]) { m2[s_] = m1[s_]; m1[s_] = sc; i1[s_] = n; }
                        else if (sc < m2[s_]) m2[s_] = sc;
                    }
                }
            }
        }
        #pragma unroll
        for (int s = 0; s < 8; s++) {
            #pragma unroll
            for (int off = 1; off <= 2; off <<= 1) {
                float om1 = __shfl_xor_sync(0xffffffffu, m1[s], off);
                float om2 = __shfl_xor_sync(0xffffffffu, m2[s], off);
                int   oi  = __shfl_xor_sync(0xffffffffu, i1[s], off);
                if (om1 < m1[s] || (om1 == m1[s] && oi < i1[s])) {
                    m2[s] = fminf(m1[s], om2); m1[s] = om1; i1[s] = oi;
                } else {
                    m2[s] = fminf(m2[s], om1);
                }
            }
        }
        if ((lane & 3) == 0) {
            #pragma unroll
            for (int mq = 0; mq < 4; mq++)
                #pragma unroll
                for (int rg = 0; rg < 2; rg++) {
                    int s_ = mq * 2 + rg;
                    int row = wm * 64 + mq * 16 + rg * 8 + (lane >> 2);
                    r1a[row * 4 + wn] = m1[s_];
                    r2a[row * 4 + wn] = m2[s_];
                    ria[row * 4 + wn] = i1[s_];
                }
        }
        __syncthreads();
        if (tid < 128) {
            float M1 = FLT_MAX, M2 = FLT_MAX; int I1 = 0x7FFFFFFF;
            #pragma unroll
            for (int w = 0; w < 4; w++) {
                float a1 = r1a[tid * 4 + w], a2 = r2a[tid * 4 + w];
                int   ai = ria[tid * 4 + w];
                if (a1 < M1 || (a1 == M1 && ai < I1)) {
                    M2 = fminf(M1, a2); M1 = a1; I1 = ai;
                } else {
                    M2 = fminf(M2, a1);
                }
            }
            int token = m0 + tid;
            g_s1[(size_t)bn * NTOK + token] = M1;
            g_s2[(size_t)bn * NTOK + token] = M2;
            g_i1[(size_t)bn * NTOK + token] = I1;
        }
    }
#undef COMPUTE_CHUNK
#undef LOAD_A
}

// ============================ reduce + flag ============================
__global__ void reduce_kernel() {
    int t = blockIdx.x * blockDim.x + threadIdx.x;
    float m1 = FLT_MAX, m2 = FLT_MAX; int i1 = 0x7FFFFFFF;
    #pragma unroll 4
    for (int nt = 0; nt < NTIL; nt++) {
        float s1 = g_s1[(size_t)nt * NTOK + t];
        float s2 = g_s2[(size_t)nt * NTOK + t];
        int   ii = g_i1[(size_t)nt * NTOK + t];
        if (s1 < m1 || (s1 == m1 && ii < i1)) {
            m2 = fminf(m1, s2); m1 = s1; i1 = ii;
        } else {
            m2 = fminf(m2, s1);
        }
    }
    if (m2 - m1 < TAU) {
        g_key[t] = 0xFFFFFFFFFFFFFFFFull;       // sentinel: exact pass decides
        int slot = atomicAdd(&g_wlcount, 1);
        g_wl[slot] = t;
    } else {
        g_key[t] = ((unsigned long long)f2ord(m1) << 32) | (uint32_t)i1;
    }
}

// ====== exact fp32 cleanup: R1-grade tile, (128 tokens) x (1024-cw slice) ======
#define CW   128         // tokens per work item (8x8 register tile)
#define CSL  8           // vocab slices (KVOC/CSL = 1024 each)
#define CKC  32
#define CPAD 132
__global__ __launch_bounds__(256, 2)
void cleanup_kernel(const float* __restrict__ seq, const float* __restrict__ vocab) {
    __shared__ float As[CKC][CPAD];  // [k][m]
    __shared__ float Bs[CKC][CPAD];  // [k][n]
    __shared__ int   tk[CW];

    const int nf = g_wlcount;
    if (nf == 0) return;
    const int ngrp   = (nf + CW - 1) / CW;
    const int nitems = ngrp * CSL;

    const int tid = threadIdx.x;
    const int tm  = tid >> 4;        // 0..15 -> token rows tm*8..tm*8+7
    const int tn  = tid & 15;        // 0..15 -> cw cols tn*8..tn*8+7
    const int lk  = tid & 31;
    const int lm  = tid >> 5;        // 0..7

    for (int item = blockIdx.x; item < nitems; item += gridDim.x) {
        const int tg    = item / CSL;
        const int nbase = (item % CSL) * (KVOC / CSL);

        __syncthreads();   // protect tk across grid-stride iterations
        if (tid < CW) {
            int w = tg * CW + tid;
            tk[tid] = g_wl[w < nf ? w : (nf - 1)];
        }
        __syncthreads();

        float minv[8]; int mini[8];
        #pragma unroll
        for (int i = 0; i < 8; i++) { minv[i] = FLT_MAX; mini[i] = 0; }

        for (int n0 = nbase; n0 < nbase + KVOC / CSL; n0 += 128) {
            float acc[8][8];
            #pragma unroll
            for (int i = 0; i < 8; i++)
                #pragma unroll
                for (int j = 0; j < 8; j++) acc[i][j] = 0.f;

            for (int kc = 0; kc < DIMD; kc += CKC) {
                __syncthreads();
                #pragma unroll
                for (int m = lm; m < CW; m += 8)
                    As[lk][m] = seq[(size_t)tk[m] * DIMD + kc + lk];
                #pragma unroll
                for (int n = lm; n < 128; n += 8)
                    Bs[lk][n] = vocab[(size_t)(n0 + n) * DIMD + kc + lk];
                __syncthreads();

                #pragma unroll 8
                for (int k = 0; k < CKC; k++) {
                    float4 a0 = *(const float4*)&As[k][tm * 8];
                    float4 a1 = *(const float4*)&As[k][tm * 8 + 4];
                    float4 b0 = *(const float4*)&Bs[k][tn * 8];
                    float4 b1 = *(const float4*)&Bs[k][tn * 8 + 4];
                    float a[8] = {a0.x, a0.y, a0.z, a0.w, a1.x, a1.y, a1.z, a1.w};
                    float b[8] = {b0.x, b0.y, b0.z, b0.w, b1.x, b1.y, b1.z, b1.w};
                    #pragma unroll
                    for (int i = 0; i < 8; i++)
                        #pragma unroll
                        for (int j = 0; j < 8; j++)
                            acc[i][j] += a[i] * b[j];
                }
            }
            #pragma unroll
            for (int j = 0; j < 8; j++) {
                int n = n0 + tn * 8 + j;
                float vn = g_vnorm[n];
                #pragma unroll
                for (int i = 0; i < 8; i++) {
                    float sc = vn - acc[i][j];
                    if (sc < minv[i]) { minv[i] = sc; mini[i] = n; }
                }
            }
        }

        // reduce across the 16 tn-threads (16-lane groups)
        #pragma unroll
        for (int off = 8; off; off >>= 1) {
            #pragma unroll
            for (int i = 0; i < 8; i++) {
                float ov = __shfl_down_sync(0xffffffffu, minv[i], off, 16);
                int   oi = __shfl_down_sync(0xffffffffu, mini[i], off, 16);
                if (ov < minv[i] || (ov == minv[i] && oi < mini[i])) {
                    minv[i] = ov; mini[i] = oi;
                }
            }
        }
        if (tn == 0) {
            #pragma unroll
            for (int i = 0; i < 8; i++) {
                unsigned long long key =
                    ((unsigned long long)f2ord(minv[i]) << 32) | (uint32_t)mini[i];
                atomicMin(&g_key[tk[tm * 8 + i]], key);
            }
        }
    }
}

// ============================ gather (reads packed key) ============================
__global__ void gather_kernel(const float* __restrict__ vocab,
                              float* __restrict__ out, int write_idx) {
    int token = blockIdx.x * 4 + (threadIdx.x >> 6);
    int l     = threadIdx.x & 63;
    int idx   = (int)(unsigned)(g_key[token] & 0xFFFFFFFFull);
    const float4* src = (const float4*)(vocab + (size_t)idx * DIMD);
    float4*       dst = (float4*)(out + (size_t)token * DIMD);
    dst[l] = src[l];
    if (write_idx && l == 0)
        out[(size_t)NTOK * DIMD + token] = (float)idx;
}

// ============================ launch ============================
extern "C" void kernel_launch(void* const* d_in, const int* in_sizes, int n_in,
                              void* d_out, int out_size) {
    const float* seq   = (const float*)d_in[0];
    const float* vocab = (const float*)d_in[1];
    float* out = (float*)d_out;
    int write_idx = (out_size >= NTOK * DIMD + NTOK) ? 1 : 0;

    cudaFuncSetAttribute(gemm_kernel,
                         cudaFuncAttributeMaxDynamicSharedMemorySize, SM_TOTAL);

    convert_kernel<<<8192 + 1024, 256>>>(seq, vocab);
    gemm_kernel<<<(NTOK / (MGRP * 128)) * NTIL, 256, SM_TOTAL>>>();
    reduce_kernel<<<NTOK / 128, 128>>>();
    cleanup_kernel<<<592, 256>>>(seq, vocab);
    gather_kernel<<<NTOK / 4, 256>>>(vocab, out, write_idx);
}

// round 9
// speedup vs baseline: 1.2464x; 1.1214x over previous
#include <cuda_runtime.h>
#include <cuda_fp16.h>
#include <cstdint>
#include <float.h>

#define NTOK 32768
#define DIMD 256
#define KVOC 8192
#define NTIL   64           // n-tiles of 128 codewords
#define MGRP   8            // m-tiles per CTA (persistent-B)
#define TAU  0.08f

// ---- device scratch ----
__device__ __half g_Ah[(size_t)NTOK * DIMD];   // 16 MB fp16 tokens
__device__ __half g_Bh[(size_t)KVOC * DIMD];   // 4 MB fp16 vocab
__device__ float  g_vnorm[KVOC];               // 0.5*||v||^2 fp32
__device__ float  g_s1[(size_t)NTIL * NTOK];
__device__ float  g_s2[(size_t)NTIL * NTOK];
__device__ int    g_i1[(size_t)NTIL * NTOK];
__device__ unsigned long long g_key[NTOK];
__device__ int    g_wl[NTOK];
__device__ int    g_wlcount;

// ---- smem layout: A stages (2x16KB) | B chunks (4x16KB) | vn | red ----
#define SA_OFF(st) ((st) * 16384)
#define SB_OFF(c)  (32768 + (c) * 16384)
#define SO_VN  98304
#define SO_R1  98816
#define SO_R2  100864
#define SO_RI  102912
#define SM_TOTAL 104960

// ============================ asm helpers ============================
__device__ __forceinline__ uint32_t smem_u32(const void* p) {
    uint32_t a;
    asm("{ .reg .u64 t; cvta.to.shared.u64 t, %1; cvt.u32.u64 %0, t; }"
        : "=r"(a) : "l"(p));
    return a;
}
__device__ __forceinline__ void cpasync16(uint32_t s, const void* g) {
    asm volatile("cp.async.cg.shared.global [%0], [%1], 16;" :: "r"(s), "l"(g));
}
#define CP_COMMIT() asm volatile("cp.async.commit_group;" ::: "memory")
#define CP_WAIT(N)  asm volatile("cp.async.wait_group " #N ";" ::: "memory")

__device__ __forceinline__ void ldsm4(uint32_t& r0, uint32_t& r1, uint32_t& r2,
                                      uint32_t& r3, uint32_t addr) {
    asm volatile("ldmatrix.sync.aligned.m8n8.x4.shared.b16 {%0,%1,%2,%3}, [%4];"
                 : "=r"(r0), "=r"(r1), "=r"(r2), "=r"(r3) : "r"(addr));
}
__device__ __forceinline__ void mma16816(float* d, const uint32_t* a,
                                         uint32_t b0, uint32_t b1) {
    asm volatile(
        "mma.sync.aligned.m16n8k16.row.col.f32.f16.f16.f32 "
        "{%0,%1,%2,%3},{%4,%5,%6,%7},{%8,%9},{%0,%1,%2,%3};"
        : "+f"(d[0]), "+f"(d[1]), "+f"(d[2]), "+f"(d[3])
        : "r"(a[0]), "r"(a[1]), "r"(a[2]), "r"(a[3]), "r"(b0), "r"(b1));
}
__device__ __forceinline__ uint32_t swz(uint32_t off) {
    return off ^ ((off >> 3) & 0x70);
}
// monotone float -> uint mapping (order preserving incl. negatives)
__device__ __forceinline__ uint32_t f2ord(float s) {
    uint32_t fb = __float_as_uint(s);
    return (fb & 0x80000000u) ? ~fb : (fb | 0x80000000u);
}

// =================== fused convert kernel (seq + vocab) ===================
__global__ void convert_kernel(const float* __restrict__ seq,
                               const float* __restrict__ vocab) {
    if (blockIdx.x == 0 && threadIdx.x == 0) g_wlcount = 0;
    if (blockIdx.x < 8192) {
        int idx = blockIdx.x * 256 + threadIdx.x;   // one float4 each
        int row = idx >> 6;
        int c4  = idx & 63;
        float4 x = ((const float4*)seq)[idx];
        __half2 a = __floats2half2_rn(x.x, x.y);
        __half2 b = __floats2half2_rn(x.z, x.w);
        uint2 u;
        u.x = *(uint32_t*)&a; u.y = *(uint32_t*)&b;
        *(uint2*)(g_Ah + (size_t)row * DIMD + c4 * 4) = u;
    } else {
        int row  = (blockIdx.x - 8192) * 8 + (threadIdx.x >> 5);
        int lane = threadIdx.x & 31;
        const float4* v = (const float4*)(vocab + (size_t)row * DIMD);
        float s = 0.f;
        #pragma unroll
        for (int c4 = lane; c4 < 64; c4 += 32) {
            float4 x = v[c4];
            s += x.x*x.x + x.y*x.y + x.z*x.z + x.w*x.w;
            __half2 a = __floats2half2_rn(x.x, x.y);
            __half2 b = __floats2half2_rn(x.z, x.w);
            uint2 u;
            u.x = *(uint32_t*)&a; u.y = *(uint32_t*)&b;
            *(uint2*)(g_Bh + (size_t)row * DIMD + c4 * 4) = u;
        }
        #pragma unroll
        for (int o = 16; o; o >>= 1) s += __shfl_xor_sync(0xffffffffu, s, o);
        if (lane == 0) g_vnorm[row] = 0.5f * s;
    }
}

// ================= persistent-B fp16 GEMM + fused top-2 =================
__global__ __launch_bounds__(256, 2)
void gemm_kernel() {
    extern __shared__ char smem[];
    uint32_t sbase = smem_u32(smem);
    float* s_vn = (float*)(smem + SO_VN);
    float* r1a  = (float*)(smem + SO_R1);
    float* r2a  = (float*)(smem + SO_R2);
    int*   ria  = (int*)  (smem + SO_RI);

    const int tid = threadIdx.x, lane = tid & 31, wid = tid >> 5;
    const int wm = wid & 1, wn = wid >> 1;          // 2 x 4 warp grid
    const int bn = blockIdx.x & (NTIL - 1);         // n-tile (fast-varying)
    const int mg = blockIdx.x >> 6;                 // m-group (8 m-tiles)
    const int n0 = bn * 128;
    const int mbase = mg * MGRP * 128;

    const char* Bb = (const char*)g_Bh + (size_t)n0 * 512;

    // ---- load full B n-tile (64KB = 4 chunk-swizzled sub-tiles), one group
    #pragma unroll
    for (int q = 0; q < 16; q++) {
        int c  = q >> 2;
        int p  = tid + 256 * (q & 3);
        int r  = p >> 3, jj = p & 7;
        cpasync16(sbase + SB_OFF(c) + swz(r * 128 + jj * 16),
                  Bb + (size_t)r * 512 + c * 128 + jj * 16);
    }
    CP_COMMIT();

    // A chunk j (j = mt*4 + c) -> stage (c & 1)
#define LOAD_A(J)                                                              \
    {                                                                          \
        int mt_ = (J) >> 2, c_ = (J) & 3;                                      \
        uint32_t st = sbase + SA_OFF(c_ & 1);                                  \
        const char* Asrc = (const char*)g_Ah                                   \
            + (size_t)(mbase + mt_ * 128) * 512 + c_ * 128;                    \
        _Pragma("unroll")                                                      \
        for (int q = 0; q < 4; q++) {                                          \
            int p = tid + 256 * q; int r = p >> 3, jj = p & 7;                 \
            cpasync16(st + swz(r * 128 + jj * 16),                             \
                      Asrc + (size_t)r * 512 + jj * 16);                       \
        }                                                                      \
        CP_COMMIT();                                                           \
    }

    LOAD_A(0)
    LOAD_A(1)
    if (tid < 128) s_vn[tid] = g_vnorm[n0 + tid];

#define COMPUTE_CHUNK(ST, CB)                                                  \
    {                                                                          \
        uint32_t Abase = sbase + SA_OFF(ST);                                   \
        uint32_t Bbase = sbase + SB_OFF(CB);                                   \
        _Pragma("unroll")                                                      \
        for (int ks = 0; ks < 4; ks++) {                                       \
            uint32_t af[4][4];                                                 \
            _Pragma("unroll")                                                  \
            for (int mt = 0; mt < 4; mt++) {                                   \
                int row = wm * 64 + mt * 16 + (lane & 15);                     \
                uint32_t ad = Abase + swz(row * 128 + ks * 32 + (lane >> 4) * 16); \
                ldsm4(af[mt][0], af[mt][1], af[mt][2], af[mt][3], ad);         \
            }                                                                  \
            uint32_t bf[2][4];                                                 \
            _Pragma("unroll")                                                  \
            for (int np = 0; np < 2; np++) {                                   \
                int row = wn * 32 + np * 16 + (lane & 15);                     \
                uint32_t bd = Bbase + swz(row * 128 + ks * 32 + (lane >> 4) * 16); \
                ldsm4(bf[np][0], bf[np][1], bf[np][2], bf[np][3], bd);         \
            }                                                                  \
            _Pragma("unroll")                                                  \
            for (int mt = 0; mt < 4; mt++) {                                   \
                _Pragma("unroll")                                              \
                for (int nt = 0; nt < 4; nt++) {                               \
                    int np = nt >> 1, sub = nt & 1;                            \
                    mma16816(acc[mt][nt], af[mt], bf[np][sub], bf[np][sub + 2]); \
                }                                                              \
            }                                                                  \
        }                                                                      \
    }

    float acc[4][4][4];

    for (int mt = 0; mt < MGRP; mt++) {
        #pragma unroll
        for (int i = 0; i < 4; i++)
            #pragma unroll
            for (int j = 0; j < 4; j++)
                #pragma unroll
                for (int c = 0; c < 4; c++) acc[i][j][c] = 0.f;

        #pragma unroll
        for (int c = 0; c < 4; c++) {
            if (mt == MGRP - 1 && c == 3) { CP_WAIT(0); } else { CP_WAIT(1); }
            __syncthreads();
            COMPUTE_CHUNK(c & 1, c)
            __syncthreads();
            int nj = mt * 4 + c + 2;
            if (nj < MGRP * 4) LOAD_A(nj)
        }

        // ---- fused top-2 epilogue for this m-tile ----
        const int m0 = mbase + mt * 128;
        float m1[8], m2[8]; int i1[8];             // slot = mtile*2 + rowgroup
        #pragma unroll
        for (int s = 0; s < 8; s++) { m1[s] = FLT_MAX; m2[s] = FLT_MAX; i1[s] = 0x7FFFFFFF; }

        #pragma unroll
        for (int nt = 0; nt < 4; nt++) {
            int nloc_base = wn * 32 + (nt >> 1) * 16 + (nt & 1) * 8 + (lane & 3) * 2;
            #pragma unroll
            for (int cc = 0; cc < 2; cc++) {
                int nloc = nloc_base + cc;
                float vn = s_vn[nloc];
                int n = n0 + nloc;
                #pragma unroll
                for (int mq = 0; mq < 4; mq++) {
                    #pragma unroll
                    for (int rg = 0; rg < 2; rg++) {
                        int s_ = mq * 2 + rg;
                        float sc = vn - acc[mq][nt][rg * 2 + cc];
                        if (sc < m1[s_]) { m2[s_] = m1[s_]; m1[s_] = sc; i1[s_] = n; }
                        else if (sc < m2[s_]) m2[s_] = sc;
                    }
                }
            }
        }
        #pragma unroll
        for (int s = 0; s < 8; s++) {
            #pragma unroll
            for (int off = 1; off <= 2; off <<= 1) {
                float om1 = __shfl_xor_sync(0xffffffffu, m1[s], off);
                float om2 = __shfl_xor_sync(0xffffffffu, m2[s], off);
                int   oi  = __shfl_xor_sync(0xffffffffu, i1[s], off);
                if (om1 < m1[s] || (om1 == m1[s] && oi < i1[s])) {
                    m2[s] = fminf(m1[s], om2); m1[s] = om1; i1[s] = oi;
                } else {
                    m2[s] = fminf(m2[s], om1);
                }
            }
        }
        if ((lane & 3) == 0) {
            #pragma unroll
            for (int mq = 0; mq < 4; mq++)
                #pragma unroll
                for (int rg = 0; rg < 2; rg++) {
                    int s_ = mq * 2 + rg;
                    int row = wm * 64 + mq * 16 + rg * 8 + (lane >> 2);
                    r1a[row * 4 + wn] = m1[s_];
                    r2a[row * 4 + wn] = m2[s_];
                    ria[row * 4 + wn] = i1[s_];
                }
        }
        __syncthreads();
        if (tid < 128) {
            float M1 = FLT_MAX, M2 = FLT_MAX; int I1 = 0x7FFFFFFF;
            #pragma unroll
            for (int w = 0; w < 4; w++) {
                float a1 = r1a[tid * 4 + w], a2 = r2a[tid * 4 + w];
                int   ai = ria[tid * 4 + w];
                if (a1 < M1 || (a1 == M1 && ai < I1)) {
                    M2 = fminf(M1, a2); M1 = a1; I1 = ai;
                } else {
                    M2 = fminf(M2, a1);
                }
            }
            int token = m0 + tid;
            g_s1[(size_t)bn * NTOK + token] = M1;
            g_s2[(size_t)bn * NTOK + token] = M2;
            g_i1[(size_t)bn * NTOK + token] = I1;
        }
    }
#undef COMPUTE_CHUNK
#undef LOAD_A
}

// ============================ reduce + flag ============================
__global__ void reduce_kernel() {
    int t = blockIdx.x * blockDim.x + threadIdx.x;
    float m1 = FLT_MAX, m2 = FLT_MAX; int i1 = 0x7FFFFFFF;
    #pragma unroll 4
    for (int nt = 0; nt < NTIL; nt++) {
        float s1 = g_s1[(size_t)nt * NTOK + t];
        float s2 = g_s2[(size_t)nt * NTOK + t];
        int   ii = g_i1[(size_t)nt * NTOK + t];
        if (s1 < m1 || (s1 == m1 && ii < i1)) {
            m2 = fminf(m1, s2); m1 = s1; i1 = ii;
        } else {
            m2 = fminf(m2, s1);
        }
    }
    if (m2 - m1 < TAU) {
        g_key[t] = 0xFFFFFFFFFFFFFFFFull;       // sentinel: exact pass decides
        int slot = atomicAdd(&g_wlcount, 1);
        g_wl[slot] = t;
    } else {
        g_key[t] = ((unsigned long long)f2ord(m1) << 32) | (uint32_t)i1;
    }
}

// ====== exact fp32 cleanup: fine grain, (32 tokens) x (128-cw slice) ======
#define CW   32          // tokens per work item
#define CSL  64          // vocab slices (KVOC/CSL = 128 each)
#define CKC  32
__global__ __launch_bounds__(256, 2)
void cleanup_kernel(const float* __restrict__ seq, const float* __restrict__ vocab) {
    __shared__ float As[CKC][33];    // [k][m]
    __shared__ float Bs[CKC][132];   // [k][n]
    __shared__ int   tk[CW];

    const int nf = g_wlcount;
    if (nf == 0) return;
    const int ngrp   = (nf + CW - 1) / CW;
    const int nitems = ngrp * CSL;

    const int tid = threadIdx.x;
    const int tm  = tid >> 4;        // 0..15 -> token rows tm*2, tm*2+1
    const int tn  = tid & 15;        // 0..15 -> 8 codeword cols
    const int lk  = tid & 31;
    const int lm  = tid >> 5;        // 0..7

    for (int item = blockIdx.x; item < nitems; item += gridDim.x) {
        const int tg = item >> 6;              // token group
        const int n0 = (item & 63) * 128;      // codeword block

        __syncthreads();   // protect tk across grid-stride iterations
        if (tid < CW) {
            int w = tg * CW + tid;
            tk[tid] = g_wl[w < nf ? w : (nf - 1)];
        }
        __syncthreads();

        float minv[2]; int mini[2];
        minv[0] = minv[1] = FLT_MAX; mini[0] = mini[1] = 0;

        float acc[2][8];
        #pragma unroll
        for (int i = 0; i < 2; i++)
            #pragma unroll
            for (int j = 0; j < 8; j++) acc[i][j] = 0.f;

        for (int kc = 0; kc < DIMD; kc += CKC) {
            __syncthreads();
            #pragma unroll
            for (int m = lm; m < CW; m += 8)
                As[lk][m] = seq[(size_t)tk[m] * DIMD + kc + lk];
            #pragma unroll
            for (int n = lm; n < 128; n += 8)
                Bs[lk][n] = vocab[(size_t)(n0 + n) * DIMD + kc + lk];
            __syncthreads();

            #pragma unroll 8
            for (int k = 0; k < CKC; k++) {
                float a0 = As[k][tm * 2];
                float a1 = As[k][tm * 2 + 1];
                float4 b0 = *(const float4*)&Bs[k][tn * 8];
                float4 b1 = *(const float4*)&Bs[k][tn * 8 + 4];
                float b[8] = {b0.x, b0.y, b0.z, b0.w, b1.x, b1.y, b1.z, b1.w};
                #pragma unroll
                for (int j = 0; j < 8; j++) {
                    acc[0][j] += a0 * b[j];
                    acc[1][j] += a1 * b[j];
                }
            }
        }
        #pragma unroll
        for (int j = 0; j < 8; j++) {
            int n = n0 + tn * 8 + j;
            float vn = g_vnorm[n];
            #pragma unroll
            for (int i = 0; i < 2; i++) {
                float sc = vn - acc[i][j];
                if (sc < minv[i]) { minv[i] = sc; mini[i] = n; }
            }
        }

        // reduce across the 16 tn-threads (16-lane groups)
        #pragma unroll
        for (int off = 8; off; off >>= 1) {
            #pragma unroll
            for (int i = 0; i < 2; i++) {
                float ov = __shfl_down_sync(0xffffffffu, minv[i], off, 16);
                int   oi = __shfl_down_sync(0xffffffffu, mini[i], off, 16);
                if (ov < minv[i] || (ov == minv[i] && oi < mini[i])) {
                    minv[i] = ov; mini[i] = oi;
                }
            }
        }
        if (tn == 0) {
            #pragma unroll
            for (int i = 0; i < 2; i++) {
                unsigned long long key =
                    ((unsigned long long)f2ord(minv[i]) << 32) | (uint32_t)mini[i];
                atomicMin(&g_key[tk[tm * 2 + i]], key);
            }
        }
    }
}

// ============================ gather (reads packed key) ============================
__global__ void gather_kernel(const float* __restrict__ vocab,
                              float* __restrict__ out, int write_idx) {
    int token = blockIdx.x * 4 + (threadIdx.x >> 6);
    int l     = threadIdx.x & 63;
    int idx   = (int)(unsigned)(g_key[token] & 0xFFFFFFFFull);
    const float4* src = (const float4*)(vocab + (size_t)idx * DIMD);
    float4*       dst = (float4*)(out + (size_t)token * DIMD);
    dst[l] = src[l];
    if (write_idx && l == 0)
        out[(size_t)NTOK * DIMD + token] = (float)idx;
}

// ============================ launch ============================
extern "C" void kernel_launch(void* const* d_in, const int* in_sizes, int n_in,
                              void* d_out, int out_size) {
    const float* seq   = (const float*)d_in[0];
    const float* vocab = (const float*)d_in[1];
    float* out = (float*)d_out;
    int write_idx = (out_size >= NTOK * DIMD + NTOK) ? 1 : 0;

    cudaFuncSetAttribute(gemm_kernel,
                         cudaFuncAttributeMaxDynamicSharedMemorySize, SM_TOTAL);

    convert_kernel<<<8192 + 1024, 256>>>(seq, vocab);
    gemm_kernel<<<(NTOK / (MGRP * 128)) * NTIL, 256, SM_TOTAL>>>();
    reduce_kernel<<<NTOK / 128, 128>>>();
    cleanup_kernel<<<1184, 256>>>(seq, vocab);
    gather_kernel<<<NTOK / 4, 256>>>(vocab, out, write_idx);
}

// round 10
// speedup vs baseline: 1.8395x; 1.4758x over previous
#include <cuda_runtime.h>
#include <cuda_fp16.h>
#include <cstdint>
#include <float.h>

#define NTOK 32768
#define DIMD 256
#define KVOC 8192
#define NTIL   64           // n-tiles of 128 codewords
#define MGRP   8            // m-tiles per CTA (persistent-B coarse gemm)
#define TAU  0.08f
#define KSPL 768            // split-K: [x_hi|x_lo|x_hi] . [v_hi|v_hi|v_lo]

// ---- device scratch ----
__device__ __half g_Ah[(size_t)NTOK * DIMD];   // 16 MB fp16 tokens (coarse)
__device__ __half g_Bh[(size_t)KVOC * DIMD];   // 4 MB fp16 vocab (coarse)
__device__ __half g_As[(size_t)NTOK * KSPL];   // 50 MB split-A (flagged, compact)
__device__ __half g_Bs[(size_t)KVOC * KSPL];   // 12.6 MB split-B
__device__ float  g_vnorm[KVOC];               // 0.5*||v||^2 fp32
__device__ float  g_s1[(size_t)NTIL * NTOK];
__device__ float  g_s2[(size_t)NTIL * NTOK];
__device__ int    g_i1[(size_t)NTIL * NTOK];
__device__ unsigned long long g_key[NTOK];
__device__ int    g_wl[NTOK];
__device__ int    g_wlcount;

// ---- smem layout coarse gemm: A stages (2x16KB) | B chunks (4x16KB) ----
#define SA_OFF(st) ((st) * 16384)
#define SB_OFF(c)  (32768 + (c) * 16384)
#define SO_VN  98304
#define SO_R1  98816
#define SO_R2  100864
#define SO_RI  102912
#define SM_TOTAL 104960

// ---- smem layout cleanup gemm: 2 stages x (A 16KB + B 16KB) ----
#define CU_ST(st)  ((st) * 32768)
#define CU_VN  65536
#define CU_R1  66048
#define CU_RI  68096
#define CU_TK  70144
#define CU_SM_TOTAL 70656

// ============================ asm helpers ============================
__device__ __forceinline__ uint32_t smem_u32(const void* p) {
    uint32_t a;
    asm("{ .reg .u64 t; cvta.to.shared.u64 t, %1; cvt.u32.u64 %0, t; }"
        : "=r"(a) : "l"(p));
    return a;
}
__device__ __forceinline__ void cpasync16(uint32_t s, const void* g) {
    asm volatile("cp.async.cg.shared.global [%0], [%1], 16;" :: "r"(s), "l"(g));
}
#define CP_COMMIT() asm volatile("cp.async.commit_group;" ::: "memory")
#define CP_WAIT(N)  asm volatile("cp.async.wait_group " #N ";" ::: "memory")

__device__ __forceinline__ void ldsm4(uint32_t& r0, uint32_t& r1, uint32_t& r2,
                                      uint32_t& r3, uint32_t addr) {
    asm volatile("ldmatrix.sync.aligned.m8n8.x4.shared.b16 {%0,%1,%2,%3}, [%4];"
                 : "=r"(r0), "=r"(r1), "=r"(r2), "=r"(r3) : "r"(addr));
}
__device__ __forceinline__ void mma16816(float* d, const uint32_t* a,
                                         uint32_t b0, uint32_t b1) {
    asm volatile(
        "mma.sync.aligned.m16n8k16.row.col.f32.f16.f16.f32 "
        "{%0,%1,%2,%3},{%4,%5,%6,%7},{%8,%9},{%0,%1,%2,%3};"
        : "+f"(d[0]), "+f"(d[1]), "+f"(d[2]), "+f"(d[3])
        : "r"(a[0]), "r"(a[1]), "r"(a[2]), "r"(a[3]), "r"(b0), "r"(b1));
}
__device__ __forceinline__ uint32_t swz(uint32_t off) {
    return off ^ ((off >> 3) & 0x70);
}
__device__ __forceinline__ uint32_t f2ord(float s) {
    uint32_t fb = __float_as_uint(s);
    return (fb & 0x80000000u) ? ~fb : (fb | 0x80000000u);
}

// =================== fused convert kernel (seq + vocab + split-B) ===================
__global__ void convert_kernel(const float* __restrict__ seq,
                               const float* __restrict__ vocab) {
    if (blockIdx.x == 0 && threadIdx.x == 0) g_wlcount = 0;
    if (blockIdx.x < 8192) {
        int idx = blockIdx.x * 256 + threadIdx.x;   // one float4 each
        int row = idx >> 6;
        int c4  = idx & 63;
        float4 x = ((const float4*)seq)[idx];
        __half2 a = __floats2half2_rn(x.x, x.y);
        __half2 b = __floats2half2_rn(x.z, x.w);
        uint2 u;
        u.x = *(uint32_t*)&a; u.y = *(uint32_t*)&b;
        *(uint2*)(g_Ah + (size_t)row * DIMD + c4 * 4) = u;
    } else {
        int row  = (blockIdx.x - 8192) * 8 + (threadIdx.x >> 5);
        int lane = threadIdx.x & 31;
        const float4* v = (const float4*)(vocab + (size_t)row * DIMD);
        __half* rs = g_Bs + (size_t)row * KSPL;
        float s = 0.f;
        #pragma unroll
        for (int c4 = lane; c4 < 64; c4 += 32) {
            float4 x = v[c4];
            s += x.x*x.x + x.y*x.y + x.z*x.z + x.w*x.w;
            float xs[4] = {x.x, x.y, x.z, x.w};
            __half h[4], l[4];
            #pragma unroll
            for (int i = 0; i < 4; i++) {
                h[i] = __float2half_rn(xs[i]);
                l[i] = __float2half_rn(xs[i] - __half2float(h[i]));
            }
            uint2 uh, ul;
            __half2 h0 = {h[0], h[1]}, h1 = {h[2], h[3]};
            __half2 l0 = {l[0], l[1]}, l1 = {l[2], l[3]};
            uh.x = *(uint32_t*)&h0; uh.y = *(uint32_t*)&h1;
            ul.x = *(uint32_t*)&l0; ul.y = *(uint32_t*)&l1;
            *(uint2*)(g_Bh + (size_t)row * DIMD + c4 * 4) = uh;  // coarse B = hi
            *(uint2*)(rs + c4 * 4)       = uh;                   // split: hi
            *(uint2*)(rs + 256 + c4 * 4) = uh;                   //        hi
            *(uint2*)(rs + 512 + c4 * 4) = ul;                   //        lo
        }
        #pragma unroll
        for (int o = 16; o; o >>= 1) s += __shfl_xor_sync(0xffffffffu, s, o);
        if (lane == 0) g_vnorm[row] = 0.5f * s;
    }
}

// ================= persistent-B fp16 coarse GEMM + fused top-2 =================
__global__ __launch_bounds__(256, 2)
void gemm_kernel() {
    extern __shared__ char smem[];
    uint32_t sbase = smem_u32(smem);
    float* s_vn = (float*)(smem + SO_VN);
    float* r1a  = (float*)(smem + SO_R1);
    float* r2a  = (float*)(smem + SO_R2);
    int*   ria  = (int*)  (smem + SO_RI);

    const int tid = threadIdx.x, lane = tid & 31, wid = tid >> 5;
    const int wm = wid & 1, wn = wid >> 1;
    const int bn = blockIdx.x & (NTIL - 1);
    const int mg = blockIdx.x >> 6;
    const int n0 = bn * 128;
    const int mbase = mg * MGRP * 128;

    const char* Bb = (const char*)g_Bh + (size_t)n0 * 512;

    #pragma unroll
    for (int q = 0; q < 16; q++) {
        int c  = q >> 2;
        int p  = tid + 256 * (q & 3);
        int r  = p >> 3, jj = p & 7;
        cpasync16(sbase + SB_OFF(c) + swz(r * 128 + jj * 16),
                  Bb + (size_t)r * 512 + c * 128 + jj * 16);
    }
    CP_COMMIT();

#define LOAD_A(J)                                                              \
    {                                                                          \
        int mt_ = (J) >> 2, c_ = (J) & 3;                                      \
        uint32_t st = sbase + SA_OFF(c_ & 1);                                  \
        const char* Asrc = (const char*)g_Ah                                   \
            + (size_t)(mbase + mt_ * 128) * 512 + c_ * 128;                    \
        _Pragma("unroll")                                                      \
        for (int q = 0; q < 4; q++) {                                          \
            int p = tid + 256 * q; int r = p >> 3, jj = p & 7;                 \
            cpasync16(st + swz(r * 128 + jj * 16),                             \
                      Asrc + (size_t)r * 512 + jj * 16);                       \
        }                                                                      \
        CP_COMMIT();                                                           \
    }

    LOAD_A(0)
    LOAD_A(1)
    if (tid < 128) s_vn[tid] = g_vnorm[n0 + tid];

#define COMPUTE_CHUNK(ST, CB)                                                  \
    {                                                                          \
        uint32_t Abase = sbase + SA_OFF(ST);                                   \
        uint32_t Bbase = sbase + SB_OFF(CB);                                   \
        _Pragma("unroll")                                                      \
        for (int ks = 0; ks < 4; ks++) {                                       \
            uint32_t af[4][4];                                                 \
            _Pragma("unroll")                                                  \
            for (int mt = 0; mt < 4; mt++) {                                   \
                int row = wm * 64 + mt * 16 + (lane & 15);                     \
                uint32_t ad = Abase + swz(row * 128 + ks * 32 + (lane >> 4) * 16); \
                ldsm4(af[mt][0], af[mt][1], af[mt][2], af[mt][3], ad);         \
            }                                                                  \
            uint32_t bf[2][4];                                                 \
            _Pragma("unroll")                                                  \
            for (int np = 0; np < 2; np++) {                                   \
                int row = wn * 32 + np * 16 + (lane & 15);                     \
                uint32_t bd = Bbase + swz(row * 128 + ks * 32 + (lane >> 4) * 16); \
                ldsm4(bf[np][0], bf[np][1], bf[np][2], bf[np][3], bd);         \
            }                                                                  \
            _Pragma("unroll")                                                  \
            for (int mt = 0; mt < 4; mt++) {                                   \
                _Pragma("unroll")                                              \
                for (int nt = 0; nt < 4; nt++) {                               \
                    int np = nt >> 1, sub = nt & 1;                            \
                    mma16816(acc[mt][nt], af[mt], bf[np][sub], bf[np][sub + 2]); \
                }                                                              \
            }                                                                  \
        }                                                                      \
    }

    float acc[4][4][4];

    for (int mt = 0; mt < MGRP; mt++) {
        #pragma unroll
        for (int i = 0; i < 4; i++)
            #pragma unroll
            for (int j = 0; j < 4; j++)
                #pragma unroll
                for (int c = 0; c < 4; c++) acc[i][j][c] = 0.f;

        #pragma unroll
        for (int c = 0; c < 4; c++) {
            if (mt == MGRP - 1 && c == 3) { CP_WAIT(0); } else { CP_WAIT(1); }
            __syncthreads();
            COMPUTE_CHUNK(c & 1, c)
            __syncthreads();
            int nj = mt * 4 + c + 2;
            if (nj < MGRP * 4) LOAD_A(nj)
        }

        const int m0 = mbase + mt * 128;
        float m1[8], m2[8]; int i1[8];
        #pragma unroll
        for (int s = 0; s < 8; s++) { m1[s] = FLT_MAX; m2[s] = FLT_MAX; i1[s] = 0x7FFFFFFF; }

        #pragma unroll
        for (int nt = 0; nt < 4; nt++) {
            int nloc_base = wn * 32 + (nt >> 1) * 16 + (nt & 1) * 8 + (lane & 3) * 2;
            #pragma unroll
            for (int cc = 0; cc < 2; cc++) {
                int nloc = nloc_base + cc;
                float vn = s_vn[nloc];
                int n = n0 + nloc;
                #pragma unroll
                for (int mq = 0; mq < 4; mq++) {
                    #pragma unroll
                    for (int rg = 0; rg < 2; rg++) {
                        int s_ = mq * 2 + rg;
                        float sc = vn - acc[mq][nt][rg * 2 + cc];
                        if (sc < m1[s_]) { m2[s_] = m1[s_]; m1[s_] = sc; i1[s_] = n; }
                        else if (sc < m2[s_]) m2[s_] = sc;
                    }
                }
            }
        }
        #pragma unroll
        for (int s = 0; s < 8; s++) {
            #pragma unroll
            for (int off = 1; off <= 2; off <<= 1) {
                float om1 = __shfl_xor_sync(0xffffffffu, m1[s], off);
                float om2 = __shfl_xor_sync(0xffffffffu, m2[s], off);
                int   oi  = __shfl_xor_sync(0xffffffffu, i1[s], off);
                if (om1 < m1[s] || (om1 == m1[s] && oi < i1[s])) {
                    m2[s] = fminf(m1[s], om2); m1[s] = om1; i1[s] = oi;
                } else {
                    m2[s] = fminf(m2[s], om1);
                }
            }
        }
        if ((lane & 3) == 0) {
            #pragma unroll
            for (int mq = 0; mq < 4; mq++)
                #pragma unroll
                for (int rg = 0; rg < 2; rg++) {
                    int s_ = mq * 2 + rg;
                    int row = wm * 64 + mq * 16 + rg * 8 + (lane >> 2);
                    r1a[row * 4 + wn] = m1[s_];
                    r2a[row * 4 + wn] = m2[s_];
                    ria[row * 4 + wn] = i1[s_];
                }
        }
        __syncthreads();
        if (tid < 128) {
            float M1 = FLT_MAX, M2 = FLT_MAX; int I1 = 0x7FFFFFFF;
            #pragma unroll
            for (int w = 0; w < 4; w++) {
                float a1 = r1a[tid * 4 + w], a2 = r2a[tid * 4 + w];
                int   ai = ria[tid * 4 + w];
                if (a1 < M1 || (a1 == M1 && ai < I1)) {
                    M2 = fminf(M1, a2); M1 = a1; I1 = ai;
                } else {
                    M2 = fminf(M2, a1);
                }
            }
            int token = m0 + tid;
            g_s1[(size_t)bn * NTOK + token] = M1;
            g_s2[(size_t)bn * NTOK + token] = M2;
            g_i1[(size_t)bn * NTOK + token] = I1;
        }
    }
#undef COMPUTE_CHUNK
#undef LOAD_A
}

// ============================ reduce + flag ============================
__global__ void reduce_kernel() {
    int t = blockIdx.x * blockDim.x + threadIdx.x;
    float m1 = FLT_MAX, m2 = FLT_MAX; int i1 = 0x7FFFFFFF;
    #pragma unroll 4
    for (int nt = 0; nt < NTIL; nt++) {
        float s1 = g_s1[(size_t)nt * NTOK + t];
        float s2 = g_s2[(size_t)nt * NTOK + t];
        int   ii = g_i1[(size_t)nt * NTOK + t];
        if (s1 < m1 || (s1 == m1 && ii < i1)) {
            m2 = fminf(m1, s2); m1 = s1; i1 = ii;
        } else {
            m2 = fminf(m2, s1);
        }
    }
    if (m2 - m1 < TAU) {
        g_key[t] = 0xFFFFFFFFFFFFFFFFull;       // sentinel: exact pass decides
        int slot = atomicAdd(&g_wlcount, 1);
        g_wl[slot] = t;
    } else {
        g_key[t] = ((unsigned long long)f2ord(m1) << 32) | (uint32_t)i1;
    }
}

// ======= afill: pack flagged tokens into compact split-A' (padded to 128) =======
__global__ void afill_kernel(const float* __restrict__ seq) {
    int nf = g_wlcount;
    if (nf == 0) return;
    int nfp = (nf + 127) & ~127;
    int total = nfp * 64;                       // 64 float4 per row
    for (int idx = blockIdx.x * blockDim.x + threadIdx.x; idx < total;
         idx += gridDim.x * blockDim.x) {
        int w  = idx >> 6;
        int c4 = idx & 63;
        int t  = g_wl[w < nf ? w : (nf - 1)];
        float4 x = ((const float4*)seq)[(size_t)t * 64 + c4];
        float xs[4] = {x.x, x.y, x.z, x.w};
        __half h[4], l[4];
        #pragma unroll
        for (int i = 0; i < 4; i++) {
            h[i] = __float2half_rn(xs[i]);
            l[i] = __float2half_rn(xs[i] - __half2float(h[i]));
        }
        uint2 uh, ul;
        __half2 h0 = {h[0], h[1]}, h1 = {h[2], h[3]};
        __half2 l0 = {l[0], l[1]}, l1 = {l[2], l[3]};
        uh.x = *(uint32_t*)&h0; uh.y = *(uint32_t*)&h1;
        ul.x = *(uint32_t*)&l0; ul.y = *(uint32_t*)&l1;
        __half* r = g_As + (size_t)w * KSPL;
        *(uint2*)(r + c4 * 4)       = uh;       // hi
        *(uint2*)(r + 256 + c4 * 4) = ul;       // lo
        *(uint2*)(r + 512 + c4 * 4) = uh;       // hi
    }
}

// ===== exact cleanup: split-fp16 GEMM (K=768) over flagged tokens, top-1 =====
__global__ __launch_bounds__(256, 2)
void cleanup_gemm() {
    int nf = g_wlcount;
    if (nf == 0) return;
    const int mg = blockIdx.x >> 6;
    if (mg * 128 >= nf) return;

    extern __shared__ char smem[];
    uint32_t sbase = smem_u32(smem);
    float* s_vn = (float*)(smem + CU_VN);
    float* r1a  = (float*)(smem + CU_R1);
    int*   ria  = (int*)  (smem + CU_RI);
    int*   tk   = (int*)  (smem + CU_TK);

    const int tid = threadIdx.x, lane = tid & 31, wid = tid >> 5;
    const int wm = wid & 1, wn = wid >> 1;
    const int bn = blockIdx.x & 63;
    const int n0 = bn * 128;
    const int m0 = mg * 128;

    const char* Ab = (const char*)g_As + (size_t)m0 * (KSPL * 2);
    const char* Bb = (const char*)g_Bs + (size_t)n0 * (KSPL * 2);

    // chunk j (K=64 slice, j=0..11) -> stage (j&1); A at +0, B at +16KB
#define CU_LOAD(J)                                                             \
    {                                                                          \
        uint32_t st = sbase + CU_ST((J) & 1);                                  \
        _Pragma("unroll")                                                      \
        for (int q = 0; q < 4; q++) {                                          \
            int p = tid + 256 * q; int r = p >> 3, jj = p & 7;                 \
            cpasync16(st + swz(r * 128 + jj * 16),                             \
                      Ab + (size_t)r * (KSPL * 2) + (J) * 128 + jj * 16);      \
        }                                                                      \
        _Pragma("unroll")                                                      \
        for (int q = 0; q < 4; q++) {                                          \
            int p = tid + 256 * q; int r = p >> 3, jj = p & 7;                 \
            cpasync16(st + 16384 + swz(r * 128 + jj * 16),                     \
                      Bb + (size_t)r * (KSPL * 2) + (J) * 128 + jj * 16);      \
        }                                                                      \
        CP_COMMIT();                                                           \
    }

    CU_LOAD(0)
    CU_LOAD(1)
    if (tid < 128) {
        s_vn[tid] = g_vnorm[n0 + tid];
        int w = m0 + tid;
        tk[tid] = g_wl[w < nf ? w : (nf - 1)];
    }

    float acc[4][4][4];
    #pragma unroll
    for (int i = 0; i < 4; i++)
        #pragma unroll
        for (int j = 0; j < 4; j++)
            #pragma unroll
            for (int c = 0; c < 4; c++) acc[i][j][c] = 0.f;

#define CU_COMPUTE(ST)                                                         \
    {                                                                          \
        uint32_t Abase = sbase + CU_ST(ST);                                    \
        uint32_t Bbase = Abase + 16384;                                        \
        _Pragma("unroll")                                                      \
        for (int ks = 0; ks < 4; ks++) {                                       \
            uint32_t af[4][4];                                                 \
            _Pragma("unroll")                                                  \
            for (int mt = 0; mt < 4; mt++) {                                   \
                int row = wm * 64 + mt * 16 + (lane & 15);                     \
                uint32_t ad = Abase + swz(row * 128 + ks * 32 + (lane >> 4) * 16); \
                ldsm4(af[mt][0], af[mt][1], af[mt][2], af[mt][3], ad);         \
            }                                                                  \
            uint32_t bf[2][4];                                                 \
            _Pragma("unroll")                                                  \
            for (int np = 0; np < 2; np++) {                                   \
                int row = wn * 32 + np * 16 + (lane & 15);                     \
                uint32_t bd = Bbase + swz(row * 128 + ks * 32 + (lane >> 4) * 16); \
                ldsm4(bf[np][0], bf[np][1], bf[np][2], bf[np][3], bd);         \
            }                                                                  \
            _Pragma("unroll")                                                  \
            for (int mt = 0; mt < 4; mt++) {                                   \
                _Pragma("unroll")                                              \
                for (int nt = 0; nt < 4; nt++) {                               \
                    int np = nt >> 1, sub = nt & 1;                            \
                    mma16816(acc[mt][nt], af[mt], bf[np][sub], bf[np][sub + 2]); \
                }                                                              \
            }                                                                  \
        }                                                                      \
    }

    #pragma unroll
    for (int c = 0; c < 12; c++) {
        if (c == 11) { CP_WAIT(0); } else { CP_WAIT(1); }
        __syncthreads();
        CU_COMPUTE(c & 1)
        __syncthreads();
        if (c + 2 < 12) CU_LOAD(c + 2)
    }
#undef CU_COMPUTE
#undef CU_LOAD

    // ---- top-1 epilogue ----
    float m1[8]; int i1[8];
    #pragma unroll
    for (int s = 0; s < 8; s++) { m1[s] = FLT_MAX; i1[s] = 0x7FFFFFFF; }

    #pragma unroll
    for (int nt = 0; nt < 4; nt++) {
        int nloc_base = wn * 32 + (nt >> 1) * 16 + (nt & 1) * 8 + (lane & 3) * 2;
        #pragma unroll
        for (int cc = 0; cc < 2; cc++) {
            int nloc = nloc_base + cc;
            float vn = s_vn[nloc];
            int n = n0 + nloc;
            #pragma unroll
            for (int mq = 0; mq < 4; mq++) {
                #pragma unroll
                for (int rg = 0; rg < 2; rg++) {
                    int s_ = mq * 2 + rg;
                    float sc = vn - acc[mq][nt][rg * 2 + cc];
                    if (sc < m1[s_]) { m1[s_] = sc; i1[s_] = n; }
                }
            }
        }
    }
    #pragma unroll
    for (int s = 0; s < 8; s++) {
        #pragma unroll
        for (int off = 1; off <= 2; off <<= 1) {
            float om1 = __shfl_xor_sync(0xffffffffu, m1[s], off);
            int   oi  = __shfl_xor_sync(0xffffffffu, i1[s], off);
            if (om1 < m1[s] || (om1 == m1[s] && oi < i1[s])) {
                m1[s] = om1; i1[s] = oi;
            }
        }
    }
    if ((lane & 3) == 0) {
        #pragma unroll
        for (int mq = 0; mq < 4; mq++)
            #pragma unroll
            for (int rg = 0; rg < 2; rg++) {
                int s_ = mq * 2 + rg;
                int row = wm * 64 + mq * 16 + rg * 8 + (lane >> 2);
                r1a[row * 4 + wn] = m1[s_];
                ria[row * 4 + wn] = i1[s_];
            }
    }
    __syncthreads();
    if (tid < 128 && m0 + tid < nf) {
        float M1 = FLT_MAX; int I1 = 0x7FFFFFFF;
        #pragma unroll
        for (int w = 0; w < 4; w++) {
            float a1 = r1a[tid * 4 + w];
            int   ai = ria[tid * 4 + w];
            if (a1 < M1 || (a1 == M1 && ai < I1)) { M1 = a1; I1 = ai; }
        }
        unsigned long long key =
            ((unsigned long long)f2ord(M1) << 32) | (uint32_t)I1;
        atomicMin(&g_key[tk[tid]], key);
    }
}

// ============================ gather (reads packed key) ============================
__global__ void gather_kernel(const float* __restrict__ vocab,
                              float* __restrict__ out, int write_idx) {
    int token = blockIdx.x * 4 + (threadIdx.x >> 6);
    int l     = threadIdx.x & 63;
    int idx   = (int)(unsigned)(g_key[token] & 0xFFFFFFFFull);
    const float4* src = (const float4*)(vocab + (size_t)idx * DIMD);
    float4*       dst = (float4*)(out + (size_t)token * DIMD);
    dst[l] = src[l];
    if (write_idx && l == 0)
        out[(size_t)NTOK * DIMD + token] = (float)idx;
}

// ============================ launch ============================
extern "C" void kernel_launch(void* const* d_in, const int* in_sizes, int n_in,
                              void* d_out, int out_size) {
    const float* seq   = (const float*)d_in[0];
    const float* vocab = (const float*)d_in[1];
    float* out = (float*)d_out;
    int write_idx = (out_size >= NTOK * DIMD + NTOK) ? 1 : 0;

    cudaFuncSetAttribute(gemm_kernel,
                         cudaFuncAttributeMaxDynamicSharedMemorySize, SM_TOTAL);
    cudaFuncSetAttribute(cleanup_gemm,
                         cudaFuncAttributeMaxDynamicSharedMemorySize, CU_SM_TOTAL);

    convert_kernel<<<8192 + 1024, 256>>>(seq, vocab);
    gemm_kernel<<<(NTOK / (MGRP * 128)) * NTIL, 256, SM_TOTAL>>>();
    reduce_kernel<<<NTOK / 128, 128>>>();
    afill_kernel<<<1024, 256>>>(seq);
    cleanup_gemm<<<(NTOK / 128) * 64, 256, CU_SM_TOTAL>>>();
    gather_kernel<<<NTOK / 4, 256>>>(vocab, out, write_idx);
}

// round 11
// speedup vs baseline: 1.8464x; 1.0038x over previous
#include <cuda_runtime.h>
#include <cuda_fp16.h>
#include <cstdint>
#include <float.h>

#define NTOK 32768
#define DIMD 256
#define KVOC 8192
#define NTIL   64           // n-tiles of 128 codewords
#define MGRP   8            // m-tiles per CTA (persistent-B coarse gemm)
#define TAU  0.08f
#define KSPL 768            // split-K: [x_hi|x_lo|x_hi] . [v_hi|v_hi|v_lo]

// ---- device scratch ----
__device__ __half g_Ah[(size_t)NTOK * DIMD];   // 16 MB fp16 tokens (coarse)
__device__ __half g_Bh[(size_t)KVOC * DIMD];   // 4 MB fp16 vocab (coarse)
__device__ __half g_As[(size_t)NTOK * KSPL];   // 50 MB split-A (flagged, compact)
__device__ __half g_Bs[(size_t)KVOC * KSPL];   // 12.6 MB split-B
__device__ float  g_vnorm[KVOC];               // 0.5*||v||^2 fp32
__device__ float  g_s1[(size_t)NTIL * NTOK];
__device__ float  g_s2[(size_t)NTIL * NTOK];
__device__ int    g_i1[(size_t)NTIL * NTOK];
__device__ unsigned long long g_key[NTOK];
__device__ int    g_wl[NTOK];
__device__ int    g_wlcount;

// ---- coarse gemm smem: A stages (2x16KB) | B chunks (4x16KB) | vn ----
#define SA_OFF(st) ((st) * 16384)
#define SB_OFF(c)  (32768 + (c) * 16384)
#define SO_VN  98304
#define SM_TOTAL 98816

// ---- cleanup gemm smem: 2 stages x (A 16KB + B 16KB) | vn | red | tk ----
#define CU_ST(st)  ((st) * 32768)
#define CU_VN  65536
#define CU_R1  66048
#define CU_RI  68096
#define CU_TK  70144
#define CU_SM_TOTAL 70656

// ============================ asm helpers ============================
__device__ __forceinline__ uint32_t smem_u32(const void* p) {
    uint32_t a;
    asm("{ .reg .u64 t; cvta.to.shared.u64 t, %1; cvt.u32.u64 %0, t; }"
        : "=r"(a) : "l"(p));
    return a;
}
__device__ __forceinline__ void cpasync16(uint32_t s, const void* g) {
    asm volatile("cp.async.cg.shared.global [%0], [%1], 16;" :: "r"(s), "l"(g));
}
#define CP_COMMIT() asm volatile("cp.async.commit_group;" ::: "memory")
#define CP_WAIT(N)  asm volatile("cp.async.wait_group " #N ";" ::: "memory")

__device__ __forceinline__ void ldsm4(uint32_t& r0, uint32_t& r1, uint32_t& r2,
                                      uint32_t& r3, uint32_t addr) {
    asm volatile("ldmatrix.sync.aligned.m8n8.x4.shared.b16 {%0,%1,%2,%3}, [%4];"
                 : "=r"(r0), "=r"(r1), "=r"(r2), "=r"(r3) : "r"(addr));
}
__device__ __forceinline__ void mma16816(float* d, const uint32_t* a,
                                         uint32_t b0, uint32_t b1) {
    asm volatile(
        "mma.sync.aligned.m16n8k16.row.col.f32.f16.f16.f32 "
        "{%0,%1,%2,%3},{%4,%5,%6,%7},{%8,%9},{%0,%1,%2,%3};"
        : "+f"(d[0]), "+f"(d[1]), "+f"(d[2]), "+f"(d[3])
        : "r"(a[0]), "r"(a[1]), "r"(a[2]), "r"(a[3]), "r"(b0), "r"(b1));
}
__device__ __forceinline__ uint32_t swz(uint32_t off) {
    return off ^ ((off >> 3) & 0x70);
}
__device__ __forceinline__ uint32_t f2ord(float s) {
    uint32_t fb = __float_as_uint(s);
    return (fb & 0x80000000u) ? ~fb : (fb | 0x80000000u);
}

// =================== fused convert kernel (seq + vocab + split-B) ===================
__global__ void convert_kernel(const float* __restrict__ seq,
                               const float* __restrict__ vocab) {
    if (blockIdx.x == 0 && threadIdx.x == 0) g_wlcount = 0;
    if (blockIdx.x < 8192) {
        int idx = blockIdx.x * 256 + threadIdx.x;   // one float4 each
        int row = idx >> 6;
        int c4  = idx & 63;
        float4 x = ((const float4*)seq)[idx];
        __half2 a = __floats2half2_rn(x.x, x.y);
        __half2 b = __floats2half2_rn(x.z, x.w);
        uint2 u;
        u.x = *(uint32_t*)&a; u.y = *(uint32_t*)&b;
        *(uint2*)(g_Ah + (size_t)row * DIMD + c4 * 4) = u;
    } else {
        int row  = (blockIdx.x - 8192) * 8 + (threadIdx.x >> 5);
        int lane = threadIdx.x & 31;
        const float4* v = (const float4*)(vocab + (size_t)row * DIMD);
        __half* rs = g_Bs + (size_t)row * KSPL;
        float s = 0.f;
        #pragma unroll
        for (int c4 = lane; c4 < 64; c4 += 32) {
            float4 x = v[c4];
            s += x.x*x.x + x.y*x.y + x.z*x.z + x.w*x.w;
            float xs[4] = {x.x, x.y, x.z, x.w};
            __half h[4], l[4];
            #pragma unroll
            for (int i = 0; i < 4; i++) {
                h[i] = __float2half_rn(xs[i]);
                l[i] = __float2half_rn(xs[i] - __half2float(h[i]));
            }
            uint2 uh, ul;
            __half2 h0 = {h[0], h[1]}, h1 = {h[2], h[3]};
            __half2 l0 = {l[0], l[1]}, l1 = {l[2], l[3]};
            uh.x = *(uint32_t*)&h0; uh.y = *(uint32_t*)&h1;
            ul.x = *(uint32_t*)&l0; ul.y = *(uint32_t*)&l1;
            *(uint2*)(g_Bh + (size_t)row * DIMD + c4 * 4) = uh;  // coarse B = hi
            *(uint2*)(rs + c4 * 4)       = uh;                   // split: hi
            *(uint2*)(rs + 256 + c4 * 4) = uh;                   //        hi
            *(uint2*)(rs + 512 + c4 * 4) = ul;                   //        lo
        }
        #pragma unroll
        for (int o = 16; o; o >>= 1) s += __shfl_xor_sync(0xffffffffu, s, o);
        if (lane == 0) g_vnorm[row] = 0.5f * s;
    }
}

// ====== persistent-B fp16 coarse GEMM, row-owning warps, fused top-2 ======
__global__ __launch_bounds__(256, 2)
void gemm_kernel() {
    extern __shared__ char smem[];
    uint32_t sbase = smem_u32(smem);
    float* s_vn = (float*)(smem + SO_VN);

    const int tid = threadIdx.x, lane = tid & 31, wid = tid >> 5;
    const int bn = blockIdx.x & (NTIL - 1);         // n-tile
    const int mg = blockIdx.x >> 6;                 // m-group
    const int n0 = bn * 128;
    const int mbase = mg * MGRP * 128;

    const char* Bb = (const char*)g_Bh + (size_t)n0 * 512;

    // ---- B n-tile (64KB = 4 chunk sub-tiles), one group
    #pragma unroll
    for (int q = 0; q < 16; q++) {
        int c  = q >> 2;
        int p  = tid + 256 * (q & 3);
        int r  = p >> 3, jj = p & 7;
        cpasync16(sbase + SB_OFF(c) + swz(r * 128 + jj * 16),
                  Bb + (size_t)r * 512 + c * 128 + jj * 16);
    }
    CP_COMMIT();

    // A chunk J (J = mt*4 + c) -> stage (J & 1)
#define LOAD_A(J)                                                              \
    {                                                                          \
        uint32_t st = sbase + SA_OFF((J) & 1);                                 \
        const char* Asrc = (const char*)g_Ah                                   \
            + (size_t)(mbase + ((J) >> 2) * 128) * 512 + ((J) & 3) * 128;      \
        _Pragma("unroll")                                                      \
        for (int q = 0; q < 4; q++) {                                          \
            int p = tid + 256 * q; int r = p >> 3, jj = p & 7;                 \
            cpasync16(st + swz(r * 128 + jj * 16),                             \
                      Asrc + (size_t)r * 512 + jj * 16);                       \
        }                                                                      \
        CP_COMMIT();                                                           \
    }

    LOAD_A(0)
    if (tid < 128) s_vn[tid] = g_vnorm[n0 + tid];

    // warp wid owns rows [wid*16, wid*16+16) x all 128 cols
    float acc[16][4];

    for (int mt = 0; mt < MGRP; mt++) {
        #pragma unroll
        for (int g = 0; g < 16; g++)
            #pragma unroll
            for (int c = 0; c < 4; c++) acc[g][c] = 0.f;

        #pragma unroll
        for (int c = 0; c < 4; c++) {
            const int j = mt * 4 + c;
            CP_WAIT(0);
            __syncthreads();            // chunk j ready; stage (j+1)&1 free
            if (j + 1 < MGRP * 4) LOAD_A(j + 1)

            uint32_t Abase = sbase + SA_OFF(j & 1);
            uint32_t Bbase = sbase + SB_OFF(c);
            #pragma unroll
            for (int ks = 0; ks < 4; ks++) {
                uint32_t af[4];
                {
                    int row = wid * 16 + (lane & 15);
                    uint32_t ad = Abase + swz(row * 128 + ks * 32 + (lane >> 4) * 16);
                    ldsm4(af[0], af[1], af[2], af[3], ad);
                }
                uint32_t bf[8][4];
                #pragma unroll
                for (int nb = 0; nb < 8; nb++) {
                    int row = nb * 16 + (lane & 15);
                    uint32_t bd = Bbase + swz(row * 128 + ks * 32 + (lane >> 4) * 16);
                    ldsm4(bf[nb][0], bf[nb][1], bf[nb][2], bf[nb][3], bd);
                }
                #pragma unroll
                for (int nb = 0; nb < 8; nb++) {
                    mma16816(acc[nb * 2],     af, bf[nb][0], bf[nb][2]);
                    mma16816(acc[nb * 2 + 1], af, bf[nb][1], bf[nb][3]);
                }
            }
        }

        // ---- warp-local top-2 epilogue (no smem, no barriers) ----
        const int m0 = mbase + mt * 128;
        float m1[2] = {FLT_MAX, FLT_MAX}, m2[2] = {FLT_MAX, FLT_MAX};
        int   i1[2] = {0x7FFFFFFF, 0x7FFFFFFF};

        #pragma unroll
        for (int g = 0; g < 16; g++) {
            int nb_ = g * 8 + (lane & 3) * 2;
            float vn0 = s_vn[nb_], vn1 = s_vn[nb_ + 1];
            #pragma unroll
            for (int c = 0; c < 4; c++) {
                int sl = c >> 1;
                float sc = ((c & 1) ? vn1 : vn0) - acc[g][c];
                int n = n0 + nb_ + (c & 1);
                if (sc < m1[sl]) { m2[sl] = m1[sl]; m1[sl] = sc; i1[sl] = n; }
                else if (sc < m2[sl]) m2[sl] = sc;
            }
        }
        #pragma unroll
        for (int off = 1; off <= 2; off <<= 1) {
            #pragma unroll
            for (int sl = 0; sl < 2; sl++) {
                float om1 = __shfl_xor_sync(0xffffffffu, m1[sl], off);
                float om2 = __shfl_xor_sync(0xffffffffu, m2[sl], off);
                int   oi  = __shfl_xor_sync(0xffffffffu, i1[sl], off);
                if (om1 < m1[sl] || (om1 == m1[sl] && oi < i1[sl])) {
                    m2[sl] = fminf(m1[sl], om2); m1[sl] = om1; i1[sl] = oi;
                } else {
                    m2[sl] = fminf(m2[sl], om1);
                }
            }
        }
        if ((lane & 3) == 0) {
            int r0 = wid * 16 + (lane >> 2);
            #pragma unroll
            for (int sl = 0; sl < 2; sl++) {
                int token = m0 + r0 + sl * 8;
                g_s1[(size_t)bn * NTOK + token] = m1[sl];
                g_s2[(size_t)bn * NTOK + token] = m2[sl];
                g_i1[(size_t)bn * NTOK + token] = i1[sl];
            }
        }
    }
#undef LOAD_A
}

// ============================ reduce + flag ============================
__global__ void reduce_kernel() {
    int t = blockIdx.x * blockDim.x + threadIdx.x;
    float m1 = FLT_MAX, m2 = FLT_MAX; int i1 = 0x7FFFFFFF;
    #pragma unroll 4
    for (int nt = 0; nt < NTIL; nt++) {
        float s1 = g_s1[(size_t)nt * NTOK + t];
        float s2 = g_s2[(size_t)nt * NTOK + t];
        int   ii = g_i1[(size_t)nt * NTOK + t];
        if (s1 < m1 || (s1 == m1 && ii < i1)) {
            m2 = fminf(m1, s2); m1 = s1; i1 = ii;
        } else {
            m2 = fminf(m2, s1);
        }
    }
    if (m2 - m1 < TAU) {
        g_key[t] = 0xFFFFFFFFFFFFFFFFull;       // sentinel: exact pass decides
        int slot = atomicAdd(&g_wlcount, 1);
        g_wl[slot] = t;
    } else {
        g_key[t] = ((unsigned long long)f2ord(m1) << 32) | (uint32_t)i1;
    }
}

// ======= afill: pack flagged tokens into compact split-A' (padded to 128) =======
__global__ void afill_kernel(const float* __restrict__ seq) {
    int nf = g_wlcount;
    if (nf == 0) return;
    int nfp = (nf + 127) & ~127;
    int total = nfp * 64;                       // 64 float4 per row
    for (int idx = blockIdx.x * blockDim.x + threadIdx.x; idx < total;
         idx += gridDim.x * blockDim.x) {
        int w  = idx >> 6;
        int c4 = idx & 63;
        int t  = g_wl[w < nf ? w : (nf - 1)];
        float4 x = ((const float4*)seq)[(size_t)t * 64 + c4];
        float xs[4] = {x.x, x.y, x.z, x.w};
        __half h[4], l[4];
        #pragma unroll
        for (int i = 0; i < 4; i++) {
            h[i] = __float2half_rn(xs[i]);
            l[i] = __float2half_rn(xs[i] - __half2float(h[i]));
        }
        uint2 uh, ul;
        __half2 h0 = {h[0], h[1]}, h1 = {h[2], h[3]};
        __half2 l0 = {l[0], l[1]}, l1 = {l[2], l[3]};
        uh.x = *(uint32_t*)&h0; uh.y = *(uint32_t*)&h1;
        ul.x = *(uint32_t*)&l0; ul.y = *(uint32_t*)&l1;
        __half* r = g_As + (size_t)w * KSPL;
        *(uint2*)(r + c4 * 4)       = uh;       // hi
        *(uint2*)(r + 256 + c4 * 4) = ul;       // lo
        *(uint2*)(r + 512 + c4 * 4) = uh;       // hi
    }
}

// ===== exact cleanup: split-fp16 GEMM (K=768) over flagged tokens, top-1 =====
__global__ __launch_bounds__(256, 2)
void cleanup_gemm() {
    int nf = g_wlcount;
    if (nf == 0) return;
    const int mg = blockIdx.x >> 6;
    if (mg * 128 >= nf) return;

    extern __shared__ char smem[];
    uint32_t sbase = smem_u32(smem);
    float* s_vn = (float*)(smem + CU_VN);
    float* r1a  = (float*)(smem + CU_R1);
    int*   ria  = (int*)  (smem + CU_RI);
    int*   tk   = (int*)  (smem + CU_TK);

    const int tid = threadIdx.x, lane = tid & 31, wid = tid >> 5;
    const int wm = wid & 1, wn = wid >> 1;
    const int bn = blockIdx.x & 63;
    const int n0 = bn * 128;
    const int m0 = mg * 128;

    const char* Ab = (const char*)g_As + (size_t)m0 * (KSPL * 2);
    const char* Bb = (const char*)g_Bs + (size_t)n0 * (KSPL * 2);

#define CU_LOAD(J)                                                             \
    {                                                                          \
        uint32_t st = sbase + CU_ST((J) & 1);                                  \
        _Pragma("unroll")                                                      \
        for (int q = 0; q < 4; q++) {                                          \
            int p = tid + 256 * q; int r = p >> 3, jj = p & 7;                 \
            cpasync16(st + swz(r * 128 + jj * 16),                             \
                      Ab + (size_t)r * (KSPL * 2) + (J) * 128 + jj * 16);      \
        }                                                                      \
        _Pragma("unroll")                                                      \
        for (int q = 0; q < 4; q++) {                                          \
            int p = tid + 256 * q; int r = p >> 3, jj = p & 7;                 \
            cpasync16(st + 16384 + swz(r * 128 + jj * 16),                     \
                      Bb + (size_t)r * (KSPL * 2) + (J) * 128 + jj * 16);      \
        }                                                                      \
        CP_COMMIT();                                                           \
    }

    CU_LOAD(0)
    CU_LOAD(1)
    if (tid < 128) {
        s_vn[tid] = g_vnorm[n0 + tid];
        int w = m0 + tid;
        tk[tid] = g_wl[w < nf ? w : (nf - 1)];
    }

    float acc[4][4][4];
    #pragma unroll
    for (int i = 0; i < 4; i++)
        #pragma unroll
        for (int j = 0; j < 4; j++)
            #pragma unroll
            for (int c = 0; c < 4; c++) acc[i][j][c] = 0.f;

#define CU_COMPUTE(ST)                                                         \
    {                                                                          \
        uint32_t Abase = sbase + CU_ST(ST);                                    \
        uint32_t Bbase = Abase + 16384;                                        \
        _Pragma("unroll")                                                      \
        for (int ks = 0; ks < 4; ks++) {                                       \
            uint32_t af[4][4];                                                 \
            _Pragma("unroll")                                                  \
            for (int mt = 0; mt < 4; mt++) {                                   \
                int row = wm * 64 + mt * 16 + (lane & 15);                     \
                uint32_t ad = Abase + swz(row * 128 + ks * 32 + (lane >> 4) * 16); \
                ldsm4(af[mt][0], af[mt][1], af[mt][2], af[mt][3], ad);         \
            }                                                                  \
            uint32_t bf[2][4];                                                 \
            _Pragma("unroll")                                                  \
            for (int np = 0; np < 2; np++) {                                   \
                int row = wn * 32 + np * 16 + (lane & 15);                     \
                uint32_t bd = Bbase + swz(row * 128 + ks * 32 + (lane >> 4) * 16); \
                ldsm4(bf[np][0], bf[np][1], bf[np][2], bf[np][3], bd);         \
            }                                                                  \
            _Pragma("unroll")                                                  \
            for (int mt = 0; mt < 4; mt++) {                                   \
                _Pragma("unroll")                                              \
                for (int nt = 0; nt < 4; nt++) {                               \
                    int np = nt >> 1, sub = nt & 1;                            \
                    mma16816(acc[mt][nt], af[mt], bf[np][sub], bf[np][sub + 2]); \
                }                                                              \
            }                                                                  \
        }                                                                      \
    }

    #pragma unroll
    for (int c = 0; c < 12; c++) {
        if (c == 11) { CP_WAIT(0); } else { CP_WAIT(1); }
        __syncthreads();
        CU_COMPUTE(c & 1)
        __syncthreads();
        if (c + 2 < 12) CU_LOAD(c + 2)
    }
#undef CU_COMPUTE
#undef CU_LOAD

    // ---- top-1 epilogue ----
    float m1[8]; int i1[8];
    #pragma unroll
    for (int s = 0; s < 8; s++) { m1[s] = FLT_MAX; i1[s] = 0x7FFFFFFF; }

    #pragma unroll
    for (int nt = 0; nt < 4; nt++) {
        int nloc_base = wn * 32 + (nt >> 1) * 16 + (nt & 1) * 8 + (lane & 3) * 2;
        #pragma unroll
        for (int cc = 0; cc < 2; cc++) {
            int nloc = nloc_base + cc;
            float vn = s_vn[nloc];
            int n = n0 + nloc;
            #pragma unroll
            for (int mq = 0; mq < 4; mq++) {
                #pragma unroll
                for (int rg = 0; rg < 2; rg++) {
                    int s_ = mq * 2 + rg;
                    float sc = vn - acc[mq][nt][rg * 2 + cc];
                    if (sc < m1[s_]) { m1[s_] = sc; i1[s_] = n; }
                }
            }
        }
    }
    #pragma unroll
    for (int s = 0; s < 8; s++) {
        #pragma unroll
        for (int off = 1; off <= 2; off <<= 1) {
            float om1 = __shfl_xor_sync(0xffffffffu, m1[s], off);
            int   oi  = __shfl_xor_sync(0xffffffffu, i1[s], off);
            if (om1 < m1[s] || (om1 == m1[s] && oi < i1[s])) {
                m1[s] = om1; i1[s] = oi;
            }
        }
    }
    if ((lane & 3) == 0) {
        #pragma unroll
        for (int mq = 0; mq < 4; mq++)
            #pragma unroll
            for (int rg = 0; rg < 2; rg++) {
                int s_ = mq * 2 + rg;
                int row = wm * 64 + mq * 16 + rg * 8 + (lane >> 2);
                r1a[row * 4 + wn] = m1[s_];
                ria[row * 4 + wn] = i1[s_];
            }
    }
    __syncthreads();
    if (tid < 128 && m0 + tid < nf) {
        float M1 = FLT_MAX; int I1 = 0x7FFFFFFF;
        #pragma unroll
        for (int w = 0; w < 4; w++) {
            float a1 = r1a[tid * 4 + w];
            int   ai = ria[tid * 4 + w];
            if (a1 < M1 || (a1 == M1 && ai < I1)) { M1 = a1; I1 = ai; }
        }
        unsigned long long key =
            ((unsigned long long)f2ord(M1) << 32) | (uint32_t)I1;
        atomicMin(&g_key[tk[tid]], key);
    }
}

// ============================ gather (reads packed key) ============================
__global__ void gather_kernel(const float* __restrict__ vocab,
                              float* __restrict__ out, int write_idx) {
    int token = blockIdx.x * 4 + (threadIdx.x >> 6);
    int l     = threadIdx.x & 63;
    int idx   = (int)(unsigned)(g_key[token] & 0xFFFFFFFFull);
    const float4* src = (const float4*)(vocab + (size_t)idx * DIMD);
    float4*       dst = (float4*)(out + (size_t)token * DIMD);
    dst[l] = src[l];
    if (write_idx && l == 0)
        out[(size_t)NTOK * DIMD + token] = (float)idx;
}

// ============================ launch ============================
extern "C" void kernel_launch(void* const* d_in, const int* in_sizes, int n_in,
                              void* d_out, int out_size) {
    const float* seq   = (const float*)d_in[0];
    const float* vocab = (const float*)d_in[1];
    float* out = (float*)d_out;
    int write_idx = (out_size >= NTOK * DIMD + NTOK) ? 1 : 0;

    cudaFuncSetAttribute(gemm_kernel,
                         cudaFuncAttributeMaxDynamicSharedMemorySize, SM_TOTAL);
    cudaFuncSetAttribute(cleanup_gemm,
                         cudaFuncAttributeMaxDynamicSharedMemorySize, CU_SM_TOTAL);

    convert_kernel<<<8192 + 1024, 256>>>(seq, vocab);
    gemm_kernel<<<(NTOK / (MGRP * 128)) * NTIL, 256, SM_TOTAL>>>();
    reduce_kernel<<<NTOK / 128, 128>>>();
    afill_kernel<<<1024, 256>>>(seq);
    cleanup_gemm<<<(NTOK / 128) * 64, 256, CU_SM_TOTAL>>>();
    gather_kernel<<<NTOK / 4, 256>>>(vocab, out, write_idx);
}

// round 12
// speedup vs baseline: 1.8999x; 1.0290x over previous
#include <cuda_runtime.h>
#include <cuda_fp16.h>
#include <cstdint>
#include <float.h>

#define NTOK 32768
#define DIMD 256
#define KVOC 8192
#define NTIL   64           // n-tiles of 128 codewords
#define MGRP   8            // m-tiles per CTA (persistent-B coarse gemm)
#define TAU  0.04f
#define KSPL 768            // split-K: [x_hi|x_lo|x_hi] . [v_hi|v_hi|v_lo]

// ---- device scratch ----
__device__ __half g_Ah[(size_t)NTOK * DIMD];   // 16 MB fp16 tokens (coarse)
__device__ __half g_Bh[(size_t)KVOC * DIMD];   // 4 MB fp16 vocab (coarse)
__device__ __half g_As[(size_t)NTOK * KSPL];   // 50 MB split-A (flagged, compact)
__device__ __half g_Bs[(size_t)KVOC * KSPL];   // 12.6 MB split-B
__device__ float  g_vnorm[KVOC];               // 0.5*||v||^2 fp32
__device__ float  g_s1[(size_t)NTIL * NTOK];
__device__ float  g_s2[(size_t)NTIL * NTOK];
__device__ int    g_i1[(size_t)NTIL * NTOK];
__device__ unsigned long long g_key[NTOK];
__device__ int    g_wl[NTOK];
__device__ int    g_wlcount;

// ---- coarse gemm smem: A stages (2x16KB) | B chunks (4x16KB) | vn ----
#define SA_OFF(st) ((st) * 16384)
#define SB_OFF(c)  (32768 + (c) * 16384)
#define SO_VN  98304
#define SM_TOTAL 98816

// ---- cleanup gemm smem: 2 stages x (A 16KB + B 16KB) | vn | red | tk ----
#define CU_ST(st)  ((st) * 32768)
#define CU_VN  65536
#define CU_R1  66048
#define CU_RI  68096
#define CU_TK  70144
#define CU_SM_TOTAL 70656

// ============================ asm helpers ============================
__device__ __forceinline__ uint32_t smem_u32(const void* p) {
    uint32_t a;
    asm("{ .reg .u64 t; cvta.to.shared.u64 t, %1; cvt.u32.u64 %0, t; }"
        : "=r"(a) : "l"(p));
    return a;
}
__device__ __forceinline__ void cpasync16(uint32_t s, const void* g) {
    asm volatile("cp.async.cg.shared.global [%0], [%1], 16;" :: "r"(s), "l"(g));
}
#define CP_COMMIT() asm volatile("cp.async.commit_group;" ::: "memory")
#define CP_WAIT(N)  asm volatile("cp.async.wait_group " #N ";" ::: "memory")

__device__ __forceinline__ void ldsm4(uint32_t& r0, uint32_t& r1, uint32_t& r2,
                                      uint32_t& r3, uint32_t addr) {
    asm volatile("ldmatrix.sync.aligned.m8n8.x4.shared.b16 {%0,%1,%2,%3}, [%4];"
                 : "=r"(r0), "=r"(r1), "=r"(r2), "=r"(r3) : "r"(addr));
}
__device__ __forceinline__ void mma16816(float* d, const uint32_t* a,
                                         uint32_t b0, uint32_t b1) {
    asm volatile(
        "mma.sync.aligned.m16n8k16.row.col.f32.f16.f16.f32 "
        "{%0,%1,%2,%3},{%4,%5,%6,%7},{%8,%9},{%0,%1,%2,%3};"
        : "+f"(d[0]), "+f"(d[1]), "+f"(d[2]), "+f"(d[3])
        : "r"(a[0]), "r"(a[1]), "r"(a[2]), "r"(a[3]), "r"(b0), "r"(b1));
}
__device__ __forceinline__ uint32_t swz(uint32_t off) {
    return off ^ ((off >> 3) & 0x70);
}
__device__ __forceinline__ uint32_t f2ord(float s) {
    uint32_t fb = __float_as_uint(s);
    return (fb & 0x80000000u) ? ~fb : (fb | 0x80000000u);
}

// =================== fused convert kernel (seq + vocab + split-B) ===================
__global__ void convert_kernel(const float* __restrict__ seq,
                               const float* __restrict__ vocab) {
    if (blockIdx.x == 0 && threadIdx.x == 0) g_wlcount = 0;
    if (blockIdx.x < 8192) {
        int idx = blockIdx.x * 256 + threadIdx.x;   // one float4 each
        int row = idx >> 6;
        int c4  = idx & 63;
        float4 x = ((const float4*)seq)[idx];
        __half2 a = __floats2half2_rn(x.x, x.y);
        __half2 b = __floats2half2_rn(x.z, x.w);
        uint2 u;
        u.x = *(uint32_t*)&a; u.y = *(uint32_t*)&b;
        *(uint2*)(g_Ah + (size_t)row * DIMD + c4 * 4) = u;
    } else {
        int row  = (blockIdx.x - 8192) * 8 + (threadIdx.x >> 5);
        int lane = threadIdx.x & 31;
        const float4* v = (const float4*)(vocab + (size_t)row * DIMD);
        __half* rs = g_Bs + (size_t)row * KSPL;
        float s = 0.f;
        #pragma unroll
        for (int c4 = lane; c4 < 64; c4 += 32) {
            float4 x = v[c4];
            s += x.x*x.x + x.y*x.y + x.z*x.z + x.w*x.w;
            float xs[4] = {x.x, x.y, x.z, x.w};
            __half h[4], l[4];
            #pragma unroll
            for (int i = 0; i < 4; i++) {
                h[i] = __float2half_rn(xs[i]);
                l[i] = __float2half_rn(xs[i] - __half2float(h[i]));
            }
            uint2 uh, ul;
            __half2 h0 = {h[0], h[1]}, h1 = {h[2], h[3]};
            __half2 l0 = {l[0], l[1]}, l1 = {l[2], l[3]};
            uh.x = *(uint32_t*)&h0; uh.y = *(uint32_t*)&h1;
            ul.x = *(uint32_t*)&l0; ul.y = *(uint32_t*)&l1;
            *(uint2*)(g_Bh + (size_t)row * DIMD + c4 * 4) = uh;  // coarse B = hi
            *(uint2*)(rs + c4 * 4)       = uh;                   // split: hi
            *(uint2*)(rs + 256 + c4 * 4) = uh;                   //        hi
            *(uint2*)(rs + 512 + c4 * 4) = ul;                   //        lo
        }
        #pragma unroll
        for (int o = 16; o; o >>= 1) s += __shfl_xor_sync(0xffffffffu, s, o);
        if (lane == 0) g_vnorm[row] = 0.5f * s;
    }
}

// ====== persistent-B fp16 coarse GEMM, row-owning warps, fused top-2 ======
__global__ __launch_bounds__(256, 2)
void gemm_kernel() {
    extern __shared__ char smem[];
    uint32_t sbase = smem_u32(smem);
    float* s_vn = (float*)(smem + SO_VN);

    const int tid = threadIdx.x, lane = tid & 31, wid = tid >> 5;
    const int bn = blockIdx.x & (NTIL - 1);         // n-tile
    const int mg = blockIdx.x >> 6;                 // m-group
    const int n0 = bn * 128;
    const int mbase = mg * MGRP * 128;

    const char* Bb = (const char*)g_Bh + (size_t)n0 * 512;

    // ---- B n-tile (64KB = 4 chunk sub-tiles), one group
    #pragma unroll
    for (int q = 0; q < 16; q++) {
        int c  = q >> 2;
        int p  = tid + 256 * (q & 3);
        int r  = p >> 3, jj = p & 7;
        cpasync16(sbase + SB_OFF(c) + swz(r * 128 + jj * 16),
                  Bb + (size_t)r * 512 + c * 128 + jj * 16);
    }
    CP_COMMIT();

    // A chunk J (J = mt*4 + c) -> stage (J & 1)
#define LOAD_A(J)                                                              \
    {                                                                          \
        uint32_t st = sbase + SA_OFF((J) & 1);                                 \
        const char* Asrc = (const char*)g_Ah                                   \
            + (size_t)(mbase + ((J) >> 2) * 128) * 512 + ((J) & 3) * 128;      \
        _Pragma("unroll")                                                      \
        for (int q = 0; q < 4; q++) {                                          \
            int p = tid + 256 * q; int r = p >> 3, jj = p & 7;                 \
            cpasync16(st + swz(r * 128 + jj * 16),                             \
                      Asrc + (size_t)r * 512 + jj * 16);                       \
        }                                                                      \
        CP_COMMIT();                                                           \
    }

    LOAD_A(0)
    if (tid < 128) s_vn[tid] = g_vnorm[n0 + tid];

    // warp wid owns rows [wid*16, wid*16+16) x all 128 cols
    float acc[16][4];

    for (int mt = 0; mt < MGRP; mt++) {
        #pragma unroll
        for (int g = 0; g < 16; g++)
            #pragma unroll
            for (int c = 0; c < 4; c++) acc[g][c] = 0.f;

        #pragma unroll
        for (int c = 0; c < 4; c++) {
            const int j = mt * 4 + c;
            CP_WAIT(0);
            __syncthreads();            // chunk j ready; stage (j+1)&1 free
            if (j + 1 < MGRP * 4) LOAD_A(j + 1)

            uint32_t Abase = sbase + SA_OFF(j & 1);
            uint32_t Bbase = sbase + SB_OFF(c);
            #pragma unroll
            for (int ks = 0; ks < 4; ks++) {
                uint32_t af[4];
                {
                    int row = wid * 16 + (lane & 15);
                    uint32_t ad = Abase + swz(row * 128 + ks * 32 + (lane >> 4) * 16);
                    ldsm4(af[0], af[1], af[2], af[3], ad);
                }
                uint32_t bf[8][4];
                #pragma unroll
                for (int nb = 0; nb < 8; nb++) {
                    int row = nb * 16 + (lane & 15);
                    uint32_t bd = Bbase + swz(row * 128 + ks * 32 + (lane >> 4) * 16);
                    ldsm4(bf[nb][0], bf[nb][1], bf[nb][2], bf[nb][3], bd);
                }
                #pragma unroll
                for (int nb = 0; nb < 8; nb++) {
                    mma16816(acc[nb * 2],     af, bf[nb][0], bf[nb][2]);
                    mma16816(acc[nb * 2 + 1], af, bf[nb][1], bf[nb][3]);
                }
            }
        }

        // ---- warp-local top-2 epilogue (no smem, no barriers) ----
        const int m0 = mbase + mt * 128;
        float m1[2] = {FLT_MAX, FLT_MAX}, m2[2] = {FLT_MAX, FLT_MAX};
        int   i1[2] = {0x7FFFFFFF, 0x7FFFFFFF};

        #pragma unroll
        for (int g = 0; g < 16; g++) {
            int nb_ = g * 8 + (lane & 3) * 2;
            float vn0 = s_vn[nb_], vn1 = s_vn[nb_ + 1];
            #pragma unroll
            for (int c = 0; c < 4; c++) {
                int sl = c >> 1;
                float sc = ((c & 1) ? vn1 : vn0) - acc[g][c];
                int n = n0 + nb_ + (c & 1);
                if (sc < m1[sl]) { m2[sl] = m1[sl]; m1[sl] = sc; i1[sl] = n; }
                else if (sc < m2[sl]) m2[sl] = sc;
            }
        }
        #pragma unroll
        for (int off = 1; off <= 2; off <<= 1) {
            #pragma unroll
            for (int sl = 0; sl < 2; sl++) {
                float om1 = __shfl_xor_sync(0xffffffffu, m1[sl], off);
                float om2 = __shfl_xor_sync(0xffffffffu, m2[sl], off);
                int   oi  = __shfl_xor_sync(0xffffffffu, i1[sl], off);
                if (om1 < m1[sl] || (om1 == m1[sl] && oi < i1[sl])) {
                    m2[sl] = fminf(m1[sl], om2); m1[sl] = om1; i1[sl] = oi;
                } else {
                    m2[sl] = fminf(m2[sl], om1);
                }
            }
        }
        // redistribute so lanes 0..15 hold token wid*16+lane -> coalesced stores
        {
            int src = (lane & 7) * 4;           // quad leader for (lane mod 8)
            float a1 = __shfl_sync(0xffffffffu, m1[0], src);
            float b1 = __shfl_sync(0xffffffffu, m1[1], src);
            float a2 = __shfl_sync(0xffffffffu, m2[0], src);
            float b2 = __shfl_sync(0xffffffffu, m2[1], src);
            int   ai = __shfl_sync(0xffffffffu, i1[0], src);
            int   bi = __shfl_sync(0xffffffffu, i1[1], src);
            if (lane < 16) {
                bool hi = lane >= 8;
                int token = m0 + wid * 16 + lane;
                size_t o = (size_t)bn * NTOK + token;
                g_s1[o] = hi ? b1 : a1;
                g_s2[o] = hi ? b2 : a2;
                g_i1[o] = hi ? bi : ai;
            }
        }
    }
#undef LOAD_A
}

// ============================ reduce + flag (2 threads/token) ============================
__global__ void reduce_kernel() {
    int gid  = blockIdx.x * blockDim.x + threadIdx.x;   // 65536 threads
    int t    = gid >> 1;
    int half = gid & 1;
    float m1 = FLT_MAX, m2 = FLT_MAX; int i1 = 0x7FFFFFFF;
    #pragma unroll 4
    for (int nt = half; nt < NTIL; nt += 2) {
        float s1 = g_s1[(size_t)nt * NTOK + t];
        float s2 = g_s2[(size_t)nt * NTOK + t];
        int   ii = g_i1[(size_t)nt * NTOK + t];
        if (s1 < m1 || (s1 == m1 && ii < i1)) {
            m2 = fminf(m1, s2); m1 = s1; i1 = ii;
        } else {
            m2 = fminf(m2, s1);
        }
    }
    // merge partner (same token, other half)
    float om1 = __shfl_xor_sync(0xffffffffu, m1, 1);
    float om2 = __shfl_xor_sync(0xffffffffu, m2, 1);
    int   oi  = __shfl_xor_sync(0xffffffffu, i1, 1);
    if (om1 < m1 || (om1 == m1 && oi < i1)) {
        m2 = fminf(m1, om2); m1 = om1; i1 = oi;
    } else {
        m2 = fminf(m2, om1);
    }
    if (half == 0) {
        if (m2 - m1 < TAU) {
            g_key[t] = 0xFFFFFFFFFFFFFFFFull;   // sentinel: exact pass decides
            int slot = atomicAdd(&g_wlcount, 1);
            g_wl[slot] = t;
        } else {
            g_key[t] = ((unsigned long long)f2ord(m1) << 32) | (uint32_t)i1;
        }
    }
}

// ======= afill: pack flagged tokens into compact split-A' (padded to 128) =======
__global__ void afill_kernel(const float* __restrict__ seq) {
    int nf = g_wlcount;
    if (nf == 0) return;
    int nfp = (nf + 127) & ~127;
    int total = nfp * 64;                       // 64 float4 per row
    for (int idx = blockIdx.x * blockDim.x + threadIdx.x; idx < total;
         idx += gridDim.x * blockDim.x) {
        int w  = idx >> 6;
        int c4 = idx & 63;
        int t  = g_wl[w < nf ? w : (nf - 1)];
        float4 x = ((const float4*)seq)[(size_t)t * 64 + c4];
        float xs[4] = {x.x, x.y, x.z, x.w};
        __half h[4], l[4];
        #pragma unroll
        for (int i = 0; i < 4; i++) {
            h[i] = __float2half_rn(xs[i]);
            l[i] = __float2half_rn(xs[i] - __half2float(h[i]));
        }
        uint2 uh, ul;
        __half2 h0 = {h[0], h[1]}, h1 = {h[2], h[3]};
        __half2 l0 = {l[0], l[1]}, l1 = {l[2], l[3]};
        uh.x = *(uint32_t*)&h0; uh.y = *(uint32_t*)&h1;
        ul.x = *(uint32_t*)&l0; ul.y = *(uint32_t*)&l1;
        __half* r = g_As + (size_t)w * KSPL;
        *(uint2*)(r + c4 * 4)       = uh;       // hi
        *(uint2*)(r + 256 + c4 * 4) = ul;       // lo
        *(uint2*)(r + 512 + c4 * 4) = uh;       // hi
    }
}

// ===== exact cleanup: split-fp16 GEMM (K=768) over flagged tokens, top-1 =====
__global__ __launch_bounds__(256, 2)
void cleanup_gemm() {
    int nf = g_wlcount;
    if (nf == 0) return;
    const int mg = blockIdx.x >> 6;
    if (mg * 128 >= nf) return;

    extern __shared__ char smem[];
    uint32_t sbase = smem_u32(smem);
    float* s_vn = (float*)(smem + CU_VN);
    float* r1a  = (float*)(smem + CU_R1);
    int*   ria  = (int*)  (smem + CU_RI);
    int*   tk   = (int*)  (smem + CU_TK);

    const int tid = threadIdx.x, lane = tid & 31, wid = tid >> 5;
    const int wm = wid & 1, wn = wid >> 1;
    const int bn = blockIdx.x & 63;
    const int n0 = bn * 128;
    const int m0 = mg * 128;

    const char* Ab = (const char*)g_As + (size_t)m0 * (KSPL * 2);
    const char* Bb = (const char*)g_Bs + (size_t)n0 * (KSPL * 2);

#define CU_LOAD(J)                                                             \
    {                                                                          \
        uint32_t st = sbase + CU_ST((J) & 1);                                  \
        _Pragma("unroll")                                                      \
        for (int q = 0; q < 4; q++) {                                          \
            int p = tid + 256 * q; int r = p >> 3, jj = p & 7;                 \
            cpasync16(st + swz(r * 128 + jj * 16),                             \
                      Ab + (size_t)r * (KSPL * 2) + (J) * 128 + jj * 16);      \
        }                                                                      \
        _Pragma("unroll")                                                      \
        for (int q = 0; q < 4; q++) {                                          \
            int p = tid + 256 * q; int r = p >> 3, jj = p & 7;                 \
            cpasync16(st + 16384 + swz(r * 128 + jj * 16),                     \
                      Bb + (size_t)r * (KSPL * 2) + (J) * 128 + jj * 16);      \
        }                                                                      \
        CP_COMMIT();                                                           \
    }

    CU_LOAD(0)
    CU_LOAD(1)
    if (tid < 128) {
        s_vn[tid] = g_vnorm[n0 + tid];
        int w = m0 + tid;
        tk[tid] = g_wl[w < nf ? w : (nf - 1)];
    }

    float acc[4][4][4];
    #pragma unroll
    for (int i = 0; i < 4; i++)
        #pragma unroll
        for (int j = 0; j < 4; j++)
            #pragma unroll
            for (int c = 0; c < 4; c++) acc[i][j][c] = 0.f;

#define CU_COMPUTE(ST)                                                         \
    {                                                                          \
        uint32_t Abase = sbase + CU_ST(ST);                                    \
        uint32_t Bbase = Abase + 16384;                                        \
        _Pragma("unroll")                                                      \
        for (int ks = 0; ks < 4; ks++) {                                       \
            uint32_t af[4][4];                                                 \
            _Pragma("unroll")                                                  \
            for (int mt = 0; mt < 4; mt++) {                                   \
                int row = wm * 64 + mt * 16 + (lane & 15);                     \
                uint32_t ad = Abase + swz(row * 128 + ks * 32 + (lane >> 4) * 16); \
                ldsm4(af[mt][0], af[mt][1], af[mt][2], af[mt][3], ad);         \
            }                                                                  \
            uint32_t bf[2][4];                                                 \
            _Pragma("unroll")                                                  \
            for (int np = 0; np < 2; np++) {                                   \
                int row = wn * 32 + np * 16 + (lane & 15);                     \
                uint32_t bd = Bbase + swz(row * 128 + ks * 32 + (lane >> 4) * 16); \
                ldsm4(bf[np][0], bf[np][1], bf[np][2], bf[np][3], bd);         \
            }                                                                  \
            _Pragma("unroll")                                                  \
            for (int mt = 0; mt < 4; mt++) {                                   \
                _Pragma("unroll")                                              \
                for (int nt = 0; nt < 4; nt++) {                               \
                    int np = nt >> 1, sub = nt & 1;                            \
                    mma16816(acc[mt][nt], af[mt], bf[np][sub], bf[np][sub + 2]); \
                }                                                              \
            }                                                                  \
        }                                                                      \
    }

    #pragma unroll
    for (int c = 0; c < 12; c++) {
        if (c == 11) { CP_WAIT(0); } else { CP_WAIT(1); }
        __syncthreads();
        CU_COMPUTE(c & 1)
        __syncthreads();
        if (c + 2 < 12) CU_LOAD(c + 2)
    }
#undef CU_COMPUTE
#undef CU_LOAD

    // ---- top-1 epilogue ----
    float m1[8]; int i1[8];
    #pragma unroll
    for (int s = 0; s < 8; s++) { m1[s] = FLT_MAX; i1[s] = 0x7FFFFFFF; }

    #pragma unroll
    for (int nt = 0; nt < 4; nt++) {
        int nloc_base = wn * 32 + (nt >> 1) * 16 + (nt & 1) * 8 + (lane & 3) * 2;
        #pragma unroll
        for (int cc = 0; cc < 2; cc++) {
            int nloc = nloc_base + cc;
            float vn = s_vn[nloc];
            int n = n0 + nloc;
            #pragma unroll
            for (int mq = 0; mq < 4; mq++) {
                #pragma unroll
                for (int rg = 0; rg < 2; rg++) {
                    int s_ = mq * 2 + rg;
                    float sc = vn - acc[mq][nt][rg * 2 + cc];
                    if (sc < m1[s_]) { m1[s_] = sc; i1[s_] = n; }
                }
            }
        }
    }
    #pragma unroll
    for (int s = 0; s < 8; s++) {
        #pragma unroll
        for (int off = 1; off <= 2; off <<= 1) {
            float om1 = __shfl_xor_sync(0xffffffffu, m1[s], off);
            int   oi  = __shfl_xor_sync(0xffffffffu, i1[s], off);
            if (om1 < m1[s] || (om1 == m1[s] && oi < i1[s])) {
                m1[s] = om1; i1[s] = oi;
            }
        }
    }
    if ((lane & 3) == 0) {
        #pragma unroll
        for (int mq = 0; mq < 4; mq++)
            #pragma unroll
            for (int rg = 0; rg < 2; rg++) {
                int s_ = mq * 2 + rg;
                int row = wm * 64 + mq * 16 + rg * 8 + (lane >> 2);
                r1a[row * 4 + wn] = m1[s_];
                ria[row * 4 + wn] = i1[s_];
            }
    }
    __syncthreads();
    if (tid < 128 && m0 + tid < nf) {
        float M1 = FLT_MAX; int I1 = 0x7FFFFFFF;
        #pragma unroll
        for (int w = 0; w < 4; w++) {
            float a1 = r1a[tid * 4 + w];
            int   ai = ria[tid * 4 + w];
            if (a1 < M1 || (a1 == M1 && ai < I1)) { M1 = a1; I1 = ai; }
        }
        unsigned long long key =
            ((unsigned long long)f2ord(M1) << 32) | (uint32_t)I1;
        atomicMin(&g_key[tk[tid]], key);
    }
}

// ============================ gather (reads packed key) ============================
__global__ void gather_kernel(const float* __restrict__ vocab,
                              float* __restrict__ out, int write_idx) {
    int token = blockIdx.x * 4 + (threadIdx.x >> 6);
    int l     = threadIdx.x & 63;
    int idx   = (int)(unsigned)(g_key[token] & 0xFFFFFFFFull);
    const float4* src = (const float4*)(vocab + (size_t)idx * DIMD);
    float4*       dst = (float4*)(out + (size_t)token * DIMD);
    dst[l] = src[l];
    if (write_idx && l == 0)
        out[(size_t)NTOK * DIMD + token] = (float)idx;
}

// ============================ launch ============================
extern "C" void kernel_launch(void* const* d_in, const int* in_sizes, int n_in,
                              void* d_out, int out_size) {
    const float* seq   = (const float*)d_in[0];
    const float* vocab = (const float*)d_in[1];
    float* out = (float*)d_out;
    int write_idx = (out_size >= NTOK * DIMD + NTOK) ? 1 : 0;

    cudaFuncSetAttribute(gemm_kernel,
                         cudaFuncAttributeMaxDynamicSharedMemorySize, SM_TOTAL);
    cudaFuncSetAttribute(cleanup_gemm,
                         cudaFuncAttributeMaxDynamicSharedMemorySize, CU_SM_TOTAL);

    convert_kernel<<<8192 + 1024, 256>>>(seq, vocab);
    gemm_kernel<<<(NTOK / (MGRP * 128)) * NTIL, 256, SM_TOTAL>>>();
    reduce_kernel<<<NTOK * 2 / 256, 256>>>();
    afill_kernel<<<1024, 256>>>(seq);
    cleanup_gemm<<<(NTOK / 128) * 64, 256, CU_SM_TOTAL>>>();
    gather_kernel<<<NTOK / 4, 256>>>(vocab, out, write_idx);
}

// round 13
// speedup vs baseline: 1.9290x; 1.0153x over previous
#include <cuda_runtime.h>
#include <cuda_fp16.h>
#include <cstdint>
#include <float.h>

#define NTOK 32768
#define DIMD 256
#define KVOC 8192
#define NTIL   64           // n-tiles of 128 codewords
#define MGRP   8            // m-tiles per CTA (persistent-B coarse gemm)
#define TAU  0.03f
#define KSPL 768            // split-K: [x_hi|x_lo|x_hi] . [v_hi|v_hi|v_lo]

// ---- device scratch ----
__device__ __half g_Ah[(size_t)NTOK * DIMD];   // 16 MB fp16 tokens (coarse)
__device__ __half g_Bh[(size_t)KVOC * DIMD];   // 4 MB fp16 vocab (coarse)
__device__ __half g_As[(size_t)NTOK * KSPL];   // split-A (flagged, compact)
__device__ __half g_Bs[(size_t)KVOC * KSPL];   // split-B
__device__ float  g_vnorm[KVOC];               // 0.5*||v||^2 fp32
__device__ float  g_s1[(size_t)NTIL * NTOK];
__device__ float  g_s2[(size_t)NTIL * NTOK];
__device__ int    g_i1[(size_t)NTIL * NTOK];
__device__ unsigned long long g_key[NTOK];
__device__ int    g_wl[NTOK];
__device__ int    g_wlcount;

// ---- coarse gemm smem: A stages (2x16KB) | B chunks (4x16KB) | vn ----
#define SA_OFF(st) ((st) * 16384)
#define SB_OFF(c)  (32768 + (c) * 16384)
#define SO_VN  98304
#define SM_TOTAL 98816

// ---- cleanup gemm smem: 2 stages x (A 16KB + B 16KB) | vn | red | tk ----
#define CU_ST(st)  ((st) * 32768)
#define CU_VN  65536
#define CU_R1  66048
#define CU_RI  68096
#define CU_TK  70144
#define CU_SM_TOTAL 70656

// ============================ asm helpers ============================
__device__ __forceinline__ uint32_t smem_u32(const void* p) {
    uint32_t a;
    asm("{ .reg .u64 t; cvta.to.shared.u64 t, %1; cvt.u32.u64 %0, t; }"
        : "=r"(a) : "l"(p));
    return a;
}
__device__ __forceinline__ void cpasync16(uint32_t s, const void* g) {
    asm volatile("cp.async.cg.shared.global [%0], [%1], 16;" :: "r"(s), "l"(g));
}
#define CP_COMMIT() asm volatile("cp.async.commit_group;" ::: "memory")
#define CP_WAIT(N)  asm volatile("cp.async.wait_group " #N ";" ::: "memory")

__device__ __forceinline__ void ldsm4(uint32_t& r0, uint32_t& r1, uint32_t& r2,
                                      uint32_t& r3, uint32_t addr) {
    asm volatile("ldmatrix.sync.aligned.m8n8.x4.shared.b16 {%0,%1,%2,%3}, [%4];"
                 : "=r"(r0), "=r"(r1), "=r"(r2), "=r"(r3) : "r"(addr));
}
__device__ __forceinline__ void mma16816(float* d, const uint32_t* a,
                                         uint32_t b0, uint32_t b1) {
    asm volatile(
        "mma.sync.aligned.m16n8k16.row.col.f32.f16.f16.f32 "
        "{%0,%1,%2,%3},{%4,%5,%6,%7},{%8,%9},{%0,%1,%2,%3};"
        : "+f"(d[0]), "+f"(d[1]), "+f"(d[2]), "+f"(d[3])
        : "r"(a[0]), "r"(a[1]), "r"(a[2]), "r"(a[3]), "r"(b0), "r"(b1));
}
__device__ __forceinline__ uint32_t swz(uint32_t off) {
    return off ^ ((off >> 3) & 0x70);
}
__device__ __forceinline__ uint32_t f2ord(float s) {
    uint32_t fb = __float_as_uint(s);
    return (fb & 0x80000000u) ? ~fb : (fb | 0x80000000u);
}

// =================== convert kernel (seq fp16 + vocab fp16/vnorm) ===================
__global__ void convert_kernel(const float* __restrict__ seq,
                               const float* __restrict__ vocab) {
    if (blockIdx.x == 0 && threadIdx.x == 0) g_wlcount = 0;
    if (blockIdx.x < 8192) {
        int idx = blockIdx.x * 256 + threadIdx.x;   // one float4 each
        int row = idx >> 6;
        int c4  = idx & 63;
        float4 x = ((const float4*)seq)[idx];
        __half2 a = __floats2half2_rn(x.x, x.y);
        __half2 b = __floats2half2_rn(x.z, x.w);
        uint2 u;
        u.x = *(uint32_t*)&a; u.y = *(uint32_t*)&b;
        *(uint2*)(g_Ah + (size_t)row * DIMD + c4 * 4) = u;
    } else {
        int row  = (blockIdx.x - 8192) * 8 + (threadIdx.x >> 5);
        int lane = threadIdx.x & 31;
        const float4* v = (const float4*)(vocab + (size_t)row * DIMD);
        float s = 0.f;
        #pragma unroll
        for (int c4 = lane; c4 < 64; c4 += 32) {
            float4 x = v[c4];
            s += x.x*x.x + x.y*x.y + x.z*x.z + x.w*x.w;
            __half2 a = __floats2half2_rn(x.x, x.y);
            __half2 b = __floats2half2_rn(x.z, x.w);
            uint2 u;
            u.x = *(uint32_t*)&a; u.y = *(uint32_t*)&b;
            *(uint2*)(g_Bh + (size_t)row * DIMD + c4 * 4) = u;
        }
        #pragma unroll
        for (int o = 16; o; o >>= 1) s += __shfl_xor_sync(0xffffffffu, s, o);
        if (lane == 0) g_vnorm[row] = 0.5f * s;
    }
}

// ====== persistent-B fp16 coarse GEMM, row-owning warps, fused top-2 ======
// Also builds split-B (g_Bs) in its tail: 2048 CTAs x 4 vocab rows.
__global__ __launch_bounds__(256, 2)
void gemm_kernel(const float* __restrict__ vocab) {
    extern __shared__ char smem[];
    uint32_t sbase = smem_u32(smem);
    float* s_vn = (float*)(smem + SO_VN);

    const int tid = threadIdx.x, lane = tid & 31, wid = tid >> 5;
    const int bn = blockIdx.x & (NTIL - 1);         // n-tile
    const int mg = blockIdx.x >> 6;                 // m-group
    const int n0 = bn * 128;
    const int mbase = mg * MGRP * 128;

    const char* Bb = (const char*)g_Bh + (size_t)n0 * 512;

    // ---- B n-tile (64KB = 4 chunk sub-tiles), one group
    #pragma unroll
    for (int q = 0; q < 16; q++) {
        int c  = q >> 2;
        int p  = tid + 256 * (q & 3);
        int r  = p >> 3, jj = p & 7;
        cpasync16(sbase + SB_OFF(c) + swz(r * 128 + jj * 16),
                  Bb + (size_t)r * 512 + c * 128 + jj * 16);
    }
    CP_COMMIT();

    // A chunk J (J = mt*4 + c) -> stage (J & 1)
#define LOAD_A(J)                                                              \
    {                                                                          \
        uint32_t st = sbase + SA_OFF((J) & 1);                                 \
        const char* Asrc = (const char*)g_Ah                                   \
            + (size_t)(mbase + ((J) >> 2) * 128) * 512 + ((J) & 3) * 128;      \
        _Pragma("unroll")                                                      \
        for (int q = 0; q < 4; q++) {                                          \
            int p = tid + 256 * q; int r = p >> 3, jj = p & 7;                 \
            cpasync16(st + swz(r * 128 + jj * 16),                             \
                      Asrc + (size_t)r * 512 + jj * 16);                       \
        }                                                                      \
        CP_COMMIT();                                                           \
    }

    LOAD_A(0)
    if (tid < 128) s_vn[tid] = g_vnorm[n0 + tid];

    // warp wid owns rows [wid*16, wid*16+16) x all 128 cols
    float acc[16][4];

    for (int mt = 0; mt < MGRP; mt++) {
        #pragma unroll
        for (int g = 0; g < 16; g++)
            #pragma unroll
            for (int c = 0; c < 4; c++) acc[g][c] = 0.f;

        #pragma unroll
        for (int c = 0; c < 4; c++) {
            const int j = mt * 4 + c;
            CP_WAIT(0);
            __syncthreads();            // chunk j ready; stage (j+1)&1 free
            if (j + 1 < MGRP * 4) LOAD_A(j + 1)

            uint32_t Abase = sbase + SA_OFF(j & 1);
            uint32_t Bbase = sbase + SB_OFF(c);
            #pragma unroll
            for (int ks = 0; ks < 4; ks++) {
                uint32_t af[4];
                {
                    int row = wid * 16 + (lane & 15);
                    uint32_t ad = Abase + swz(row * 128 + ks * 32 + (lane >> 4) * 16);
                    ldsm4(af[0], af[1], af[2], af[3], ad);
                }
                uint32_t bf[8][4];
                #pragma unroll
                for (int nb = 0; nb < 8; nb++) {
                    int row = nb * 16 + (lane & 15);
                    uint32_t bd = Bbase + swz(row * 128 + ks * 32 + (lane >> 4) * 16);
                    ldsm4(bf[nb][0], bf[nb][1], bf[nb][2], bf[nb][3], bd);
                }
                #pragma unroll
                for (int nb = 0; nb < 8; nb++) {
                    mma16816(acc[nb * 2],     af, bf[nb][0], bf[nb][2]);
                    mma16816(acc[nb * 2 + 1], af, bf[nb][1], bf[nb][3]);
                }
            }
        }

        // ---- warp-local top-2 epilogue (no smem, no barriers) ----
        const int m0 = mbase + mt * 128;
        float m1[2] = {FLT_MAX, FLT_MAX}, m2[2] = {FLT_MAX, FLT_MAX};
        int   i1[2] = {0x7FFFFFFF, 0x7FFFFFFF};

        #pragma unroll
        for (int g = 0; g < 16; g++) {
            int nb_ = g * 8 + (lane & 3) * 2;
            float vn0 = s_vn[nb_], vn1 = s_vn[nb_ + 1];
            #pragma unroll
            for (int c = 0; c < 4; c++) {
                int sl = c >> 1;
                float sc = ((c & 1) ? vn1 : vn0) - acc[g][c];
                int n = n0 + nb_ + (c & 1);
                if (sc < m1[sl]) { m2[sl] = m1[sl]; m1[sl] = sc; i1[sl] = n; }
                else if (sc < m2[sl]) m2[sl] = sc;
            }
        }
        #pragma unroll
        for (int off = 1; off <= 2; off <<= 1) {
            #pragma unroll
            for (int sl = 0; sl < 2; sl++) {
                float om1 = __shfl_xor_sync(0xffffffffu, m1[sl], off);
                float om2 = __shfl_xor_sync(0xffffffffu, m2[sl], off);
                int   oi  = __shfl_xor_sync(0xffffffffu, i1[sl], off);
                if (om1 < m1[sl] || (om1 == m1[sl] && oi < i1[sl])) {
                    m2[sl] = fminf(m1[sl], om2); m1[sl] = om1; i1[sl] = oi;
                } else {
                    m2[sl] = fminf(m2[sl], om1);
                }
            }
        }
        // redistribute so lanes 0..15 hold token wid*16+lane -> coalesced stores
        {
            int src = (lane & 7) * 4;           // quad leader for (lane mod 8)
            float a1 = __shfl_sync(0xffffffffu, m1[0], src);
            float b1 = __shfl_sync(0xffffffffu, m1[1], src);
            float a2 = __shfl_sync(0xffffffffu, m2[0], src);
            float b2 = __shfl_sync(0xffffffffu, m2[1], src);
            int   ai = __shfl_sync(0xffffffffu, i1[0], src);
            int   bi = __shfl_sync(0xffffffffu, i1[1], src);
            if (lane < 16) {
                bool hi = lane >= 8;
                int token = m0 + wid * 16 + lane;
                size_t o = (size_t)bn * NTOK + token;
                g_s1[o] = hi ? b1 : a1;
                g_s2[o] = hi ? b2 : a2;
                g_i1[o] = hi ? bi : ai;
            }
        }
    }
#undef LOAD_A

    // ---- tail: build split-B rows [blockIdx.x*4, +4) (tensor pipe idle) ----
    {
        int row  = blockIdx.x * 4 + (wid >> 1);       // 2 warps per row
        int c4   = (wid & 1) * 32 + lane;             // float4 index 0..63
        float4 x = ((const float4*)vocab)[(size_t)row * 64 + c4];
        float xs[4] = {x.x, x.y, x.z, x.w};
        __half h[4], l[4];
        #pragma unroll
        for (int i = 0; i < 4; i++) {
            h[i] = __float2half_rn(xs[i]);
            l[i] = __float2half_rn(xs[i] - __half2float(h[i]));
        }
        uint2 uh, ul;
        __half2 h0 = {h[0], h[1]}, h1 = {h[2], h[3]};
        __half2 l0 = {l[0], l[1]}, l1 = {l[2], l[3]};
        uh.x = *(uint32_t*)&h0; uh.y = *(uint32_t*)&h1;
        ul.x = *(uint32_t*)&l0; ul.y = *(uint32_t*)&l1;
        __half* rs = g_Bs + (size_t)row * KSPL;
        int col = c4 * 4;
        *(uint2*)(rs + col)       = uh;               // hi
        *(uint2*)(rs + 256 + col) = uh;               // hi
        *(uint2*)(rs + 512 + col) = ul;               // lo
    }
}

// ======== reduce + flag + inline split-A fill (2 threads/token) ========
__global__ void reduce_kernel(const float* __restrict__ seq) {
    int gid  = blockIdx.x * blockDim.x + threadIdx.x;   // 65536 threads
    int t    = gid >> 1;
    int half = gid & 1;
    int lane = threadIdx.x & 31;
    float m1 = FLT_MAX, m2 = FLT_MAX; int i1 = 0x7FFFFFFF;
    #pragma unroll 4
    for (int nt = half; nt < NTIL; nt += 2) {
        float s1 = g_s1[(size_t)nt * NTOK + t];
        float s2 = g_s2[(size_t)nt * NTOK + t];
        int   ii = g_i1[(size_t)nt * NTOK + t];
        if (s1 < m1 || (s1 == m1 && ii < i1)) {
            m2 = fminf(m1, s2); m1 = s1; i1 = ii;
        } else {
            m2 = fminf(m2, s1);
        }
    }
    // merge partner (same token, other half)
    float om1 = __shfl_xor_sync(0xffffffffu, m1, 1);
    float om2 = __shfl_xor_sync(0xffffffffu, m2, 1);
    int   oi  = __shfl_xor_sync(0xffffffffu, i1, 1);
    if (om1 < m1 || (om1 == m1 && oi < i1)) {
        m2 = fminf(m1, om2); m1 = om1; i1 = oi;
    } else {
        m2 = fminf(m2, om1);
    }
    bool flag = (m2 - m1 < TAU);
    int slot = -1;
    if (half == 0) {
        if (flag) {
            g_key[t] = 0xFFFFFFFFFFFFFFFFull;   // sentinel: exact pass decides
            slot = atomicAdd(&g_wlcount, 1);
            g_wl[slot] = t;
        } else {
            g_key[t] = ((unsigned long long)f2ord(m1) << 32) | (uint32_t)i1;
        }
    }
    // broadcast slot from the half==0 partner
    slot = __shfl_sync(0xffffffffu, slot, lane & ~1);
    if (flag) {
        // this thread fills cols [half*128, half*128+128) of split-A row `slot`
        __half* r = g_As + (size_t)slot * KSPL;
        const float4* src = (const float4*)(seq) + (size_t)t * 64 + half * 32;
        #pragma unroll 8
        for (int i = 0; i < 32; i++) {
            float4 x = src[i];
            float xs[4] = {x.x, x.y, x.z, x.w};
            __half h[4], l[4];
            #pragma unroll
            for (int k = 0; k < 4; k++) {
                h[k] = __float2half_rn(xs[k]);
                l[k] = __float2half_rn(xs[k] - __half2float(h[k]));
            }
            uint2 uh, ul;
            __half2 h0 = {h[0], h[1]}, h1 = {h[2], h[3]};
            __half2 l0 = {l[0], l[1]}, l1 = {l[2], l[3]};
            uh.x = *(uint32_t*)&h0; uh.y = *(uint32_t*)&h1;
            ul.x = *(uint32_t*)&l0; ul.y = *(uint32_t*)&l1;
            int col = half * 128 + i * 4;
            *(uint2*)(r + col)       = uh;      // hi
            *(uint2*)(r + 256 + col) = ul;      // lo
            *(uint2*)(r + 512 + col) = uh;      // hi
        }
    }
}

// ===== exact cleanup: split-fp16 GEMM (K=768) over flagged tokens, top-1 =====
__global__ __launch_bounds__(256, 2)
void cleanup_gemm() {
    int nf = g_wlcount;
    if (nf == 0) return;
    const int mg = blockIdx.x >> 6;
    if (mg * 128 >= nf) return;

    extern __shared__ char smem[];
    uint32_t sbase = smem_u32(smem);
    float* s_vn = (float*)(smem + CU_VN);
    float* r1a  = (float*)(smem + CU_R1);
    int*   ria  = (int*)  (smem + CU_RI);
    int*   tk   = (int*)  (smem + CU_TK);

    const int tid = threadIdx.x, lane = tid & 31, wid = tid >> 5;
    const int wm = wid & 1, wn = wid >> 1;
    const int bn = blockIdx.x & 63;
    const int n0 = bn * 128;
    const int m0 = mg * 128;

    const char* Ab = (const char*)g_As + (size_t)m0 * (KSPL * 2);
    const char* Bb = (const char*)g_Bs + (size_t)n0 * (KSPL * 2);

#define CU_LOAD(J)                                                             \
    {                                                                          \
        uint32_t st = sbase + CU_ST((J) & 1);                                  \
        _Pragma("unroll")                                                      \
        for (int q = 0; q < 4; q++) {                                          \
            int p = tid + 256 * q; int r = p >> 3, jj = p & 7;                 \
            cpasync16(st + swz(r * 128 + jj * 16),                             \
                      Ab + (size_t)r * (KSPL * 2) + (J) * 128 + jj * 16);      \
        }                                                                      \
        _Pragma("unroll")                                                      \
        for (int q = 0; q < 4; q++) {                                          \
            int p = tid + 256 * q; int r = p >> 3, jj = p & 7;                 \
            cpasync16(st + 16384 + swz(r * 128 + jj * 16),                     \
                      Bb + (size_t)r * (KSPL * 2) + (J) * 128 + jj * 16);      \
        }                                                                      \
        CP_COMMIT();                                                           \
    }

    CU_LOAD(0)
    CU_LOAD(1)
    if (tid < 128) {
        s_vn[tid] = g_vnorm[n0 + tid];
        int w = m0 + tid;
        tk[tid] = g_wl[w < nf ? w : (nf - 1)];
    }

    float acc[4][4][4];
    #pragma unroll
    for (int i = 0; i < 4; i++)
        #pragma unroll
        for (int j = 0; j < 4; j++)
            #pragma unroll
            for (int c = 0; c < 4; c++) acc[i][j][c] = 0.f;

#define CU_COMPUTE(ST)                                                         \
    {                                                                          \
        uint32_t Abase = sbase + CU_ST(ST);                                    \
        uint32_t Bbase = Abase + 16384;                                        \
        _Pragma("unroll")                                                      \
        for (int ks = 0; ks < 4; ks++) {                                       \
            uint32_t af[4][4];                                                 \
            _Pragma("unroll")                                                  \
            for (int mt = 0; mt < 4; mt++) {                                   \
                int row = wm * 64 + mt * 16 + (lane & 15);                     \
                uint32_t ad = Abase + swz(row * 128 + ks * 32 + (lane >> 4) * 16); \
                ldsm4(af[mt][0], af[mt][1], af[mt][2], af[mt][3], ad);         \
            }                                                                  \
            uint32_t bf[2][4];                                                 \
            _Pragma("unroll")                                                  \
            for (int np = 0; np < 2; np++) {                                   \
                int row = wn * 32 + np * 16 + (lane & 15);                     \
                uint32_t bd = Bbase + swz(row * 128 + ks * 32 + (lane >> 4) * 16); \
                ldsm4(bf[np][0], bf[np][1], bf[np][2], bf[np][3], bd);         \
            }                                                                  \
            _Pragma("unroll")                                                  \
            for (int mt = 0; mt < 4; mt++) {                                   \
                _Pragma("unroll")                                              \
                for (int nt = 0; nt < 4; nt++) {                               \
                    int np = nt >> 1, sub = nt & 1;                            \
                    mma16816(acc[mt][nt], af[mt], bf[np][sub], bf[np][sub + 2]); \
                }                                                              \
            }                                                                  \
        }                                                                      \
    }

    #pragma unroll
    for (int c = 0; c < 12; c++) {
        if (c == 11) { CP_WAIT(0); } else { CP_WAIT(1); }
        __syncthreads();
        CU_COMPUTE(c & 1)
        __syncthreads();
        if (c + 2 < 12) CU_LOAD(c + 2)
    }
#undef CU_COMPUTE
#undef CU_LOAD

    // ---- top-1 epilogue ----
    float m1[8]; int i1[8];
    #pragma unroll
    for (int s = 0; s < 8; s++) { m1[s] = FLT_MAX; i1[s] = 0x7FFFFFFF; }

    #pragma unroll
    for (int nt = 0; nt < 4; nt++) {
        int nloc_base = wn * 32 + (nt >> 1) * 16 + (nt & 1) * 8 + (lane & 3) * 2;
        #pragma unroll
        for (int cc = 0; cc < 2; cc++) {
            int nloc = nloc_base + cc;
            float vn = s_vn[nloc];
            int n = n0 + nloc;
            #pragma unroll
            for (int mq = 0; mq < 4; mq++) {
                #pragma unroll
                for (int rg = 0; rg < 2; rg++) {
                    int s_ = mq * 2 + rg;
                    float sc = vn - acc[mq][nt][rg * 2 + cc];
                    if (sc < m1[s_]) { m1[s_] = sc; i1[s_] = n; }
                }
            }
        }
    }
    #pragma unroll
    for (int s = 0; s < 8; s++) {
        #pragma unroll
        for (int off = 1; off <= 2; off <<= 1) {
            float om1 = __shfl_xor_sync(0xffffffffu, m1[s], off);
            int   oi  = __shfl_xor_sync(0xffffffffu, i1[s], off);
            if (om1 < m1[s] || (om1 == m1[s] && oi < i1[s])) {
                m1[s] = om1; i1[s] = oi;
            }
        }
    }
    if ((lane & 3) == 0) {
        #pragma unroll
        for (int mq = 0; mq < 4; mq++)
            #pragma unroll
            for (int rg = 0; rg < 2; rg++) {
                int s_ = mq * 2 + rg;
                int row = wm * 64 + mq * 16 + rg * 8 + (lane >> 2);
                r1a[row * 4 + wn] = m1[s_];
                ria[row * 4 + wn] = i1[s_];
            }
    }
    __syncthreads();
    if (tid < 128 && m0 + tid < nf) {
        float M1 = FLT_MAX; int I1 = 0x7FFFFFFF;
        #pragma unroll
        for (int w = 0; w < 4; w++) {
            float a1 = r1a[tid * 4 + w];
            int   ai = ria[tid * 4 + w];
            if (a1 < M1 || (a1 == M1 && ai < I1)) { M1 = a1; I1 = ai; }
        }
        unsigned long long key =
            ((unsigned long long)f2ord(M1) << 32) | (uint32_t)I1;
        atomicMin(&g_key[tk[tid]], key);
    }
}

// ============================ gather (reads packed key) ============================
__global__ void gather_kernel(const float* __restrict__ vocab,
                              float* __restrict__ out, int write_idx) {
    int token = blockIdx.x * 4 + (threadIdx.x >> 6);
    int l     = threadIdx.x & 63;
    int idx   = (int)(unsigned)(g_key[token] & 0xFFFFFFFFull);
    const float4* src = (const float4*)(vocab + (size_t)idx * DIMD);
    float4*       dst = (float4*)(out + (size_t)token * DIMD);
    dst[l] = src[l];
    if (write_idx && l == 0)
        out[(size_t)NTOK * DIMD + token] = (float)idx;
}

// ============================ launch ============================
extern "C" void kernel_launch(void* const* d_in, const int* in_sizes, int n_in,
                              void* d_out, int out_size) {
    const float* seq   = (const float*)d_in[0];
    const float* vocab = (const float*)d_in[1];
    float* out = (float*)d_out;
    int write_idx = (out_size >= NTOK * DIMD + NTOK) ? 1 : 0;

    cudaFuncSetAttribute(gemm_kernel,
                         cudaFuncAttributeMaxDynamicSharedMemorySize, SM_TOTAL);
    cudaFuncSetAttribute(cleanup_gemm,
                         cudaFuncAttributeMaxDynamicSharedMemorySize, CU_SM_TOTAL);

    convert_kernel<<<8192 + 1024, 256>>>(seq, vocab);
    gemm_kernel<<<(NTOK / (MGRP * 128)) * NTIL, 256, SM_TOTAL>>>(vocab);
    reduce_kernel<<<NTOK * 2 / 256, 256>>>(seq);
    cleanup_gemm<<<(NTOK / 128) * 64, 256, CU_SM_TOTAL>>>();
    gather_kernel<<<NTOK / 4, 256>>>(vocab, out, write_idx);
}

// round 14
// speedup vs baseline: 1.9443x; 1.0079x over previous
#include <cuda_runtime.h>
#include <cuda_fp16.h>
#include <cstdint>
#include <float.h>

#define NTOK 32768
#define DIMD 256
#define KVOC 8192
#define NTIL   64           // n-tiles of 128 codewords
#define MGRP   8            // m-tiles per CTA (persistent-B coarse gemm)
#define TAU  0.03f
#define KSPL 768            // split-K: [x_hi|x_lo|x_hi] . [v_hi|v_hi|v_lo]

// ---- device scratch ----
__device__ __half g_Ah[(size_t)NTOK * DIMD];   // 16 MB fp16 tokens (coarse)
__device__ __half g_Bh[(size_t)KVOC * DIMD];   // 4 MB fp16 vocab (coarse)
__device__ __half g_As[(size_t)NTOK * KSPL];   // split-A (flagged, compact)
__device__ __half g_Bs[(size_t)KVOC * KSPL];   // split-B
__device__ float  g_vnorm[KVOC];               // 0.5*||v||^2 fp32
__device__ float  g_s1[(size_t)NTIL * NTOK];
__device__ float  g_s2[(size_t)NTIL * NTOK];
__device__ int    g_i1[(size_t)NTIL * NTOK];
__device__ unsigned long long g_key[NTOK];
__device__ int    g_wl[NTOK];
__device__ int    g_wlcount;

// ---- coarse gemm smem: A stages (2x16KB) | B chunks (4x16KB) | vn ----
#define SA_OFF(st) ((st) * 16384)
#define SB_OFF(c)  (32768 + (c) * 16384)
#define SO_VN  98304
#define SM_TOTAL 98816

// ---- cleanup gemm smem: 2 stages x (A 16KB + B 16KB) | vn | red | tk ----
#define CU_ST(st)  ((st) * 32768)
#define CU_VN  65536
#define CU_R1  66048
#define CU_RI  68096
#define CU_TK  70144
#define CU_SM_TOTAL 70656

// ============================ asm helpers ============================
__device__ __forceinline__ uint32_t smem_u32(const void* p) {
    uint32_t a;
    asm("{ .reg .u64 t; cvta.to.shared.u64 t, %1; cvt.u32.u64 %0, t; }"
        : "=r"(a) : "l"(p));
    return a;
}
__device__ __forceinline__ void cpasync16(uint32_t s, const void* g) {
    asm volatile("cp.async.cg.shared.global [%0], [%1], 16;" :: "r"(s), "l"(g));
}
#define CP_COMMIT() asm volatile("cp.async.commit_group;" ::: "memory")
#define CP_WAIT(N)  asm volatile("cp.async.wait_group " #N ";" ::: "memory")

__device__ __forceinline__ void ldsm4(uint32_t& r0, uint32_t& r1, uint32_t& r2,
                                      uint32_t& r3, uint32_t addr) {
    asm volatile("ldmatrix.sync.aligned.m8n8.x4.shared.b16 {%0,%1,%2,%3}, [%4];"
                 : "=r"(r0), "=r"(r1), "=r"(r2), "=r"(r3) : "r"(addr));
}
__device__ __forceinline__ void mma16816(float* d, const uint32_t* a,
                                         uint32_t b0, uint32_t b1) {
    asm volatile(
        "mma.sync.aligned.m16n8k16.row.col.f32.f16.f16.f32 "
        "{%0,%1,%2,%3},{%4,%5,%6,%7},{%8,%9},{%0,%1,%2,%3};"
        : "+f"(d[0]), "+f"(d[1]), "+f"(d[2]), "+f"(d[3])
        : "r"(a[0]), "r"(a[1]), "r"(a[2]), "r"(a[3]), "r"(b0), "r"(b1));
}
__device__ __forceinline__ uint32_t swz(uint32_t off) {
    return off ^ ((off >> 3) & 0x70);
}
__device__ __forceinline__ uint32_t f2ord(float s) {
    uint32_t fb = __float_as_uint(s);
    return (fb & 0x80000000u) ? ~fb : (fb | 0x80000000u);
}

// =================== convert kernel (seq fp16 + vocab fp16/vnorm) ===================
// blocks [0, 2048): seq, 4 float4 per thread (linear fp16 layout -> 2 uint4 stores)
// blocks [2048, 3072): vocab fp16 + vnorm
__global__ void convert_kernel(const float* __restrict__ seq,
                               const float* __restrict__ vocab) {
    if (blockIdx.x == 0 && threadIdx.x == 0) g_wlcount = 0;
    if (blockIdx.x < 2048) {
        int gid = blockIdx.x * 256 + threadIdx.x;     // 524288 threads
        const float4* s4 = (const float4*)seq + (size_t)gid * 4;
        uint2 u[4];
        #pragma unroll
        for (int k = 0; k < 4; k++) {
            float4 x = s4[k];
            __half2 a = __floats2half2_rn(x.x, x.y);
            __half2 b = __floats2half2_rn(x.z, x.w);
            u[k].x = *(uint32_t*)&a; u[k].y = *(uint32_t*)&b;
        }
        uint4* dst = (uint4*)(g_Ah + (size_t)gid * 16);
        dst[0] = make_uint4(u[0].x, u[0].y, u[1].x, u[1].y);
        dst[1] = make_uint4(u[2].x, u[2].y, u[3].x, u[3].y);
    } else {
        int row  = (blockIdx.x - 2048) * 8 + (threadIdx.x >> 5);
        int lane = threadIdx.x & 31;
        const float4* v = (const float4*)(vocab + (size_t)row * DIMD);
        float s = 0.f;
        #pragma unroll
        for (int c4 = lane; c4 < 64; c4 += 32) {
            float4 x = v[c4];
            s += x.x*x.x + x.y*x.y + x.z*x.z + x.w*x.w;
            __half2 a = __floats2half2_rn(x.x, x.y);
            __half2 b = __floats2half2_rn(x.z, x.w);
            uint2 u;
            u.x = *(uint32_t*)&a; u.y = *(uint32_t*)&b;
            *(uint2*)(g_Bh + (size_t)row * DIMD + c4 * 4) = u;
        }
        #pragma unroll
        for (int o = 16; o; o >>= 1) s += __shfl_xor_sync(0xffffffffu, s, o);
        if (lane == 0) g_vnorm[row] = 0.5f * s;
    }
}

// ====== persistent-B fp16 coarse GEMM, row-owning warps, fused top-2 ======
// Also builds split-B (g_Bs) in its tail: 2048 CTAs x 4 vocab rows.
__global__ __launch_bounds__(256, 2)
void gemm_kernel(const float* __restrict__ vocab) {
    extern __shared__ char smem[];
    uint32_t sbase = smem_u32(smem);
    float* s_vn = (float*)(smem + SO_VN);

    const int tid = threadIdx.x, lane = tid & 31, wid = tid >> 5;
    const int bn = blockIdx.x & (NTIL - 1);         // n-tile
    const int mg = blockIdx.x >> 6;                 // m-group
    const int n0 = bn * 128;
    const int mbase = mg * MGRP * 128;

    const char* Bb = (const char*)g_Bh + (size_t)n0 * 512;

    // ---- B n-tile (64KB = 4 chunk sub-tiles), one group
    #pragma unroll
    for (int q = 0; q < 16; q++) {
        int c  = q >> 2;
        int p  = tid + 256 * (q & 3);
        int r  = p >> 3, jj = p & 7;
        cpasync16(sbase + SB_OFF(c) + swz(r * 128 + jj * 16),
                  Bb + (size_t)r * 512 + c * 128 + jj * 16);
    }
    CP_COMMIT();

    // A chunk J (J = mt*4 + c) -> stage (J & 1)
#define LOAD_A(J)                                                              \
    {                                                                          \
        uint32_t st = sbase + SA_OFF((J) & 1);                                 \
        const char* Asrc = (const char*)g_Ah                                   \
            + (size_t)(mbase + ((J) >> 2) * 128) * 512 + ((J) & 3) * 128;      \
        _Pragma("unroll")                                                      \
        for (int q = 0; q < 4; q++) {                                          \
            int p = tid + 256 * q; int r = p >> 3, jj = p & 7;                 \
            cpasync16(st + swz(r * 128 + jj * 16),                             \
                      Asrc + (size_t)r * 512 + jj * 16);                       \
        }                                                                      \
        CP_COMMIT();                                                           \
    }

    LOAD_A(0)
    if (tid < 128) s_vn[tid] = g_vnorm[n0 + tid];

    // warp wid owns rows [wid*16, wid*16+16) x all 128 cols
    float acc[16][4];

    for (int mt = 0; mt < MGRP; mt++) {
        #pragma unroll
        for (int g = 0; g < 16; g++)
            #pragma unroll
            for (int c = 0; c < 4; c++) acc[g][c] = 0.f;

        #pragma unroll
        for (int c = 0; c < 4; c++) {
            const int j = mt * 4 + c;
            CP_WAIT(0);
            __syncthreads();            // chunk j ready; stage (j+1)&1 free
            if (j + 1 < MGRP * 4) LOAD_A(j + 1)

            uint32_t Abase = sbase + SA_OFF(j & 1);
            uint32_t Bbase = sbase + SB_OFF(c);
            #pragma unroll
            for (int ks = 0; ks < 4; ks++) {
                uint32_t af[4];
                {
                    int row = wid * 16 + (lane & 15);
                    uint32_t ad = Abase + swz(row * 128 + ks * 32 + (lane >> 4) * 16);
                    ldsm4(af[0], af[1], af[2], af[3], ad);
                }
                uint32_t bf[8][4];
                #pragma unroll
                for (int nb = 0; nb < 8; nb++) {
                    int row = nb * 16 + (lane & 15);
                    uint32_t bd = Bbase + swz(row * 128 + ks * 32 + (lane >> 4) * 16);
                    ldsm4(bf[nb][0], bf[nb][1], bf[nb][2], bf[nb][3], bd);
                }
                #pragma unroll
                for (int nb = 0; nb < 8; nb++) {
                    mma16816(acc[nb * 2],     af, bf[nb][0], bf[nb][2]);
                    mma16816(acc[nb * 2 + 1], af, bf[nb][1], bf[nb][3]);
                }
            }
        }

        // ---- warp-local top-2 epilogue (no smem, no barriers) ----
        const int m0 = mbase + mt * 128;
        float m1[2] = {FLT_MAX, FLT_MAX}, m2[2] = {FLT_MAX, FLT_MAX};
        int   i1[2] = {0x7FFFFFFF, 0x7FFFFFFF};

        #pragma unroll
        for (int g = 0; g < 16; g++) {
            int nb_ = g * 8 + (lane & 3) * 2;
            float vn0 = s_vn[nb_], vn1 = s_vn[nb_ + 1];
            #pragma unroll
            for (int c = 0; c < 4; c++) {
                int sl = c >> 1;
                float sc = ((c & 1) ? vn1 : vn0) - acc[g][c];
                int n = n0 + nb_ + (c & 1);
                if (sc < m1[sl]) { m2[sl] = m1[sl]; m1[sl] = sc; i1[sl] = n; }
                else if (sc < m2[sl]) m2[sl] = sc;
            }
        }
        #pragma unroll
        for (int off = 1; off <= 2; off <<= 1) {
            #pragma unroll
            for (int sl = 0; sl < 2; sl++) {
                float om1 = __shfl_xor_sync(0xffffffffu, m1[sl], off);
                float om2 = __shfl_xor_sync(0xffffffffu, m2[sl], off);
                int   oi  = __shfl_xor_sync(0xffffffffu, i1[sl], off);
                if (om1 < m1[sl] || (om1 == m1[sl] && oi < i1[sl])) {
                    m2[sl] = fminf(m1[sl], om2); m1[sl] = om1; i1[sl] = oi;
                } else {
                    m2[sl] = fminf(m2[sl], om1);
                }
            }
        }
        // redistribute so lanes 0..15 hold token wid*16+lane -> coalesced stores
        {
            int src = (lane & 7) * 4;           // quad leader for (lane mod 8)
            float a1 = __shfl_sync(0xffffffffu, m1[0], src);
            float b1 = __shfl_sync(0xffffffffu, m1[1], src);
            float a2 = __shfl_sync(0xffffffffu, m2[0], src);
            float b2 = __shfl_sync(0xffffffffu, m2[1], src);
            int   ai = __shfl_sync(0xffffffffu, i1[0], src);
            int   bi = __shfl_sync(0xffffffffu, i1[1], src);
            if (lane < 16) {
                bool hi = lane >= 8;
                int token = m0 + wid * 16 + lane;
                size_t o = (size_t)bn * NTOK + token;
                g_s1[o] = hi ? b1 : a1;
                g_s2[o] = hi ? b2 : a2;
                g_i1[o] = hi ? bi : ai;
            }
        }
    }
#undef LOAD_A

    // ---- tail: build split-B rows [blockIdx.x*4, +4) (tensor pipe idle) ----
    {
        int row  = blockIdx.x * 4 + (wid >> 1);       // 2 warps per row
        int c4   = (wid & 1) * 32 + lane;             // float4 index 0..63
        float4 x = ((const float4*)vocab)[(size_t)row * 64 + c4];
        float xs[4] = {x.x, x.y, x.z, x.w};
        __half h[4], l[4];
        #pragma unroll
        for (int i = 0; i < 4; i++) {
            h[i] = __float2half_rn(xs[i]);
            l[i] = __float2half_rn(xs[i] - __half2float(h[i]));
        }
        uint2 uh, ul;
        __half2 h0 = {h[0], h[1]}, h1 = {h[2], h[3]};
        __half2 l0 = {l[0], l[1]}, l1 = {l[2], l[3]};
        uh.x = *(uint32_t*)&h0; uh.y = *(uint32_t*)&h1;
        ul.x = *(uint32_t*)&l0; ul.y = *(uint32_t*)&l1;
        __half* rs = g_Bs + (size_t)row * KSPL;
        int col = c4 * 4;
        *(uint2*)(rs + col)       = uh;               // hi
        *(uint2*)(rs + 256 + col) = uh;               // hi
        *(uint2*)(rs + 512 + col) = ul;               // lo
    }
}

// ======== reduce + flag + inline split-A fill (2 threads/token) ========
__global__ void reduce_kernel(const float* __restrict__ seq) {
    int gid  = blockIdx.x * blockDim.x + threadIdx.x;   // 65536 threads
    int t    = gid >> 1;
    int half = gid & 1;
    int lane = threadIdx.x & 31;
    float m1 = FLT_MAX, m2 = FLT_MAX; int i1 = 0x7FFFFFFF;
    #pragma unroll 4
    for (int nt = half; nt < NTIL; nt += 2) {
        float s1 = g_s1[(size_t)nt * NTOK + t];
        float s2 = g_s2[(size_t)nt * NTOK + t];
        int   ii = g_i1[(size_t)nt * NTOK + t];
        if (s1 < m1 || (s1 == m1 && ii < i1)) {
            m2 = fminf(m1, s2); m1 = s1; i1 = ii;
        } else {
            m2 = fminf(m2, s1);
        }
    }
    // merge partner (same token, other half)
    float om1 = __shfl_xor_sync(0xffffffffu, m1, 1);
    float om2 = __shfl_xor_sync(0xffffffffu, m2, 1);
    int   oi  = __shfl_xor_sync(0xffffffffu, i1, 1);
    if (om1 < m1 || (om1 == m1 && oi < i1)) {
        m2 = fminf(m1, om2); m1 = om1; i1 = oi;
    } else {
        m2 = fminf(m2, om1);
    }
    bool flag = (m2 - m1 < TAU);
    int slot = -1;
    if (half == 0) {
        if (flag) {
            g_key[t] = 0xFFFFFFFFFFFFFFFFull;   // sentinel: exact pass decides
            slot = atomicAdd(&g_wlcount, 1);
            g_wl[slot] = t;
        } else {
            g_key[t] = ((unsigned long long)f2ord(m1) << 32) | (uint32_t)i1;
        }
    }
    // broadcast slot from the half==0 partner
    slot = __shfl_sync(0xffffffffu, slot, lane & ~1);
    if (flag) {
        // this thread fills cols [half*128, half*128+128) of split-A row `slot`
        __half* r = g_As + (size_t)slot * KSPL;
        const float4* src = (const float4*)(seq) + (size_t)t * 64 + half * 32;
        #pragma unroll 8
        for (int i = 0; i < 32; i++) {
            float4 x = src[i];
            float xs[4] = {x.x, x.y, x.z, x.w};
            __half h[4], l[4];
            #pragma unroll
            for (int k = 0; k < 4; k++) {
                h[k] = __float2half_rn(xs[k]);
                l[k] = __float2half_rn(xs[k] - __half2float(h[k]));
            }
            uint2 uh, ul;
            __half2 h0 = {h[0], h[1]}, h1 = {h[2], h[3]};
            __half2 l0 = {l[0], l[1]}, l1 = {l[2], l[3]};
            uh.x = *(uint32_t*)&h0; uh.y = *(uint32_t*)&h1;
            ul.x = *(uint32_t*)&l0; ul.y = *(uint32_t*)&l1;
            int col = half * 128 + i * 4;
            *(uint2*)(r + col)       = uh;      // hi
            *(uint2*)(r + 256 + col) = ul;      // lo
            *(uint2*)(r + 512 + col) = uh;      // hi
        }
    }
}

// ===== exact cleanup: split-fp16 GEMM (K=768), persistent grid-stride =====
__global__ __launch_bounds__(256, 2)
void cleanup_gemm() {
    const int nf = g_wlcount;
    if (nf == 0) return;
    const int ngrp   = (nf + 127) >> 7;
    const int nitems = ngrp * 64;

    extern __shared__ char smem[];
    uint32_t sbase = smem_u32(smem);
    float* s_vn = (float*)(smem + CU_VN);
    float* r1a  = (float*)(smem + CU_R1);
    int*   ria  = (int*)  (smem + CU_RI);
    int*   tk   = (int*)  (smem + CU_TK);

    const int tid = threadIdx.x, lane = tid & 31, wid = tid >> 5;
    const int wm = wid & 1, wn = wid >> 1;

    for (int item = blockIdx.x; item < nitems; item += gridDim.x) {
        const int mg = item >> 6;
        const int bn = item & 63;
        const int n0 = bn * 128;
        const int m0 = mg * 128;

        const char* Ab = (const char*)g_As + (size_t)m0 * (KSPL * 2);
        const char* Bb = (const char*)g_Bs + (size_t)n0 * (KSPL * 2);

#define CU_LOAD(J)                                                             \
        {                                                                      \
            uint32_t st = sbase + CU_ST((J) & 1);                              \
            _Pragma("unroll")                                                  \
            for (int q = 0; q < 4; q++) {                                      \
                int p = tid + 256 * q; int r = p >> 3, jj = p & 7;             \
                cpasync16(st + swz(r * 128 + jj * 16),                         \
                          Ab + (size_t)r * (KSPL * 2) + (J) * 128 + jj * 16);  \
            }                                                                  \
            _Pragma("unroll")                                                  \
            for (int q = 0; q < 4; q++) {                                      \
                int p = tid + 256 * q; int r = p >> 3, jj = p & 7;             \
                cpasync16(st + 16384 + swz(r * 128 + jj * 16),                 \
                          Bb + (size_t)r * (KSPL * 2) + (J) * 128 + jj * 16);  \
            }                                                                  \
            CP_COMMIT();                                                       \
        }

        __syncthreads();            // protect smem (tk/vn/red) across items
        CU_LOAD(0)
        CU_LOAD(1)
        if (tid < 128) {
            s_vn[tid] = g_vnorm[n0 + tid];
            int w = m0 + tid;
            tk[tid] = g_wl[w < nf ? w : (nf - 1)];
        }

        float acc[4][4][4];
        #pragma unroll
        for (int i = 0; i < 4; i++)
            #pragma unroll
            for (int j = 0; j < 4; j++)
                #pragma unroll
                for (int c = 0; c < 4; c++) acc[i][j][c] = 0.f;

#define CU_COMPUTE(ST)                                                         \
        {                                                                      \
            uint32_t Abase = sbase + CU_ST(ST);                                \
            uint32_t Bbase = Abase + 16384;                                    \
            _Pragma("unroll")                                                  \
            for (int ks = 0; ks < 4; ks++) {                                   \
                uint32_t af[4][4];                                             \
                _Pragma("unroll")                                              \
                for (int mt = 0; mt < 4; mt++) {                               \
                    int row = wm * 64 + mt * 16 + (lane & 15);                 \
                    uint32_t ad = Abase + swz(row * 128 + ks * 32 + (lane >> 4) * 16); \
                    ldsm4(af[mt][0], af[mt][1], af[mt][2], af[mt][3], ad);     \
                }                                                              \
                uint32_t bf[2][4];                                             \
                _Pragma("unroll")                                              \
                for (int np = 0; np < 2; np++) {                               \
                    int row = wn * 32 + np * 16 + (lane & 15);                 \
                    uint32_t bd = Bbase + swz(row * 128 + ks * 32 + (lane >> 4) * 16); \
                    ldsm4(bf[np][0], bf[np][1], bf[np][2], bf[np][3], bd);     \
                }                                                              \
                _Pragma("unroll")                                              \
                for (int mt = 0; mt < 4; mt++) {                               \
                    _Pragma("unroll")                                          \
                    for (int nt = 0; nt < 4; nt++) {                           \
                        int np = nt >> 1, sub = nt & 1;                        \
                        mma16816(acc[mt][nt], af[mt], bf[np][sub], bf[np][sub + 2]); \
                    }                                                          \
                }                                                              \
            }                                                                  \
        }

        #pragma unroll
        for (int c = 0; c < 12; c++) {
            if (c == 11) { CP_WAIT(0); } else { CP_WAIT(1); }
            __syncthreads();
            CU_COMPUTE(c & 1)
            __syncthreads();
            if (c + 2 < 12) CU_LOAD(c + 2)
        }
#undef CU_COMPUTE
#undef CU_LOAD

        // ---- top-1 epilogue ----
        float m1[8]; int i1[8];
        #pragma unroll
        for (int s = 0; s < 8; s++) { m1[s] = FLT_MAX; i1[s] = 0x7FFFFFFF; }

        #pragma unroll
        for (int nt = 0; nt < 4; nt++) {
            int nloc_base = wn * 32 + (nt >> 1) * 16 + (nt & 1) * 8 + (lane & 3) * 2;
            #pragma unroll
            for (int cc = 0; cc < 2; cc++) {
                int nloc = nloc_base + cc;
                float vn = s_vn[nloc];
                int n = n0 + nloc;
                #pragma unroll
                for (int mq = 0; mq < 4; mq++) {
                    #pragma unroll
                    for (int rg = 0; rg < 2; rg++) {
                        int s_ = mq * 2 + rg;
                        float sc = vn - acc[mq][nt][rg * 2 + cc];
                        if (sc < m1[s_]) { m1[s_] = sc; i1[s_] = n; }
                    }
                }
            }
        }
        #pragma unroll
        for (int s = 0; s < 8; s++) {
            #pragma unroll
            for (int off = 1; off <= 2; off <<= 1) {
                float om1 = __shfl_xor_sync(0xffffffffu, m1[s], off);
                int   oi  = __shfl_xor_sync(0xffffffffu, i1[s], off);
                if (om1 < m1[s] || (om1 == m1[s] && oi < i1[s])) {
                    m1[s] = om1; i1[s] = oi;
                }
            }
        }
        if ((lane & 3) == 0) {
            #pragma unroll
            for (int mq = 0; mq < 4; mq++)
                #pragma unroll
                for (int rg = 0; rg < 2; rg++) {
                    int s_ = mq * 2 + rg;
                    int row = wm * 64 + mq * 16 + rg * 8 + (lane >> 2);
                    r1a[row * 4 + wn] = m1[s_];
                    ria[row * 4 + wn] = i1[s_];
                }
        }
        __syncthreads();
        if (tid < 128 && m0 + tid < nf) {
            float M1 = FLT_MAX; int I1 = 0x7FFFFFFF;
            #pragma unroll
            for (int w = 0; w < 4; w++) {
                float a1 = r1a[tid * 4 + w];
                int   ai = ria[tid * 4 + w];
                if (a1 < M1 || (a1 == M1 && ai < I1)) { M1 = a1; I1 = ai; }
            }
            unsigned long long key =
                ((unsigned long long)f2ord(M1) << 32) | (uint32_t)I1;
            atomicMin(&g_key[tk[tid]], key);
        }
    }
}

// ============================ gather (reads packed key) ============================
__global__ void gather_kernel(const float* __restrict__ vocab,
                              float* __restrict__ out, int write_idx) {
    int token = blockIdx.x * 4 + (threadIdx.x >> 6);
    int l     = threadIdx.x & 63;
    int idx   = (int)(unsigned)(g_key[token] & 0xFFFFFFFFull);
    const float4* src = (const float4*)(vocab + (size_t)idx * DIMD);
    float4*       dst = (float4*)(out + (size_t)token * DIMD);
    dst[l] = src[l];
    if (write_idx && l == 0)
        out[(size_t)NTOK * DIMD + token] = (float)idx;
}

// ============================ launch ============================
extern "C" void kernel_launch(void* const* d_in, const int* in_sizes, int n_in,
                              void* d_out, int out_size) {
    const float* seq   = (const float*)d_in[0];
    const float* vocab = (const float*)d_in[1];
    float* out = (float*)d_out;
    int write_idx = (out_size >= NTOK * DIMD + NTOK) ? 1 : 0;

    cudaFuncSetAttribute(gemm_kernel,
                         cudaFuncAttributeMaxDynamicSharedMemorySize, SM_TOTAL);
    cudaFuncSetAttribute(cleanup_gemm,
                         cudaFuncAttributeMaxDynamicSharedMemorySize, CU_SM_TOTAL);

    convert_kernel<<<2048 + 1024, 256>>>(seq, vocab);
    gemm_kernel<<<(NTOK / (MGRP * 128)) * NTIL, 256, SM_TOTAL>>>(vocab);
    reduce_kernel<<<NTOK * 2 / 256, 256>>>(seq);
    cleanup_gemm<<<1184, 256, CU_SM_TOTAL>>>();
    gather_kernel<<<NTOK / 4, 256>>>(vocab, out, write_idx);
}

// round 15
// speedup vs baseline: 1.9616x; 1.0089x over previous
#include <cuda_runtime.h>
#include <cuda_fp16.h>
#include <cstdint>
#include <float.h>

#define NTOK 32768
#define DIMD 256
#define KVOC 8192
#define NTIL   64           // n-tiles of 128 codewords
#define MGRP   8            // m-tiles per CTA (persistent-B coarse gemm)
#define TAU  0.03f
#define KSPL 768            // split-K: [x_hi|x_lo|x_hi] . [v_hi|v_hi|v_lo]

// ---- device scratch ----
__device__ __half g_Ah[(size_t)NTOK * DIMD];   // 16 MB fp16 tokens (coarse)
__device__ __half g_Bh[(size_t)KVOC * DIMD];   // 4 MB fp16 vocab (coarse)
__device__ __half g_As[(size_t)NTOK * KSPL];   // split-A (flagged, compact)
__device__ __half g_Bs[(size_t)KVOC * KSPL];   // split-B
__device__ float  g_vnorm[KVOC];               // 0.5*||v||^2 fp32
__device__ float  g_s1[(size_t)NTIL * NTOK];
__device__ float  g_s2[(size_t)NTIL * NTOK];
__device__ int    g_i1[(size_t)NTIL * NTOK];
__device__ unsigned long long g_key[NTOK];
__device__ int    g_wl[NTOK];
__device__ int    g_wlcount;

// ---- coarse gemm smem: A stages (2x16KB) | B chunks (4x16KB) | vn ----
#define SA_OFF(st) ((st) * 16384)
#define SB_OFF(c)  (32768 + (c) * 16384)
#define SO_VN  98304
#define SM_TOTAL 98816

// ---- cleanup gemm smem (M=64 tile): 2 stages x (A 8KB + B 16KB) | vn | red | tk ----
#define CU_ST(st)  ((st) * 24576)
#define CU_VN  49152
#define CU_R1  49664
#define CU_RI  50688
#define CU_TK  51712
#define CU_SM_TOTAL 52224

// ============================ asm helpers ============================
__device__ __forceinline__ uint32_t smem_u32(const void* p) {
    uint32_t a;
    asm("{ .reg .u64 t; cvta.to.shared.u64 t, %1; cvt.u32.u64 %0, t; }"
        : "=r"(a) : "l"(p));
    return a;
}
__device__ __forceinline__ void cpasync16(uint32_t s, const void* g) {
    asm volatile("cp.async.cg.shared.global [%0], [%1], 16;" :: "r"(s), "l"(g));
}
#define CP_COMMIT() asm volatile("cp.async.commit_group;" ::: "memory")
#define CP_WAIT(N)  asm volatile("cp.async.wait_group " #N ";" ::: "memory")

__device__ __forceinline__ void ldsm4(uint32_t& r0, uint32_t& r1, uint32_t& r2,
                                      uint32_t& r3, uint32_t addr) {
    asm volatile("ldmatrix.sync.aligned.m8n8.x4.shared.b16 {%0,%1,%2,%3}, [%4];"
                 : "=r"(r0), "=r"(r1), "=r"(r2), "=r"(r3) : "r"(addr));
}
__device__ __forceinline__ void mma16816(float* d, const uint32_t* a,
                                         uint32_t b0, uint32_t b1) {
    asm volatile(
        "mma.sync.aligned.m16n8k16.row.col.f32.f16.f16.f32 "
        "{%0,%1,%2,%3},{%4,%5,%6,%7},{%8,%9},{%0,%1,%2,%3};"
        : "+f"(d[0]), "+f"(d[1]), "+f"(d[2]), "+f"(d[3])
        : "r"(a[0]), "r"(a[1]), "r"(a[2]), "r"(a[3]), "r"(b0), "r"(b1));
}
__device__ __forceinline__ uint32_t swz(uint32_t off) {
    return off ^ ((off >> 3) & 0x70);
}
__device__ __forceinline__ uint32_t f2ord(float s) {
    uint32_t fb = __float_as_uint(s);
    return (fb & 0x80000000u) ? ~fb : (fb | 0x80000000u);
}

// =================== convert kernel (seq fp16 + vocab fp16/vnorm) ===================
__global__ void convert_kernel(const float* __restrict__ seq,
                               const float* __restrict__ vocab) {
    if (blockIdx.x == 0 && threadIdx.x == 0) g_wlcount = 0;
    if (blockIdx.x < 2048) {
        int gid = blockIdx.x * 256 + threadIdx.x;     // 524288 threads
        const float4* s4 = (const float4*)seq + (size_t)gid * 4;
        uint2 u[4];
        #pragma unroll
        for (int k = 0; k < 4; k++) {
            float4 x = s4[k];
            __half2 a = __floats2half2_rn(x.x, x.y);
            __half2 b = __floats2half2_rn(x.z, x.w);
            u[k].x = *(uint32_t*)&a; u[k].y = *(uint32_t*)&b;
        }
        uint4* dst = (uint4*)(g_Ah + (size_t)gid * 16);
        dst[0] = make_uint4(u[0].x, u[0].y, u[1].x, u[1].y);
        dst[1] = make_uint4(u[2].x, u[2].y, u[3].x, u[3].y);
    } else {
        int row  = (blockIdx.x - 2048) * 8 + (threadIdx.x >> 5);
        int lane = threadIdx.x & 31;
        const float4* v = (const float4*)(vocab + (size_t)row * DIMD);
        float s = 0.f;
        #pragma unroll
        for (int c4 = lane; c4 < 64; c4 += 32) {
            float4 x = v[c4];
            s += x.x*x.x + x.y*x.y + x.z*x.z + x.w*x.w;
            __half2 a = __floats2half2_rn(x.x, x.y);
            __half2 b = __floats2half2_rn(x.z, x.w);
            uint2 u;
            u.x = *(uint32_t*)&a; u.y = *(uint32_t*)&b;
            *(uint2*)(g_Bh + (size_t)row * DIMD + c4 * 4) = u;
        }
        #pragma unroll
        for (int o = 16; o; o >>= 1) s += __shfl_xor_sync(0xffffffffu, s, o);
        if (lane == 0) g_vnorm[row] = 0.5f * s;
    }
}

// ====== persistent-B fp16 coarse GEMM, row-owning warps, fused top-2 ======
// Also builds split-B (g_Bs) in its tail: 2048 CTAs x 4 vocab rows.
__global__ __launch_bounds__(256, 2)
void gemm_kernel(const float* __restrict__ vocab) {
    extern __shared__ char smem[];
    uint32_t sbase = smem_u32(smem);
    float* s_vn = (float*)(smem + SO_VN);

    const int tid = threadIdx.x, lane = tid & 31, wid = tid >> 5;
    const int bn = blockIdx.x & (NTIL - 1);         // n-tile
    const int mg = blockIdx.x >> 6;                 // m-group
    const int n0 = bn * 128;
    const int mbase = mg * MGRP * 128;

    const char* Bb = (const char*)g_Bh + (size_t)n0 * 512;

    // ---- B n-tile (64KB = 4 chunk sub-tiles), one group
    #pragma unroll
    for (int q = 0; q < 16; q++) {
        int c  = q >> 2;
        int p  = tid + 256 * (q & 3);
        int r  = p >> 3, jj = p & 7;
        cpasync16(sbase + SB_OFF(c) + swz(r * 128 + jj * 16),
                  Bb + (size_t)r * 512 + c * 128 + jj * 16);
    }
    CP_COMMIT();

    // A chunk J (J = mt*4 + c) -> stage (J & 1)
#define LOAD_A(J)                                                              \
    {                                                                          \
        uint32_t st = sbase + SA_OFF((J) & 1);                                 \
        const char* Asrc = (const char*)g_Ah                                   \
            + (size_t)(mbase + ((J) >> 2) * 128) * 512 + ((J) & 3) * 128;      \
        _Pragma("unroll")                                                      \
        for (int q = 0; q < 4; q++) {                                          \
            int p = tid + 256 * q; int r = p >> 3, jj = p & 7;                 \
            cpasync16(st + swz(r * 128 + jj * 16),                             \
                      Asrc + (size_t)r * 512 + jj * 16);                       \
        }                                                                      \
        CP_COMMIT();                                                           \
    }

    LOAD_A(0)
    if (tid < 128) s_vn[tid] = g_vnorm[n0 + tid];

    // warp wid owns rows [wid*16, wid*16+16) x all 128 cols
    float acc[16][4];

    for (int mt = 0; mt < MGRP; mt++) {
        #pragma unroll
        for (int g = 0; g < 16; g++)
            #pragma unroll
            for (int c = 0; c < 4; c++) acc[g][c] = 0.f;

        #pragma unroll
        for (int c = 0; c < 4; c++) {
            const int j = mt * 4 + c;
            CP_WAIT(0);
            __syncthreads();            // chunk j ready; stage (j+1)&1 free
            if (j + 1 < MGRP * 4) LOAD_A(j + 1)

            uint32_t Abase = sbase + SA_OFF(j & 1);
            uint32_t Bbase = sbase + SB_OFF(c);
            #pragma unroll
            for (int ks = 0; ks < 4; ks++) {
                uint32_t af[4];
                {
                    int row = wid * 16 + (lane & 15);
                    uint32_t ad = Abase + swz(row * 128 + ks * 32 + (lane >> 4) * 16);
                    ldsm4(af[0], af[1], af[2], af[3], ad);
                }
                uint32_t bf[8][4];
                #pragma unroll
                for (int nb = 0; nb < 8; nb++) {
                    int row = nb * 16 + (lane & 15);
                    uint32_t bd = Bbase + swz(row * 128 + ks * 32 + (lane >> 4) * 16);
                    ldsm4(bf[nb][0], bf[nb][1], bf[nb][2], bf[nb][3], bd);
                }
                #pragma unroll
                for (int nb = 0; nb < 8; nb++) {
                    mma16816(acc[nb * 2],     af, bf[nb][0], bf[nb][2]);
                    mma16816(acc[nb * 2 + 1], af, bf[nb][1], bf[nb][3]);
                }
            }
        }

        // ---- warp-local top-2 epilogue (no smem, no barriers) ----
        const int m0 = mbase + mt * 128;
        float m1[2] = {FLT_MAX, FLT_MAX}, m2[2] = {FLT_MAX, FLT_MAX};
        int   i1[2] = {0x7FFFFFFF, 0x7FFFFFFF};

        #pragma unroll
        for (int g = 0; g < 16; g++) {
            int nb_ = g * 8 + (lane & 3) * 2;
            float vn0 = s_vn[nb_], vn1 = s_vn[nb_ + 1];
            #pragma unroll
            for (int c = 0; c < 4; c++) {
                int sl = c >> 1;
                float sc = ((c & 1) ? vn1 : vn0) - acc[g][c];
                int n = n0 + nb_ + (c & 1);
                if (sc < m1[sl]) { m2[sl] = m1[sl]; m1[sl] = sc; i1[sl] = n; }
                else if (sc < m2[sl]) m2[sl] = sc;
            }
        }
        #pragma unroll
        for (int off = 1; off <= 2; off <<= 1) {
            #pragma unroll
            for (int sl = 0; sl < 2; sl++) {
                float om1 = __shfl_xor_sync(0xffffffffu, m1[sl], off);
                float om2 = __shfl_xor_sync(0xffffffffu, m2[sl], off);
                int   oi  = __shfl_xor_sync(0xffffffffu, i1[sl], off);
                if (om1 < m1[sl] || (om1 == m1[sl] && oi < i1[sl])) {
                    m2[sl] = fminf(m1[sl], om2); m1[sl] = om1; i1[sl] = oi;
                } else {
                    m2[sl] = fminf(m2[sl], om1);
                }
            }
        }
        // redistribute so lanes 0..15 hold token wid*16+lane -> coalesced stores
        {
            int src = (lane & 7) * 4;           // quad leader for (lane mod 8)
            float a1 = __shfl_sync(0xffffffffu, m1[0], src);
            float b1 = __shfl_sync(0xffffffffu, m1[1], src);
            float a2 = __shfl_sync(0xffffffffu, m2[0], src);
            float b2 = __shfl_sync(0xffffffffu, m2[1], src);
            int   ai = __shfl_sync(0xffffffffu, i1[0], src);
            int   bi = __shfl_sync(0xffffffffu, i1[1], src);
            if (lane < 16) {
                bool hi = lane >= 8;
                int token = m0 + wid * 16 + lane;
                size_t o = (size_t)bn * NTOK + token;
                g_s1[o] = hi ? b1 : a1;
                g_s2[o] = hi ? b2 : a2;
                g_i1[o] = hi ? bi : ai;
            }
        }
    }
#undef LOAD_A

    // ---- tail: build split-B rows [blockIdx.x*4, +4) (tensor pipe idle) ----
    {
        int row  = blockIdx.x * 4 + (wid >> 1);       // 2 warps per row
        int c4   = (wid & 1) * 32 + lane;             // float4 index 0..63
        float4 x = ((const float4*)vocab)[(size_t)row * 64 + c4];
        float xs[4] = {x.x, x.y, x.z, x.w};
        __half h[4], l[4];
        #pragma unroll
        for (int i = 0; i < 4; i++) {
            h[i] = __float2half_rn(xs[i]);
            l[i] = __float2half_rn(xs[i] - __half2float(h[i]));
        }
        uint2 uh, ul;
        __half2 h0 = {h[0], h[1]}, h1 = {h[2], h[3]};
        __half2 l0 = {l[0], l[1]}, l1 = {l[2], l[3]};
        uh.x = *(uint32_t*)&h0; uh.y = *(uint32_t*)&h1;
        ul.x = *(uint32_t*)&l0; ul.y = *(uint32_t*)&l1;
        __half* rs = g_Bs + (size_t)row * KSPL;
        int col = c4 * 4;
        *(uint2*)(rs + col)       = uh;               // hi
        *(uint2*)(rs + 256 + col) = uh;               // hi
        *(uint2*)(rs + 512 + col) = ul;               // lo
    }
}

// ======== reduce + flag + inline split-A fill (2 threads/token) ========
__global__ void reduce_kernel(const float* __restrict__ seq) {
    int gid  = blockIdx.x * blockDim.x + threadIdx.x;   // 65536 threads
    int t    = gid >> 1;
    int half = gid & 1;
    int lane = threadIdx.x & 31;
    float m1 = FLT_MAX, m2 = FLT_MAX; int i1 = 0x7FFFFFFF;
    #pragma unroll 4
    for (int nt = half; nt < NTIL; nt += 2) {
        float s1 = g_s1[(size_t)nt * NTOK + t];
        float s2 = g_s2[(size_t)nt * NTOK + t];
        int   ii = g_i1[(size_t)nt * NTOK + t];
        if (s1 < m1 || (s1 == m1 && ii < i1)) {
            m2 = fminf(m1, s2); m1 = s1; i1 = ii;
        } else {
            m2 = fminf(m2, s1);
        }
    }
    // merge partner (same token, other half)
    float om1 = __shfl_xor_sync(0xffffffffu, m1, 1);
    float om2 = __shfl_xor_sync(0xffffffffu, m2, 1);
    int   oi  = __shfl_xor_sync(0xffffffffu, i1, 1);
    if (om1 < m1 || (om1 == m1 && oi < i1)) {
        m2 = fminf(m1, om2); m1 = om1; i1 = oi;
    } else {
        m2 = fminf(m2, om1);
    }
    bool flag = (m2 - m1 < TAU);
    int slot = -1;
    if (half == 0) {
        if (flag) {
            g_key[t] = 0xFFFFFFFFFFFFFFFFull;   // sentinel: exact pass decides
            slot = atomicAdd(&g_wlcount, 1);
            g_wl[slot] = t;
        } else {
            g_key[t] = ((unsigned long long)f2ord(m1) << 32) | (uint32_t)i1;
        }
    }
    // broadcast slot from the half==0 partner
    slot = __shfl_sync(0xffffffffu, slot, lane & ~1);
    if (flag) {
        // this thread fills cols [half*128, half*128+128) of split-A row `slot`
        __half* r = g_As + (size_t)slot * KSPL;
        const float4* src = (const float4*)(seq) + (size_t)t * 64 + half * 32;
        #pragma unroll 8
        for (int i = 0; i < 32; i++) {
            float4 x = src[i];
            float xs[4] = {x.x, x.y, x.z, x.w};
            __half h[4], l[4];
            #pragma unroll
            for (int k = 0; k < 4; k++) {
                h[k] = __float2half_rn(xs[k]);
                l[k] = __float2half_rn(xs[k] - __half2float(h[k]));
            }
            uint2 uh, ul;
            __half2 h0 = {h[0], h[1]}, h1 = {h[2], h[3]};
            __half2 l0 = {l[0], l[1]}, l1 = {l[2], l[3]};
            uh.x = *(uint32_t*)&h0; uh.y = *(uint32_t*)&h1;
            ul.x = *(uint32_t*)&l0; ul.y = *(uint32_t*)&l1;
            int col = half * 128 + i * 4;
            *(uint2*)(r + col)       = uh;      // hi
            *(uint2*)(r + 256 + col) = ul;      // lo
            *(uint2*)(r + 512 + col) = uh;      // hi
        }
    }
}

// ===== exact cleanup: split-fp16 GEMM (K=768), M=64 tile, persistent =====
__global__ __launch_bounds__(256, 2)
void cleanup_gemm() {
    const int nf = g_wlcount;
    if (nf == 0) return;
    const int ngrp   = (nf + 63) >> 6;
    const int nitems = ngrp * 64;

    extern __shared__ char smem[];
    uint32_t sbase = smem_u32(smem);
    float* s_vn = (float*)(smem + CU_VN);
    float* r1a  = (float*)(smem + CU_R1);
    int*   ria  = (int*)  (smem + CU_RI);
    int*   tk   = (int*)  (smem + CU_TK);

    const int tid = threadIdx.x, lane = tid & 31, wid = tid >> 5;
    const int wm = wid & 1, wn = wid >> 1;

    for (int item = blockIdx.x; item < nitems; item += gridDim.x) {
        const int mg = item >> 6;
        const int bn = item & 63;
        const int n0 = bn * 128;
        const int m0 = mg * 64;

        const char* Ab = (const char*)g_As + (size_t)m0 * (KSPL * 2);
        const char* Bb = (const char*)g_Bs + (size_t)n0 * (KSPL * 2);

        // chunk J: A 64x128B (8KB, 2 ops/thread) at +0, B 128x128B (16KB) at +8192
#define CU_LOAD(J)                                                             \
        {                                                                      \
            uint32_t st = sbase + CU_ST((J) & 1);                              \
            _Pragma("unroll")                                                  \
            for (int q = 0; q < 2; q++) {                                      \
                int p = tid + 256 * q; int r = p >> 3, jj = p & 7;             \
                cpasync16(st + swz(r * 128 + jj * 16),                         \
                          Ab + (size_t)r * (KSPL * 2) + (J) * 128 + jj * 16);  \
            }                                                                  \
            _Pragma("unroll")                                                  \
            for (int q = 0; q < 4; q++) {                                      \
                int p = tid + 256 * q; int r = p >> 3, jj = p & 7;             \
                cpasync16(st + 8192 + swz(r * 128 + jj * 16),                  \
                          Bb + (size_t)r * (KSPL * 2) + (J) * 128 + jj * 16);  \
            }                                                                  \
            CP_COMMIT();                                                       \
        }

        __syncthreads();            // protect smem (tk/vn/red) across items
        CU_LOAD(0)
        CU_LOAD(1)
        if (tid < 128) s_vn[tid] = g_vnorm[n0 + tid];
        if (tid < 64) {
            int w = m0 + tid;
            tk[tid] = g_wl[w < nf ? w : (nf - 1)];
        }

        float acc[2][4][4];
        #pragma unroll
        for (int i = 0; i < 2; i++)
            #pragma unroll
            for (int j = 0; j < 4; j++)
                #pragma unroll
                for (int c = 0; c < 4; c++) acc[i][j][c] = 0.f;

#define CU_COMPUTE(ST)                                                         \
        {                                                                      \
            uint32_t Abase = sbase + CU_ST(ST);                                \
            uint32_t Bbase = Abase + 8192;                                     \
            _Pragma("unroll")                                                  \
            for (int ks = 0; ks < 4; ks++) {                                   \
                uint32_t af[2][4];                                             \
                _Pragma("unroll")                                              \
                for (int mt = 0; mt < 2; mt++) {                               \
                    int row = wm * 32 + mt * 16 + (lane & 15);                 \
                    uint32_t ad = Abase + swz(row * 128 + ks * 32 + (lane >> 4) * 16); \
                    ldsm4(af[mt][0], af[mt][1], af[mt][2], af[mt][3], ad);     \
                }                                                              \
                uint32_t bf[2][4];                                             \
                _Pragma("unroll")                                              \
                for (int np = 0; np < 2; np++) {                               \
                    int row = wn * 32 + np * 16 + (lane & 15);                 \
                    uint32_t bd = Bbase + swz(row * 128 + ks * 32 + (lane >> 4) * 16); \
                    ldsm4(bf[np][0], bf[np][1], bf[np][2], bf[np][3], bd);     \
                }                                                              \
                _Pragma("unroll")                                              \
                for (int mt = 0; mt < 2; mt++) {                               \
                    _Pragma("unroll")                                          \
                    for (int nt = 0; nt < 4; nt++) {                           \
                        int np = nt >> 1, sub = nt & 1;                        \
                        mma16816(acc[mt][nt], af[mt], bf[np][sub], bf[np][sub + 2]); \
                    }                                                          \
                }                                                              \
            }                                                                  \
        }

        #pragma unroll
        for (int c = 0; c < 12; c++) {
            if (c == 11) { CP_WAIT(0); } else { CP_WAIT(1); }
            __syncthreads();
            CU_COMPUTE(c & 1)
            __syncthreads();
            if (c + 2 < 12) CU_LOAD(c + 2)
        }
#undef CU_COMPUTE
#undef CU_LOAD

        // ---- top-1 epilogue (64 rows) ----
        float m1[4]; int i1[4];                  // slot = mt*2 + rg
        #pragma unroll
        for (int s = 0; s < 4; s++) { m1[s] = FLT_MAX; i1[s] = 0x7FFFFFFF; }

        #pragma unroll
        for (int nt = 0; nt < 4; nt++) {
            int nloc_base = wn * 32 + (nt >> 1) * 16 + (nt & 1) * 8 + (lane & 3) * 2;
            #pragma unroll
            for (int cc = 0; cc < 2; cc++) {
                int nloc = nloc_base + cc;
                float vn = s_vn[nloc];
                int n = n0 + nloc;
                #pragma unroll
                for (int mt = 0; mt < 2; mt++) {
                    #pragma unroll
                    for (int rg = 0; rg < 2; rg++) {
                        int s_ = mt * 2 + rg;
                        float sc = vn - acc[mt][nt][rg * 2 + cc];
                        if (sc < m1[s_]) { m1[s_] = sc; i1[s_] = n; }
                    }
                }
            }
        }
        #pragma unroll
        for (int s = 0; s < 4; s++) {
            #pragma unroll
            for (int off = 1; off <= 2; off <<= 1) {
                float om1 = __shfl_xor_sync(0xffffffffu, m1[s], off);
                int   oi  = __shfl_xor_sync(0xffffffffu, i1[s], off);
                if (om1 < m1[s] || (om1 == m1[s] && oi < i1[s])) {
                    m1[s] = om1; i1[s] = oi;
                }
            }
        }
        if ((lane & 3) == 0) {
            #pragma unroll
            for (int mt = 0; mt < 2; mt++)
                #pragma unroll
                for (int rg = 0; rg < 2; rg++) {
                    int s_ = mt * 2 + rg;
                    int row = wm * 32 + mt * 16 + rg * 8 + (lane >> 2);
                    r1a[row * 4 + wn] = m1[s_];
                    ria[row * 4 + wn] = i1[s_];
                }
        }
        __syncthreads();
        if (tid < 64 && m0 + tid < nf) {
            float M1 = FLT_MAX; int I1 = 0x7FFFFFFF;
            #pragma unroll
            for (int w = 0; w < 4; w++) {
                float a1 = r1a[tid * 4 + w];
                int   ai = ria[tid * 4 + w];
                if (a1 < M1 || (a1 == M1 && ai < I1)) { M1 = a1; I1 = ai; }
            }
            unsigned long long key =
                ((unsigned long long)f2ord(M1) << 32) | (uint32_t)I1;
            atomicMin(&g_key[tk[tid]], key);
        }
    }
}

// ============================ gather (reads packed key) ============================
__global__ void gather_kernel(const float* __restrict__ vocab,
                              float* __restrict__ out, int write_idx) {
    int token = blockIdx.x * 4 + (threadIdx.x >> 6);
    int l     = threadIdx.x & 63;
    int idx   = (int)(unsigned)(g_key[token] & 0xFFFFFFFFull);
    const float4* src = (const float4*)(vocab + (size_t)idx * DIMD);
    float4*       dst = (float4*)(out + (size_t)token * DIMD);
    dst[l] = src[l];
    if (write_idx && l == 0)
        out[(size_t)NTOK * DIMD + token] = (float)idx;
}

// ============================ launch ============================
extern "C" void kernel_launch(void* const* d_in, const int* in_sizes, int n_in,
                              void* d_out, int out_size) {
    const float* seq   = (const float*)d_in[0];
    const float* vocab = (const float*)d_in[1];
    float* out = (float*)d_out;
    int write_idx = (out_size >= NTOK * DIMD + NTOK) ? 1 : 0;

    cudaFuncSetAttribute(gemm_kernel,
                         cudaFuncAttributeMaxDynamicSharedMemorySize, SM_TOTAL);
    cudaFuncSetAttribute(cleanup_gemm,
                         cudaFuncAttributeMaxDynamicSharedMemorySize, CU_SM_TOTAL);

    convert_kernel<<<2048 + 1024, 256>>>(seq, vocab);
    gemm_kernel<<<(NTOK / (MGRP * 128)) * NTIL, 256, SM_TOTAL>>>(vocab);
    reduce_kernel<<<NTOK * 2 / 256, 256>>>(seq);
    cleanup_gemm<<<1184, 256, CU_SM_TOTAL>>>();
    gather_kernel<<<NTOK / 4, 256>>>(vocab, out, write_idx);
}